// round 4
// baseline (speedup 1.0000x reference)
#include <cuda_runtime.h>
#include <cuda_bf16.h>
#include <cstdint>
#include <cstddef>

#define NB     16
#define NN     256
#define NT     4
#define HD     128
#define NL     2
#define CELLS  (NB*NN)
#define LOFF   (CELLS*HD)
#define MAXST  15
#define OUTV   1000
#define BUFSZ  65536u
#define TSMEM  (131072 + 128)
#define ZSTR   132

typedef __nv_bfloat16 bf16;

// ---------------- device scratch ----------------
__device__ float g_c_st [NL*CELLS*HD];
__device__ float g_h_st [NL*CELLS*HD];
__device__ bf16  g_hst_h[NL*CELLS*HD];
__device__ bf16  g_hst_l[NL*CELLS*HD];
__device__ float g_c_tok[NL*CELLS*HD];
__device__ float g_h_tok[2][NL*CELLS*HD];
__device__ bf16  g_ht_h [2][NL*CELLS*HD];
__device__ bf16  g_ht_l [2][NL*CELLS*HD];
__device__ bf16  g_emb_h[CELLS*NT*HD];
__device__ bf16  g_emb_l[CELLS*NT*HD];
__device__ float g_xw   [CELLS*NT*512];
__device__ bf16  g_w0x_h[512*128];
__device__ bf16  g_w0x_l[512*128];
__device__ bf16  g_w0h_h[512*128];
__device__ bf16  g_w0h_l[512*128];
__device__ bf16  g_w1_h [512*256];
__device__ bf16  g_w1_l [512*256];
__device__ float g_ip[CELLS], g_wt[CELLS], g_wf[CELLS];

__device__ __forceinline__ float sigf(float x)  { return 1.0f/(1.0f+__expf(-x)); }
__device__ __forceinline__ float tanh_(float x) { return 2.0f/(1.0f+__expf(-2.0f*x))-1.0f; }

__device__ __forceinline__ uint32_t smem_u32(const void* p){
    uint32_t a; asm("{ .reg .u64 t; cvta.to.shared.u64 t, %1; cvt.u32.u64 %0, t; }":"=r"(a):"l"(p)); return a;
}
#define CPA16(d,s) asm volatile("cp.async.cg.shared.global [%0], [%1], 16;"::"r"(d),"l"((unsigned long long)__cvta_generic_to_global((const void*)(s))):"memory")
#define CP_COMMIT() asm volatile("cp.async.commit_group;":::"memory")

__device__ __forceinline__ void ldmx4(uint32_t* r, uint32_t a){
    asm volatile("ldmatrix.sync.aligned.m8n8.x4.shared.b16 {%0,%1,%2,%3}, [%4];"
        : "=r"(r[0]),"=r"(r[1]),"=r"(r[2]),"=r"(r[3]) : "r"(a));
}
__device__ __forceinline__ void ldmx2(uint32_t* r, uint32_t a){
    asm volatile("ldmatrix.sync.aligned.m8n8.x2.shared.b16 {%0,%1}, [%2];"
        : "=r"(r[0]),"=r"(r[1]) : "r"(a));
}
__device__ __forceinline__ void mmabf(float* d, const uint32_t* a, const uint32_t* b){
    asm volatile("mma.sync.aligned.m16n8k16.row.col.f32.bf16.bf16.f32 "
        "{%0,%1,%2,%3}, {%4,%5,%6,%7}, {%8,%9}, {%0,%1,%2,%3};"
        : "+f"(d[0]),"+f"(d[1]),"+f"(d[2]),"+f"(d[3])
        : "r"(a[0]),"r"(a[1]),"r"(a[2]),"r"(a[3]),"r"(b[0]),"r"(b[1]));
}

// ---------------- HMMA GEMM + LSTM epilogue ----------------
// D[128,128] = A[128,K] @ Wt_tile[128,K]^T, 3-pass bf16 hi/lo split.
// Wt rows permuted: p = nt*128 + gate*32 + j <- orig col gate*128 + nt*32 + j.
// MODE 0: store D to zout (permuted cols). MODE 1: LSTM gate epilogue.
template<int NCH, int MODE>
__global__ void __launch_bounds__(256,1) tlstm(
    const bf16* __restrict__ a0h, const bf16* __restrict__ a0l,
    const bf16* __restrict__ a1h, const bf16* __restrict__ a1l,
    const bf16* __restrict__ wth, const bf16* __restrict__ wtl, int kw,
    const float* __restrict__ zinit, int szinit,
    const float* __restrict__ bias,
    const float* __restrict__ cin, float* __restrict__ cout,
    float* __restrict__ hout, bf16* __restrict__ houth, bf16* __restrict__ houtl,
    float* __restrict__ zout)
{
    extern __shared__ char smem[];
    const uint32_t BUF0 = (smem_u32(smem) + 127u) & ~127u;
    float* Z = (float*)(size_t)( (char*)smem + (BUF0 - smem_u32(smem)) );
    const int tid = threadIdx.x, lane = tid & 31, wid = tid >> 5;
    const int mw = wid & 3, nw = wid >> 2;
    const int rowbase = blockIdx.x * 128, nt = blockIdx.y;

    auto load_chunk = [&](int c){
        const uint32_t b = BUF0 + (uint32_t)(c & 1) * BUFSZ;
        const int kbase = c * 64;
        #pragma unroll
        for (int i = 0; i < 4; ++i){
            int u = tid + i * 256;            // 0..1023
            int row = u >> 3;
            int col16 = u & 7;                // 16B unit within 128B row
            uint32_t sw = (uint32_t)(row * 128 + ((col16 ^ (row & 7)) * 16));
            int kg = kbase + col16 * 8;       // bf16 elem index
            const bf16 *ah, *al;
            if (kg < 128){ size_t o = (size_t)(rowbase + row) * 128 + kg;        ah = a0h + o; al = a0l + o; }
            else         { size_t o = (size_t)(rowbase + row) * 128 + (kg - 128); ah = a1h + o; al = a1l + o; }
            CPA16(b + sw,         ah);
            CPA16(b + 16384 + sw, al);
            size_t wo = (size_t)(nt * 128 + row) * kw + kg;
            CPA16(b + 32768 + sw, wth + wo);
            CPA16(b + 49152 + sw, wtl + wo);
        }
        CP_COMMIT();
    };

    float acc[2][8][4];
    #pragma unroll
    for (int mt = 0; mt < 2; ++mt)
        #pragma unroll
        for (int n8 = 0; n8 < 8; ++n8)
            #pragma unroll
            for (int e = 0; e < 4; ++e) acc[mt][n8][e] = 0.f;

    // precomputed ldmatrix lane address components
    const int arow = mw * 32 + (lane & 15);       // + mt*16
    const uint32_t arbase = (uint32_t)(arow * 128);
    const uint32_t axr = (uint32_t)((arow & 7) << 4);
    const uint32_t acolh = (uint32_t)((lane >> 4) * 16);
    const int brow = nw * 64 + (lane & 7);        // + n8*8
    const uint32_t bcolh = (uint32_t)(((lane >> 3) & 1) * 16);

    load_chunk(0);
    #pragma unroll
    for (int c = 0; c < NCH; ++c){
        if (c + 1 < NCH) load_chunk(c + 1);
        if (c + 1 < NCH) asm volatile("cp.async.wait_group 1;":::"memory");
        else             asm volatile("cp.async.wait_group 0;":::"memory");
        __syncthreads();
        const uint32_t b = BUF0 + (uint32_t)(c & 1) * BUFSZ;
        #pragma unroll
        for (int kk = 0; kk < 4; ++kk){
            uint32_t ah[2][4], al[2][4];
            #pragma unroll
            for (int mt = 0; mt < 2; ++mt){
                uint32_t off = (uint32_t)(mt * 16 * 128) + arbase + (((uint32_t)(kk * 32) + acolh) ^ axr);
                ldmx4(ah[mt], b + off);
                ldmx4(al[mt], b + 16384 + off);
            }
            uint32_t bh[8][2], bl[8][2];
            #pragma unroll
            for (int n8 = 0; n8 < 8; ++n8){
                int r = brow + n8 * 8;
                uint32_t off = (uint32_t)(r * 128) + (((uint32_t)(kk * 32) + bcolh) ^ ((uint32_t)((r & 7) << 4)));
                ldmx2(bh[n8], b + 32768 + off);
                ldmx2(bl[n8], b + 49152 + off);
            }
            #pragma unroll
            for (int mt = 0; mt < 2; ++mt)
                #pragma unroll
                for (int n8 = 0; n8 < 8; ++n8){
                    mmabf(acc[mt][n8], ah[mt], bh[n8]);
                    mmabf(acc[mt][n8], ah[mt], bl[n8]);
                    mmabf(acc[mt][n8], al[mt], bh[n8]);
                }
        }
        __syncthreads();
    }

    // dump accumulators to smem Z[128][ZSTR]
    {
        const int qr = lane >> 2, qc = (lane & 3) * 2;
        #pragma unroll
        for (int mt = 0; mt < 2; ++mt){
            int r0 = mw * 32 + mt * 16 + qr;
            #pragma unroll
            for (int n8 = 0; n8 < 8; ++n8){
                int c0 = nw * 64 + n8 * 8 + qc;
                Z[r0 * ZSTR + c0]           = acc[mt][n8][0];
                Z[r0 * ZSTR + c0 + 1]       = acc[mt][n8][1];
                Z[(r0 + 8) * ZSTR + c0]     = acc[mt][n8][2];
                Z[(r0 + 8) * ZSTR + c0 + 1] = acc[mt][n8][3];
            }
        }
    }
    __syncthreads();

    const int row = tid >> 1;
    const int cell = rowbase + row;
    if (MODE == 0){
        const int cb = (tid & 1) * 64;
        float* zp = zout + (size_t)cell * 512 + nt * 128 + cb;
        #pragma unroll
        for (int q = 0; q < 16; ++q)
            *(float4*)(zp + q * 4) = *(float4*)&Z[row * ZSTR + cb + q * 4];
    } else {
        const int jb = (tid & 1) * 16;
        const float* zr = zinit ? zinit + (size_t)cell * szinit + nt * 128 : nullptr;
        #pragma unroll
        for (int jj = 0; jj < 16; ++jj){
            int j = jb + jj;
            int d = nt * 32 + j;
            float vi = Z[row * ZSTR + j]      + bias[d];
            float vf = Z[row * ZSTR + 32 + j] + bias[128 + d];
            float vg = Z[row * ZSTR + 64 + j] + bias[256 + d];
            float vo = Z[row * ZSTR + 96 + j] + bias[384 + d];
            if (zr){ vi += zr[j]; vf += zr[32 + j]; vg += zr[64 + j]; vo += zr[96 + j]; }
            float cold = cin[(size_t)cell * 128 + d];
            float c2 = sigf(vf) * cold + sigf(vi) * tanh_(vg);
            float hv = sigf(vo) * tanh_(c2);
            cout[(size_t)cell * 128 + d] = c2;
            hout[(size_t)cell * 128 + d] = hv;
            bf16 hh = __float2bfloat16(hv);
            houth[(size_t)cell * 128 + d] = hh;
            houtl[(size_t)cell * 128 + d] = __float2bfloat16(hv - __bfloat162float(hh));
        }
    }
}

// ---------------- aux kernels ----------------
__global__ void gather_kernel(const int* __restrict__ data, const float* __restrict__ embed,
                              bf16* __restrict__ eh, bf16* __restrict__ el)
{
    int i = blockIdx.x*blockDim.x + threadIdx.x;
    if (i >= CELLS*NT*HD) return;
    float v = embed[(size_t)data[i>>7]*HD + (i&127)];
    bf16 h = __float2bfloat16(v);
    eh[i] = h; el[i] = __float2bfloat16(v - __bfloat162float(h));
}

__global__ void buildwt_kernel(const float* __restrict__ Wi, const float* __restrict__ Wh,
                               bf16* w0xh, bf16* w0xl, bf16* w0hh, bf16* w0hl,
                               bf16* w1h, bf16* w1l)
{
    int i = blockIdx.x*blockDim.x + threadIdx.x;
    if (i < 512*256){
        int p = i>>8, k = i&255;
        int ntc = p>>7, c = p&127, g = c>>5, j = c&31;
        int orig = g*128 + ntc*32 + j;
        float v = (k<128) ? Wi[(size_t)(128+k)*512+orig] : Wh[(size_t)(128+(k-128))*512+orig];
        bf16 h = __float2bfloat16(v);
        w1h[i] = h; w1l[i] = __float2bfloat16(v - __bfloat162float(h));
    }
    if (i < 512*128){
        int p = i>>7, k = i&127;
        int ntc = p>>7, c = p&127, g = c>>5, j = c&31;
        int orig = g*128 + ntc*32 + j;
        float vx = Wi[(size_t)k*512+orig], vh = Wh[(size_t)k*512+orig];
        bf16 hx = __float2bfloat16(vx), hh = __float2bfloat16(vh);
        w0xh[i] = hx; w0xl[i] = __float2bfloat16(vx - __bfloat162float(hx));
        w0hh[i] = hh; w0hl[i] = __float2bfloat16(vh - __bfloat162float(hh));
    }
}

__global__ void ipinit_kernel(float* ip){ if (threadIdx.x < NB) ip[threadIdx.x*NN] = 1.0f; }

__global__ void restore_kernel(const int* __restrict__ exi, float* cw, float* hw,
                               const float* __restrict__ cc, const float* __restrict__ hc)
{
    int b = blockIdx.x, cell = b*NN + exi[b];
    for (int i = threadIdx.x; i < NL*HD; i += blockDim.x){
        size_t off = (size_t)(i>>7)*LOFF + (size_t)cell*HD + (i&127);
        cw[off] = cc[off]; hw[off] = hc[off];
    }
}

__global__ void branch_kernel(const float* __restrict__ c0, const float* __restrict__ h0,
                              const float* __restrict__ c1, const float* __restrict__ h1,
                              const float* __restrict__ Wb, const float* __restrict__ bb,
                              const float* __restrict__ ip, float* wt, float* wf)
{
    int warp = (blockIdx.x*blockDim.x + threadIdx.x) >> 5;
    int lane = threadIdx.x & 31;
    if (warp >= CELLS) return;
    const float* arrs[4] = {c0,h0,c1,h1};
    float a0=0.f, a1=0.f;
    #pragma unroll
    for (int q=0;q<4;++q){
        const float* p = arrs[q] + (size_t)warp*HD;
        #pragma unroll
        for (int d=lane; d<HD; d+=32){
            float v = p[d];
            float2 w = *(const float2*)&Wb[2*(q*HD+d)];
            a0 += v*w.x; a1 += v*w.y;
        }
    }
    #pragma unroll
    for (int o=16;o;o>>=1){ a0 += __shfl_xor_sync(~0u,a0,o); a1 += __shfl_xor_sync(~0u,a1,o); }
    if (lane==0){
        a0 += bb[0]; a1 += bb[1];
        float m = fmaxf(a0,a1), e0 = __expf(a0-m), e1 = __expf(a1-m);
        float inv = 1.0f/(e0+e1), w = ip[warp];
        wt[warp] = e0*inv*w; wf[warp] = e1*inv*w;
    }
}

__global__ void __launch_bounds__(128) agg_kernel(
    int step, const int* __restrict__ steps,
    const int* __restrict__ tb, const int* __restrict__ fb,
    const float* __restrict__ wt, const float* __restrict__ wf,
    const float* __restrict__ cw, const float* __restrict__ hw,
    float* cc, float* hc, bf16* hch, bf16* hcl, float* ip)
{
    int cell = blockIdx.x, b = cell>>8, dst = cell&255;
    if (step >= steps[b]) return;
    __shared__ float swt[NN], swf[NN];
    __shared__ int   stb[NN], sfb[NN];
    int tid = threadIdx.x;
    for (int i=tid;i<NN;i+=128){
        swt[i]=wt[b*NN+i]; swf[i]=wf[b*NN+i]; stb[i]=tb[b*NN+i]; sfb[i]=fb[b*NN+i];
    }
    __syncthreads();
    float a0=0,a1=0,a2=0,a3=0,ipn=0;
    for (int s=0;s<NN;++s){
        bool m1 = (stb[s]==dst), m2 = (sfb[s]==dst);
        if (m1|m2){
            float w = (m1?swt[s]:0.f) + (m2?swf[s]:0.f);
            ipn += w;
            size_t o = (size_t)(b*NN+s)*HD + tid;
            a0 += w*cw[o]; a1 += w*hw[o]; a2 += w*cw[o+LOFF]; a3 += w*hw[o+LOFF];
        }
    }
    float inv = 1.0f/(ipn+1e-7f);
    size_t od = (size_t)cell*HD + tid;
    float h0 = a1*inv, h1v = a3*inv;
    cc[od] = a0*inv; hc[od] = h0;
    cc[od+LOFF] = a2*inv; hc[od+LOFF] = h1v;
    bf16 hh0 = __float2bfloat16(h0), hh1 = __float2bfloat16(h1v);
    hch[od] = hh0;       hcl[od] = __float2bfloat16(h0 - __bfloat162float(hh0));
    hch[od+LOFF] = hh1;  hcl[od+LOFF] = __float2bfloat16(h1v - __bfloat162float(hh1));
    if (tid==0) ip[cell] = ipn;
}

__global__ void final_kernel(const int* __restrict__ exi,
                             const float* __restrict__ cc, const float* __restrict__ hc,
                             const float* __restrict__ Wo, const float* __restrict__ bo,
                             float* __restrict__ out)
{
    int b = blockIdx.x;
    __shared__ float f[4*HD];
    int cell = b*NN + exi[b];
    for (int i=threadIdx.x;i<4*HD;i+=blockDim.x){
        int l = i>>8, ch = (i>>7)&1, d = i&127;
        const float* src = ch ? hc : cc;
        f[i] = src[(size_t)l*LOFF + (size_t)cell*HD + d];
    }
    __syncthreads();
    for (int o=threadIdx.x;o<OUTV;o+=blockDim.x){
        float acc = bo[o];
        #pragma unroll 8
        for (int k=0;k<4*HD;++k) acc += f[k]*Wo[(size_t)k*OUTV+o];
        out[(size_t)b*OUTV+o] = acc;
    }
}

// ---------------- host ----------------
extern "C" void kernel_launch(void* const* d_in, const int* in_sizes, int n_in,
                              void* d_out, int out_size)
{
    const int*   data  = (const int*)  d_in[0];
    const int*   tb    = (const int*)  d_in[1];
    const int*   fb    = (const int*)  d_in[2];
    const int*   exi   = (const int*)  d_in[3];
    const int*   steps = (const int*)  d_in[4];
    const float* embed = (const float*)d_in[5];
    const float* Wi    = (const float*)d_in[6];
    const float* Wh    = (const float*)d_in[7];
    const float* bl    = (const float*)d_in[8];
    const float* Wb    = (const float*)d_in[9];
    const float* bb    = (const float*)d_in[10];
    const float* Wo    = (const float*)d_in[11];
    const float* bo    = (const float*)d_in[12];
    float* out = (float*)d_out;

    float *c_st,*h_st,*c_tok,*h_tok0,*h_tok1,*xw,*ip,*wt,*wf;
    bf16 *hsth,*hstl,*hth0,*htl0,*hth1,*htl1,*embh,*embl;
    bf16 *w0xh,*w0xl,*w0hh,*w0hl,*w1h,*w1l;
    cudaGetSymbolAddress((void**)&c_st, g_c_st);
    cudaGetSymbolAddress((void**)&h_st, g_h_st);
    cudaGetSymbolAddress((void**)&hsth, g_hst_h);
    cudaGetSymbolAddress((void**)&hstl, g_hst_l);
    cudaGetSymbolAddress((void**)&c_tok, g_c_tok);
    { void* p; cudaGetSymbolAddress(&p, g_h_tok); h_tok0=(float*)p; h_tok1=h_tok0+NL*CELLS*HD; }
    { void* p; cudaGetSymbolAddress(&p, g_ht_h);  hth0=(bf16*)p; hth1=hth0+NL*CELLS*HD; }
    { void* p; cudaGetSymbolAddress(&p, g_ht_l);  htl0=(bf16*)p; htl1=htl0+NL*CELLS*HD; }
    cudaGetSymbolAddress((void**)&embh, g_emb_h);
    cudaGetSymbolAddress((void**)&embl, g_emb_l);
    cudaGetSymbolAddress((void**)&xw,   g_xw);
    cudaGetSymbolAddress((void**)&w0xh, g_w0x_h);
    cudaGetSymbolAddress((void**)&w0xl, g_w0x_l);
    cudaGetSymbolAddress((void**)&w0hh, g_w0h_h);
    cudaGetSymbolAddress((void**)&w0hl, g_w0h_l);
    cudaGetSymbolAddress((void**)&w1h,  g_w1_h);
    cudaGetSymbolAddress((void**)&w1l,  g_w1_l);
    cudaGetSymbolAddress((void**)&ip, g_ip);
    cudaGetSymbolAddress((void**)&wt, g_wt);
    cudaGetSymbolAddress((void**)&wf, g_wf);

    cudaFuncSetAttribute(tlstm<2,0>, cudaFuncAttributeMaxDynamicSharedMemorySize, TSMEM);
    cudaFuncSetAttribute(tlstm<2,1>, cudaFuncAttributeMaxDynamicSharedMemorySize, TSMEM);
    cudaFuncSetAttribute(tlstm<4,1>, cudaFuncAttributeMaxDynamicSharedMemorySize, TSMEM);

    size_t stbytes = sizeof(float)*NL*CELLS*HD;
    cudaMemsetAsync(c_st, 0, stbytes, 0);
    cudaMemsetAsync(h_st, 0, stbytes, 0);
    cudaMemsetAsync(hsth, 0, sizeof(bf16)*NL*CELLS*HD, 0);
    cudaMemsetAsync(hstl, 0, sizeof(bf16)*NL*CELLS*HD, 0);
    cudaMemsetAsync(ip,   0, sizeof(float)*CELLS, 0);
    ipinit_kernel<<<1,32>>>(ip);
    gather_kernel<<<(CELLS*NT*HD+255)/256,256>>>(data, embed, embh, embl);
    buildwt_kernel<<<(512*256+255)/256,256>>>(Wi, Wh, w0xh, w0xl, w0hh, w0hl, w1h, w1l);

    // xw = emb @ Wi(l0), permuted cols; M = CELLS*NT rows
    tlstm<2,0><<<dim3(CELLS*NT/128,4),256,TSMEM>>>(
        embh, embl, embh, embl, w0xh, w0xl, 128,
        nullptr, 0, nullptr, nullptr, nullptr, nullptr, nullptr, nullptr, xw);

    float* h_tok[2] = {h_tok0, h_tok1};
    bf16*  hth[2]   = {hth0, hth1};
    bf16*  htl[2]   = {htl0, htl1};

    for (int s = 0; s < MAXST; ++s){
        for (int t = 0; t < NT; ++t){
            int cur = t&1, prv = (t-1)&1;
            const bf16* hi0h = (t==0) ? hsth : hth[prv];
            const bf16* hi0l = (t==0) ? hstl : htl[prv];
            const float* ci0 = (t==0) ? c_st : c_tok;
            tlstm<2,1><<<dim3(CELLS/128,4),256,TSMEM>>>(
                hi0h, hi0l, hi0h, hi0l, w0hh, w0hl, 128,
                xw + t*512, NT*512, bl,
                ci0, c_tok, h_tok[cur], hth[cur], htl[cur], nullptr);
            const bf16* hi1h = (t==0) ? hsth + LOFF : hth[prv] + LOFF;
            const bf16* hi1l = (t==0) ? hstl + LOFF : htl[prv] + LOFF;
            const float* ci1 = (t==0) ? c_st + LOFF : c_tok + LOFF;
            tlstm<4,1><<<dim3(CELLS/128,4),256,TSMEM>>>(
                hth[cur], htl[cur], hi1h, hi1l, w1h, w1l, 256,
                nullptr, 0, bl + 512,
                ci1, c_tok + LOFF, h_tok[cur] + LOFF, hth[cur] + LOFF, htl[cur] + LOFF, nullptr);
        }
        float* hw = h_tok[(NT-1)&1];
        restore_kernel<<<NB,256>>>(exi, c_tok, hw, c_st, h_st);
        branch_kernel<<<(CELLS*32+255)/256,256>>>(
            c_tok, hw, c_tok+LOFF, hw+LOFF, Wb, bb, ip, wt, wf);
        agg_kernel<<<CELLS,128>>>(s, steps, tb, fb, wt, wf,
                                  c_tok, hw, c_st, h_st, hsth, hstl, ip);
    }
    final_kernel<<<NB,256>>>(exi, c_st, h_st, Wo, bo, out);
}

// round 5
// speedup vs baseline: 2.1840x; 2.1840x over previous
#include <cuda_runtime.h>
#include <cuda_bf16.h>
#include <cstdint>
#include <cstddef>

#define NB     16
#define NN     256
#define NT     4
#define HD     128
#define NL     2
#define CELLS  (NB*NN)
#define LOFF   (CELLS*HD)
#define MAXST  15
#define OUTV   1000
#define NCTA   128
#define ZSTR   132

typedef __nv_bfloat16 bf16;

// ---------------- device scratch ----------------
__device__ float g_c_st [NL*CELLS*HD];
__device__ float g_h_st [NL*CELLS*HD];
__device__ bf16  g_hst_h[NL*CELLS*HD];
__device__ bf16  g_hst_l[NL*CELLS*HD];
__device__ float g_c_tok[NL*CELLS*HD];
__device__ float g_hfin [NL*CELLS*HD];           // fp32 h of final token (cur==1)
__device__ bf16  g_ht_h [2][NL*CELLS*HD];
__device__ bf16  g_ht_l [2][NL*CELLS*HD];
__device__ bf16  g_emb_h[CELLS*NT*HD];
__device__ bf16  g_emb_l[CELLS*NT*HD];
__device__ float g_xw   [CELLS*NT*512];
__device__ bf16  g_w0x_h[512*128];
__device__ bf16  g_w0x_l[512*128];
__device__ bf16  g_w0h_h[512*128];
__device__ bf16  g_w0h_l[512*128];
__device__ bf16  g_w1_h [512*256];
__device__ bf16  g_w1_l [512*256];
__device__ float g_ip[CELLS], g_wtb[CELLS], g_wfb[CELLS];
__device__ float g_snapC[NB*2*HD], g_snapH[NB*2*HD];
__device__ int   g_csr_off[NB*NN];
__device__ int   g_csr_ent[NB*NN*2];
__device__ unsigned g_bar_ctr;
__device__ volatile unsigned g_bar_gen;

__device__ __forceinline__ float sigf(float x)  { return 1.0f/(1.0f+__expf(-x)); }
__device__ __forceinline__ float tanh_(float x) { return 2.0f/(1.0f+__expf(-2.0f*x))-1.0f; }

__device__ __forceinline__ uint32_t smem_u32(const void* p){
    uint32_t a; asm("{ .reg .u64 t; cvta.to.shared.u64 t, %1; cvt.u32.u64 %0, t; }":"=r"(a):"l"(p)); return a;
}
#define CPA16(d,s) asm volatile("cp.async.cg.shared.global [%0], [%1], 16;"::"r"(d),"l"((unsigned long long)__cvta_generic_to_global((const void*)(s))):"memory")
#define CP_COMMIT() asm volatile("cp.async.commit_group;":::"memory")

__device__ __forceinline__ void ldmx4(uint32_t* r, uint32_t a){
    asm volatile("ldmatrix.sync.aligned.m8n8.x4.shared.b16 {%0,%1,%2,%3}, [%4];"
        : "=r"(r[0]),"=r"(r[1]),"=r"(r[2]),"=r"(r[3]) : "r"(a));
}
__device__ __forceinline__ void ldmx2(uint32_t* r, uint32_t a){
    asm volatile("ldmatrix.sync.aligned.m8n8.x2.shared.b16 {%0,%1}, [%2];"
        : "=r"(r[0]),"=r"(r[1]) : "r"(a));
}
__device__ __forceinline__ void mmabf(float* d, const uint32_t* a, const uint32_t* b){
    asm volatile("mma.sync.aligned.m16n8k16.row.col.f32.bf16.bf16.f32 "
        "{%0,%1,%2,%3}, {%4,%5,%6,%7}, {%8,%9}, {%0,%1,%2,%3};"
        : "+f"(d[0]),"+f"(d[1]),"+f"(d[2]),"+f"(d[3])
        : "r"(a[0]),"r"(a[1]),"r"(a[2]),"r"(a[3]),"r"(b[0]),"r"(b[1]));
}

__device__ __forceinline__ void gridsync(){
    __syncthreads();
    if (threadIdx.x == 0){
        __threadfence();
        unsigned gen = g_bar_gen;
        if (atomicAdd(&g_bar_ctr, 1u) == (unsigned)(NCTA-1)){
            atomicExch(&g_bar_ctr, 0u);
            __threadfence();
            g_bar_gen = gen + 1u;
        } else {
            while (g_bar_gen == gen) { __nanosleep(64); }
        }
        __threadfence();
    }
    __syncthreads();
}

// ==================== persistent kernel ====================
__global__ __launch_bounds__(512,1) void persist(
    const int* __restrict__ exi, const int* __restrict__ steps,
    const float* __restrict__ bl, const float* __restrict__ Wb,
    const float* __restrict__ bb)
{
    extern __shared__ char dsm[];
    const uint32_t SM0 = smem_u32(dsm);
    const uint32_t SM  = (SM0 + 1023u) & ~1023u;
    char* base = dsm + (SM - SM0);
    const uint32_t WRES   = SM;             // 6 x 16KB: w0 hi chunks(2), w1 hi chunks(4)
    const uint32_t STREAM = SM + 98304u;    // 2 slots x 49152 (Ahi|Alo|Wlo)
    float* Zs    = (float*)(base + 98304);
    float* swt_s = (float*)(base + 98304);
    float* swf_s = (float*)(base + 99328);

    const int tid = threadIdx.x, lane = tid & 31, wid = tid >> 5;
    const int bid = blockIdx.x;
    const int rt = bid >> 2, nt = bid & 3, rowbase = rt * 128;
    const int mw = wid & 3, nwp = wid >> 2;

    // ---- load resident W_hi (once) ----
    {
        const bf16* w0 = g_w0h_h + (size_t)(nt*128)*128;
        const bf16* w1 = g_w1_h  + (size_t)(nt*128)*256;
        #pragma unroll
        for (int cc = 0; cc < 2; ++cc)
            #pragma unroll
            for (int i = 0; i < 2; ++i){
                int u = tid + i*512, row = u>>3, c16 = u&7;
                uint32_t sw = (uint32_t)(row*128 + ((c16^(row&7))*16));
                CPA16(WRES + cc*16384u + sw, w0 + (size_t)row*128 + cc*64 + c16*8);
            }
        #pragma unroll
        for (int cc = 0; cc < 4; ++cc)
            #pragma unroll
            for (int i = 0; i < 2; ++i){
                int u = tid + i*512, row = u>>3, c16 = u&7;
                uint32_t sw = (uint32_t)(row*128 + ((c16^(row&7))*16));
                CPA16(WRES + 32768u + cc*16384u + sw, w1 + (size_t)row*256 + cc*64 + c16*8);
            }
        CP_COMMIT();
        asm volatile("cp.async.wait_group 0;":::"memory");
        __syncthreads();
    }

    // ---- fused GEMM + LSTM gate phase ----
    auto gemm = [&](const bf16* a0h, const bf16* a0l,
                    const bf16* a1h, const bf16* a1l,
                    uint32_t wres, const bf16* wlo, int kw, int nch,
                    const float* zinit, int szinit, const float* bias,
                    const float* cin, float* cout,
                    float* hout, bf16* houth, bf16* houtl)
    {
        float acc[2][4][4];
        #pragma unroll
        for (int mt=0;mt<2;++mt)
            #pragma unroll
            for (int n8=0;n8<4;++n8)
                #pragma unroll
                for (int e=0;e<4;++e) acc[mt][n8][e]=0.f;

        auto load_chunk = [&](int c){
            uint32_t slot = STREAM + (uint32_t)(c&1)*49152u;
            int kbase = c*64;
            #pragma unroll
            for (int i=0;i<2;++i){
                int u = tid + i*512, row = u>>3, c16 = u&7;
                uint32_t sw = (uint32_t)(row*128 + ((c16^(row&7))*16));
                int kg = kbase + c16*8;
                const bf16 *ah,*al;
                if (kg < 128){ size_t o=(size_t)(rowbase+row)*128+kg;       ah=a0h+o; al=a0l+o; }
                else         { size_t o=(size_t)(rowbase+row)*128+(kg-128); ah=a1h+o; al=a1l+o; }
                CPA16(slot + sw,          ah);
                CPA16(slot + 16384u + sw, al);
                CPA16(slot + 32768u + sw, wlo + (size_t)row*kw + kg);
            }
            CP_COMMIT();
        };

        const uint32_t axor = (uint32_t)((lane&7)<<4);
        const int arow = mw*32 + (lane&15);
        const uint32_t acolh = (uint32_t)((lane>>4)*16);
        const int brow = nwp*32 + (lane&7);
        const uint32_t bcolh = (uint32_t)(((lane>>3)&1)*16);
        const uint32_t bxor = (uint32_t)((lane&7)<<4);

        load_chunk(0);
        for (int c = 0; c < nch; ++c){
            if (c + 1 < nch) load_chunk(c + 1);
            if (c + 1 < nch) asm volatile("cp.async.wait_group 1;":::"memory");
            else             asm volatile("cp.async.wait_group 0;":::"memory");
            __syncthreads();
            uint32_t slot = STREAM + (uint32_t)(c&1)*49152u;
            uint32_t whi  = wres + (uint32_t)c*16384u;
            #pragma unroll
            for (int kk = 0; kk < 4; ++kk){
                uint32_t ah2[2][4], al2[2][4];
                #pragma unroll
                for (int mt = 0; mt < 2; ++mt){
                    uint32_t off = (uint32_t)((arow + mt*16)*128) + (((uint32_t)(kk*32) + acolh) ^ axor);
                    ldmx4(ah2[mt], slot + off);
                    ldmx4(al2[mt], slot + 16384u + off);
                }
                uint32_t bh[4][2], bl2[4][2];
                #pragma unroll
                for (int n8 = 0; n8 < 4; ++n8){
                    uint32_t off = (uint32_t)((brow + n8*8)*128) + (((uint32_t)(kk*32) + bcolh) ^ bxor);
                    ldmx2(bh[n8],  whi + off);
                    ldmx2(bl2[n8], slot + 32768u + off);
                }
                #pragma unroll
                for (int mt = 0; mt < 2; ++mt)
                    #pragma unroll
                    for (int n8 = 0; n8 < 4; ++n8){
                        mmabf(acc[mt][n8], ah2[mt], bh[n8]);
                        mmabf(acc[mt][n8], ah2[mt], bl2[n8]);
                        mmabf(acc[mt][n8], al2[mt], bh[n8]);
                    }
            }
            __syncthreads();
        }

        // dump accumulators to Z
        {
            const int qr = lane >> 2, qc = (lane & 3) * 2;
            #pragma unroll
            for (int mt = 0; mt < 2; ++mt){
                int r0 = mw*32 + mt*16 + qr;
                #pragma unroll
                for (int n8 = 0; n8 < 4; ++n8){
                    int c0 = nwp*32 + n8*8 + qc;
                    Zs[r0*ZSTR + c0]         = acc[mt][n8][0];
                    Zs[r0*ZSTR + c0 + 1]     = acc[mt][n8][1];
                    Zs[(r0+8)*ZSTR + c0]     = acc[mt][n8][2];
                    Zs[(r0+8)*ZSTR + c0 + 1] = acc[mt][n8][3];
                }
            }
        }
        __syncthreads();

        // gate epilogue
        {
            const int row = tid >> 2, jb = (tid & 3) * 8;
            const int cell = rowbase + row;
            const float* zr = zinit ? zinit + (size_t)cell*szinit + nt*128 : nullptr;
            #pragma unroll
            for (int jj = 0; jj < 8; ++jj){
                int j = jb + jj;
                int d = nt*32 + j;
                float vi = Zs[row*ZSTR + j]      + bias[d];
                float vf = Zs[row*ZSTR + 32 + j] + bias[128 + d];
                float vg = Zs[row*ZSTR + 64 + j] + bias[256 + d];
                float vo = Zs[row*ZSTR + 96 + j] + bias[384 + d];
                if (zr){ vi += zr[j]; vf += zr[32+j]; vg += zr[64+j]; vo += zr[96+j]; }
                float cold = __ldcg(cin + (size_t)cell*128 + d);
                float c2 = sigf(vf)*cold + sigf(vi)*tanh_(vg);
                float hv = sigf(vo)*tanh_(c2);
                cout[(size_t)cell*128 + d] = c2;
                if (hout) hout[(size_t)cell*128 + d] = hv;
                bf16 hh = __float2bfloat16(hv);
                houth[(size_t)cell*128 + d] = hh;
                houtl[(size_t)cell*128 + d] = __float2bfloat16(hv - __bfloat162float(hh));
            }
        }
        __syncthreads();
    };

    // ==================== main loop ====================
    for (int s = 0; s < MAXST; ++s){
        for (int t = 0; t < NT; ++t){
            int cur = t & 1, prv = (t-1) & 1;
            const bf16* h0h = (t==0) ? g_hst_h : g_ht_h[prv];
            const bf16* h0l = (t==0) ? g_hst_l : g_ht_l[prv];
            const float* ci0 = (t==0) ? g_c_st : g_c_tok;
            gemm(h0h, h0l, h0h, h0l,
                 WRES, g_w0h_l + (size_t)(nt*128)*128, 128, 2,
                 g_xw + t*512, NT*512, bl,
                 ci0, g_c_tok,
                 (cur ? g_hfin : nullptr), g_ht_h[cur], g_ht_l[cur]);
            gridsync();

            const bf16* h1h = (t==0) ? g_hst_h + LOFF : g_ht_h[prv] + LOFF;
            const bf16* h1l = (t==0) ? g_hst_l + LOFF : g_ht_l[prv] + LOFF;
            const float* ci1 = (t==0) ? g_c_st + LOFF : g_c_tok + LOFF;
            gemm(g_ht_h[cur], g_ht_l[cur], h1h, h1l,
                 WRES + 32768u, g_w1_l + (size_t)(nt*128)*256, 256, 4,
                 nullptr, 0, bl + 512,
                 ci1, g_c_tok + LOFF,
                 (cur ? g_hfin + LOFF : nullptr), g_ht_h[cur] + LOFF, g_ht_l[cur] + LOFF);
            gridsync();
        }

        // ---- branch phase (+ exit snapshot) ----
        {
            #pragma unroll
            for (int q = 0; q < 2; ++q){
                int cell = bid*32 + wid*2 + q;
                int b = cell >> 8;
                int ecell = b*256 + exi[b];
                const float* pc = (cell == ecell) ? g_c_st : g_c_tok;
                const float* ph = (cell == ecell) ? g_h_st : g_hfin;
                float a0 = 0.f, a1 = 0.f;
                #pragma unroll
                for (int arr = 0; arr < 4; ++arr){
                    const float* p = ((arr & 1) ? ph : pc) + (size_t)(arr>>1)*LOFF + (size_t)cell*128;
                    #pragma unroll
                    for (int d = lane; d < 128; d += 32){
                        float v = __ldcg(p + d);
                        int fi = (arr*128 + d) * 2;
                        a0 += v * __ldg(Wb + fi);
                        a1 += v * __ldg(Wb + fi + 1);
                    }
                }
                #pragma unroll
                for (int o2 = 16; o2; o2 >>= 1){
                    a0 += __shfl_xor_sync(~0u, a0, o2);
                    a1 += __shfl_xor_sync(~0u, a1, o2);
                }
                if (lane == 0){
                    a0 += bb[0]; a1 += bb[1];
                    float m = fmaxf(a0, a1), e0 = __expf(a0 - m), e1 = __expf(a1 - m);
                    float inv = 1.0f/(e0 + e1), w = __ldcg(g_ip + cell);
                    g_wtb[cell] = e0*inv*w;
                    g_wfb[cell] = e1*inv*w;
                }
            }
            if (bid < NB){
                int b = bid, ecell = b*256 + exi[b];
                int d = tid & 127, l = (tid>>7) & 1, which = tid >> 8;
                size_t o = (size_t)l*LOFF + (size_t)ecell*128 + d;
                if (which == 0) g_snapC[b*256 + l*128 + d] = __ldcg(g_c_st + o);
                else            g_snapH[b*256 + l*128 + d] = __ldcg(g_h_st + o);
            }
        }
        gridsync();

        // ---- aggregation phase (CSR) ----
        {
            int b = bid >> 3;
            if (s < steps[b]){
                for (int i = tid; i < NN; i += 512){
                    swt_s[i] = __ldcg(g_wtb + b*NN + i);
                    swf_s[i] = __ldcg(g_wfb + b*NN + i);
                }
                __syncthreads();
                int e = exi[b];
                #pragma unroll
                for (int ci = 0; ci < 8; ++ci){
                    int cell = bid*32 + ci*4 + (tid >> 7);
                    int d = tid & 127, dst = cell & 255;
                    int o0 = g_csr_off[b*NN + dst];
                    int o1 = (dst == NN-1) ? (b*2*NN + 2*NN) : g_csr_off[b*NN + dst + 1];
                    float a0=0.f, a1=0.f, a2=0.f, a3=0.f, ipn=0.f;
                    for (int qq = o0; qq < o1; ++qq){
                        int v = g_csr_ent[qq];
                        int src = v & 255;
                        float w = (v < 0) ? swf_s[src] : swt_s[src];
                        ipn += w;
                        if (src == e){
                            a0 += w * g_snapC[b*256 + d];
                            a1 += w * g_snapH[b*256 + d];
                            a2 += w * g_snapC[b*256 + 128 + d];
                            a3 += w * g_snapH[b*256 + 128 + d];
                        } else {
                            size_t o = (size_t)(b*NN + src)*128 + d;
                            a0 += w * __ldcg(g_c_tok + o);
                            a1 += w * __ldcg(g_hfin  + o);
                            a2 += w * __ldcg(g_c_tok + LOFF + o);
                            a3 += w * __ldcg(g_hfin  + LOFF + o);
                        }
                    }
                    float inv = 1.0f/(ipn + 1e-7f);
                    size_t od = (size_t)cell*128 + d;
                    float h0 = a1*inv, h1v = a3*inv;
                    g_c_st[od] = a0*inv;        g_h_st[od] = h0;
                    g_c_st[od+LOFF] = a2*inv;   g_h_st[od+LOFF] = h1v;
                    bf16 x0 = __float2bfloat16(h0), x1 = __float2bfloat16(h1v);
                    g_hst_h[od] = x0;        g_hst_l[od] = __float2bfloat16(h0 - __bfloat162float(x0));
                    g_hst_h[od+LOFF] = x1;   g_hst_l[od+LOFF] = __float2bfloat16(h1v - __bfloat162float(x1));
                    if (d == 0) g_ip[cell] = ipn;
                }
            }
        }
        gridsync();
    }
}

// ==================== xw precompute (standalone, proven R4 path) ====================
__global__ void __launch_bounds__(256,1) xwgemm()
{
    extern __shared__ char smem[];
    const uint32_t BUF0 = (smem_u32(smem) + 127u) & ~127u;
    float* Z = (float*)(smem + (BUF0 - smem_u32(smem)));
    const int tid = threadIdx.x, lane = tid & 31, wid = tid >> 5;
    const int mw = wid & 3, nw = wid >> 2;
    const int rowbase = blockIdx.x * 128, nt = blockIdx.y;
    const bf16* a0h = g_emb_h; const bf16* a0l = g_emb_l;
    const bf16* wth = g_w0x_h; const bf16* wtl = g_w0x_l;

    auto load_chunk = [&](int c){
        const uint32_t b = BUF0 + (uint32_t)(c & 1) * 65536u;
        const int kbase = c * 64;
        #pragma unroll
        for (int i = 0; i < 4; ++i){
            int u = tid + i * 256;
            int row = u >> 3, col16 = u & 7;
            uint32_t sw = (uint32_t)(row * 128 + ((col16 ^ (row & 7)) * 16));
            int kg = kbase + col16 * 8;
            size_t o = (size_t)(rowbase + row) * 128 + kg;
            CPA16(b + sw,         a0h + o);
            CPA16(b + 16384 + sw, a0l + o);
            size_t wo = (size_t)(nt * 128 + row) * 128 + kg;
            CPA16(b + 32768 + sw, wth + wo);
            CPA16(b + 49152 + sw, wtl + wo);
        }
        CP_COMMIT();
    };

    float acc[2][8][4];
    #pragma unroll
    for (int mt=0;mt<2;++mt)
        #pragma unroll
        for (int n8=0;n8<8;++n8)
            #pragma unroll
            for (int e=0;e<4;++e) acc[mt][n8][e]=0.f;

    const int arow = mw * 32 + (lane & 15);
    const uint32_t arbase = (uint32_t)(arow * 128);
    const uint32_t axr = (uint32_t)((arow & 7) << 4);
    const uint32_t acolh = (uint32_t)((lane >> 4) * 16);
    const int brow = nw * 64 + (lane & 7);
    const uint32_t bcolh = (uint32_t)(((lane >> 3) & 1) * 16);

    load_chunk(0);
    #pragma unroll
    for (int c = 0; c < 2; ++c){
        if (c + 1 < 2) load_chunk(c + 1);
        if (c + 1 < 2) asm volatile("cp.async.wait_group 1;":::"memory");
        else           asm volatile("cp.async.wait_group 0;":::"memory");
        __syncthreads();
        const uint32_t b = BUF0 + (uint32_t)(c & 1) * 65536u;
        #pragma unroll
        for (int kk = 0; kk < 4; ++kk){
            uint32_t ah[2][4], al[2][4];
            #pragma unroll
            for (int mt = 0; mt < 2; ++mt){
                uint32_t off = (uint32_t)(mt * 16 * 128) + arbase + (((uint32_t)(kk * 32) + acolh) ^ axr);
                ldmx4(ah[mt], b + off);
                ldmx4(al[mt], b + 16384 + off);
            }
            uint32_t bh[8][2], bl[8][2];
            #pragma unroll
            for (int n8 = 0; n8 < 8; ++n8){
                int r = brow + n8 * 8;
                uint32_t off = (uint32_t)(r * 128) + (((uint32_t)(kk * 32) + bcolh) ^ ((uint32_t)((r & 7) << 4)));
                ldmx2(bh[n8], b + 32768 + off);
                ldmx2(bl[n8], b + 49152 + off);
            }
            #pragma unroll
            for (int mt = 0; mt < 2; ++mt)
                #pragma unroll
                for (int n8 = 0; n8 < 8; ++n8){
                    mmabf(acc[mt][n8], ah[mt], bh[n8]);
                    mmabf(acc[mt][n8], ah[mt], bl[n8]);
                    mmabf(acc[mt][n8], al[mt], bh[n8]);
                }
        }
        __syncthreads();
    }
    {
        const int qr = lane >> 2, qc = (lane & 3) * 2;
        #pragma unroll
        for (int mt = 0; mt < 2; ++mt){
            int r0 = mw * 32 + mt * 16 + qr;
            #pragma unroll
            for (int n8 = 0; n8 < 8; ++n8){
                int c0 = nw * 64 + n8 * 8 + qc;
                Z[r0 * ZSTR + c0]           = acc[mt][n8][0];
                Z[r0 * ZSTR + c0 + 1]       = acc[mt][n8][1];
                Z[(r0 + 8) * ZSTR + c0]     = acc[mt][n8][2];
                Z[(r0 + 8) * ZSTR + c0 + 1] = acc[mt][n8][3];
            }
        }
    }
    __syncthreads();
    const int row = tid >> 1;
    const int cell = rowbase + row;
    const int cb = (tid & 1) * 64;
    float* zp = g_xw + (size_t)cell * 512 + nt * 128 + cb;
    #pragma unroll
    for (int q = 0; q < 16; ++q)
        *(float4*)(zp + q * 4) = *(float4*)&Z[row * ZSTR + cb + q * 4];
}

// ==================== setup / final kernels ====================
__global__ void gather_kernel(const int* __restrict__ data, const float* __restrict__ embed)
{
    int i = blockIdx.x*blockDim.x + threadIdx.x;
    if (i >= CELLS*NT*HD) return;
    float v = embed[(size_t)data[i>>7]*HD + (i&127)];
    bf16 h = __float2bfloat16(v);
    g_emb_h[i] = h; g_emb_l[i] = __float2bfloat16(v - __bfloat162float(h));
}

__global__ void buildwt_kernel(const float* __restrict__ Wi, const float* __restrict__ Wh)
{
    int i = blockIdx.x*blockDim.x + threadIdx.x;
    if (i < 512*256){
        int p = i>>8, k = i&255;
        int ntc = p>>7, c = p&127, g = c>>5, j = c&31;
        int orig = g*128 + ntc*32 + j;
        float v = (k<128) ? Wi[(size_t)(128+k)*512+orig] : Wh[(size_t)(128+(k-128))*512+orig];
        bf16 h = __float2bfloat16(v);
        g_w1_h[i] = h; g_w1_l[i] = __float2bfloat16(v - __bfloat162float(h));
    }
    if (i < 512*128){
        int p = i>>7, k = i&127;
        int ntc = p>>7, c = p&127, g = c>>5, j = c&31;
        int orig = g*128 + ntc*32 + j;
        float vx = Wi[(size_t)k*512+orig], vh = Wh[(size_t)k*512+orig];
        bf16 hx = __float2bfloat16(vx), hh = __float2bfloat16(vh);
        g_w0x_h[i] = hx; g_w0x_l[i] = __float2bfloat16(vx - __bfloat162float(hx));
        g_w0h_h[i] = hh; g_w0h_l[i] = __float2bfloat16(vh - __bfloat162float(hh));
    }
}

__global__ void ipinit_kernel(){ if (threadIdx.x < NB) g_ip[threadIdx.x*NN] = 1.0f; }

__global__ void csr_kernel(const int* __restrict__ tb, const int* __restrict__ fb)
{
    int b = blockIdx.x, dst = threadIdx.x;
    __shared__ int stb[NN], sfb[NN], ps[NN];
    stb[dst] = tb[b*NN+dst]; sfb[dst] = fb[b*NN+dst];
    __syncthreads();
    int cnt = 0;
    for (int ss = 0; ss < NN; ++ss) cnt += (stb[ss]==dst) + (sfb[ss]==dst);
    ps[dst] = cnt; __syncthreads();
    for (int o2 = 1; o2 < NN; o2 <<= 1){
        int v = (dst >= o2) ? ps[dst-o2] : 0;
        __syncthreads();
        ps[dst] += v;
        __syncthreads();
    }
    int start = ps[dst] - cnt;
    g_csr_off[b*NN + dst] = b*2*NN + start;
    int p = b*2*NN + start;
    for (int ss = 0; ss < NN; ++ss) if (stb[ss]==dst) g_csr_ent[p++] = ss;
    for (int ss = 0; ss < NN; ++ss) if (sfb[ss]==dst) g_csr_ent[p++] = ss | (int)0x80000000;
}

__global__ void final_kernel(const int* __restrict__ exi,
                             const float* __restrict__ Wo, const float* __restrict__ bo,
                             float* __restrict__ out)
{
    int b = blockIdx.x;
    __shared__ float f[4*HD];
    int cell = b*NN + exi[b];
    for (int i = threadIdx.x; i < 4*HD; i += blockDim.x){
        int l = i>>8, ch = (i>>7)&1, d = i&127;
        const float* src = ch ? g_h_st : g_c_st;
        f[i] = src[(size_t)l*LOFF + (size_t)cell*HD + d];
    }
    __syncthreads();
    for (int o = threadIdx.x; o < OUTV; o += blockDim.x){
        float acc = bo[o];
        #pragma unroll 8
        for (int k = 0; k < 4*HD; ++k) acc += f[k]*Wo[(size_t)k*OUTV + o];
        out[(size_t)b*OUTV + o] = acc;
    }
}

// ==================== host ====================
#define TSMEM_P  197632
#define TSMEM_XW (131072 + 128)

extern "C" void kernel_launch(void* const* d_in, const int* in_sizes, int n_in,
                              void* d_out, int out_size)
{
    const int*   data  = (const int*)  d_in[0];
    const int*   tb    = (const int*)  d_in[1];
    const int*   fb    = (const int*)  d_in[2];
    const int*   exi   = (const int*)  d_in[3];
    const int*   steps = (const int*)  d_in[4];
    const float* embed = (const float*)d_in[5];
    const float* Wi    = (const float*)d_in[6];
    const float* Wh    = (const float*)d_in[7];
    const float* bl    = (const float*)d_in[8];
    const float* Wb    = (const float*)d_in[9];
    const float* bb    = (const float*)d_in[10];
    const float* Wo    = (const float*)d_in[11];
    const float* bo    = (const float*)d_in[12];
    float* out = (float*)d_out;

    float *c_st, *h_st, *ip; bf16 *hsth, *hstl;
    cudaGetSymbolAddress((void**)&c_st, g_c_st);
    cudaGetSymbolAddress((void**)&h_st, g_h_st);
    cudaGetSymbolAddress((void**)&hsth, g_hst_h);
    cudaGetSymbolAddress((void**)&hstl, g_hst_l);
    cudaGetSymbolAddress((void**)&ip,   g_ip);

    cudaFuncSetAttribute(persist, cudaFuncAttributeMaxDynamicSharedMemorySize, TSMEM_P);
    cudaFuncSetAttribute(xwgemm,  cudaFuncAttributeMaxDynamicSharedMemorySize, TSMEM_XW);

    cudaMemsetAsync(c_st, 0, sizeof(float)*NL*CELLS*HD, 0);
    cudaMemsetAsync(h_st, 0, sizeof(float)*NL*CELLS*HD, 0);
    cudaMemsetAsync(hsth, 0, sizeof(bf16)*NL*CELLS*HD, 0);
    cudaMemsetAsync(hstl, 0, sizeof(bf16)*NL*CELLS*HD, 0);
    cudaMemsetAsync(ip,   0, sizeof(float)*CELLS, 0);
    ipinit_kernel<<<1, 32>>>();
    gather_kernel<<<(CELLS*NT*HD + 255)/256, 256>>>(data, embed);
    buildwt_kernel<<<(512*256 + 255)/256, 256>>>(Wi, Wh);
    csr_kernel<<<NB, NN>>>(tb, fb);

    xwgemm<<<dim3(CELLS*NT/128, 4), 256, TSMEM_XW>>>();

    persist<<<NCTA, 512, TSMEM_P>>>(exi, steps, bl, Wb, bb);

    final_kernel<<<NB, 256>>>(exi, Wo, bo, out);
}

// round 6
// speedup vs baseline: 2.2940x; 1.0503x over previous
#include <cuda_runtime.h>
#include <cuda_bf16.h>
#include <cstdint>
#include <cstddef>

#define NB     16
#define NN     256
#define NT     4
#define HD     128
#define NL     2
#define CELLS  (NB*NN)
#define LOFF   (CELLS*HD)
#define MAXST  15
#define OUTV   1000
#define NCTA   128
#define ZSTR   132

typedef __nv_bfloat16 bf16;

// ---------------- device scratch ----------------
__device__ float g_c_st [NL*CELLS*HD];
__device__ float g_h_st [NL*CELLS*HD];
__device__ bf16  g_hst_h[NL*CELLS*HD];
__device__ bf16  g_hst_l[NL*CELLS*HD];
__device__ float g_c_tok[NL*CELLS*HD];
__device__ float g_hfin [NL*CELLS*HD];
__device__ bf16  g_ht_h [2][NL*CELLS*HD];
__device__ bf16  g_ht_l [2][NL*CELLS*HD];
__device__ bf16  g_emb_h[CELLS*NT*HD];
__device__ bf16  g_emb_l[CELLS*NT*HD];
__device__ float g_xw   [CELLS*NT*512];
__device__ bf16  g_w0x_h[512*128];
__device__ bf16  g_w0x_l[512*128];
__device__ bf16  g_w0h_h[512*128];
__device__ bf16  g_w0h_l[512*128];
__device__ bf16  g_w1_h [512*256];
__device__ bf16  g_w1_l [512*256];
__device__ float g_ip[CELLS], g_wtb[CELLS], g_wfb[CELLS];
__device__ float g_snapC[NB*2*HD], g_snapH[NB*2*HD];
__device__ int   g_csr_off[NB*NN];
__device__ int   g_csr_ent[NB*NN*2];
__device__ unsigned g_bctr[NB];
__device__ unsigned g_bgen[NB];

__device__ __forceinline__ float sigf(float x)  { return 1.0f/(1.0f+__expf(-x)); }
__device__ __forceinline__ float tanh_(float x) { return 2.0f/(1.0f+__expf(-2.0f*x))-1.0f; }

__device__ __forceinline__ uint32_t smem_u32(const void* p){
    uint32_t a; asm("{ .reg .u64 t; cvta.to.shared.u64 t, %1; cvt.u32.u64 %0, t; }":"=r"(a):"l"(p)); return a;
}
#define CPA16(d,s) asm volatile("cp.async.cg.shared.global [%0], [%1], 16;"::"r"(d),"l"((unsigned long long)__cvta_generic_to_global((const void*)(s))):"memory")
#define CP_COMMIT() asm volatile("cp.async.commit_group;":::"memory")

__device__ __forceinline__ void ldmx4(uint32_t* r, uint32_t a){
    asm volatile("ldmatrix.sync.aligned.m8n8.x4.shared.b16 {%0,%1,%2,%3}, [%4];"
        : "=r"(r[0]),"=r"(r[1]),"=r"(r[2]),"=r"(r[3]) : "r"(a));
}
__device__ __forceinline__ void ldmx2(uint32_t* r, uint32_t a){
    asm volatile("ldmatrix.sync.aligned.m8n8.x2.shared.b16 {%0,%1}, [%2];"
        : "=r"(r[0]),"=r"(r[1]) : "r"(a));
}
__device__ __forceinline__ void mmabf(float* d, const uint32_t* a, const uint32_t* b){
    asm volatile("mma.sync.aligned.m16n8k16.row.col.f32.bf16.bf16.f32 "
        "{%0,%1,%2,%3}, {%4,%5,%6,%7}, {%8,%9}, {%0,%1,%2,%3};"
        : "+f"(d[0]),"+f"(d[1]),"+f"(d[2]),"+f"(d[3])
        : "r"(a[0]),"r"(a[1]),"r"(a[2]),"r"(a[3]),"r"(b[0]),"r"(b[1]));
}

// per-batch 8-CTA barrier (monotonic generation)
__device__ __forceinline__ void batchsync(int b, unsigned &cnt){
    __syncthreads();
    if (threadIdx.x == 0){
        __threadfence();
        unsigned t = ++cnt;
        if (atomicAdd(&g_bctr[b], 1u) == 7u){
            atomicExch(&g_bctr[b], 0u);
            __threadfence();
            *(volatile unsigned*)&g_bgen[b] = t;
        } else {
            while (*(volatile unsigned*)&g_bgen[b] < t) __nanosleep(32);
        }
        __threadfence();
    }
    __syncthreads();
}

// ==================== persistent kernel ====================
__global__ __launch_bounds__(512,1) void persist(
    const int* __restrict__ exi, const int* __restrict__ steps,
    const float* __restrict__ bl, const float* __restrict__ Wb,
    const float* __restrict__ bb)
{
    extern __shared__ char dsm[];
    const uint32_t SM0 = smem_u32(dsm);
    const uint32_t SM  = (SM0 + 1023u) & ~1023u;
    char* base = dsm + (SM - SM0);
    const uint32_t WRES   = SM;             // 6 x 16KB resident W hi
    const uint32_t STREAM = SM + 98304u;    // 2 slots x 49152 (Ahi|Alo|Wlo)
    float* Zs    = (float*)(base + 98304);
    float* swt_s = (float*)(base + 98304);
    float* swf_s = (float*)(base + 99328);

    const int tid = threadIdx.x, lane = tid & 31, wid = tid >> 5;
    const int bid = blockIdx.x;
    const int nt = bid & 3, rowbase = (bid >> 2) * 128;
    const int b = bid >> 3;
    const int mw = wid & 3, nwp = wid >> 2;

    // ---- load resident W_hi ----
    {
        const bf16* w0 = g_w0h_h + (size_t)(nt*128)*128;
        const bf16* w1 = g_w1_h  + (size_t)(nt*128)*256;
        #pragma unroll
        for (int cc = 0; cc < 2; ++cc)
            #pragma unroll
            for (int i = 0; i < 2; ++i){
                int u = tid + i*512, row = u>>3, c16 = u&7;
                uint32_t sw = (uint32_t)(row*128 + ((c16^(row&7))*16));
                CPA16(WRES + cc*16384u + sw, w0 + (size_t)row*128 + cc*64 + c16*8);
            }
        #pragma unroll
        for (int cc = 0; cc < 4; ++cc)
            #pragma unroll
            for (int i = 0; i < 2; ++i){
                int u = tid + i*512, row = u>>3, c16 = u&7;
                uint32_t sw = (uint32_t)(row*128 + ((c16^(row&7))*16));
                CPA16(WRES + 32768u + cc*16384u + sw, w1 + (size_t)row*256 + cc*64 + c16*8);
            }
        CP_COMMIT();
        asm volatile("cp.async.wait_group 0;":::"memory");
        __syncthreads();
    }

    auto gemm = [&](const bf16* a0h, const bf16* a0l,
                    const bf16* a1h, const bf16* a1l,
                    uint32_t wres, const bf16* wlo, int kw, int nch,
                    const float* zinit, int szinit, const float* bias,
                    const float* cin, float* cout,
                    float* hout, bf16* houth, bf16* houtl)
    {
        float acc[2][4][4];
        #pragma unroll
        for (int mt=0;mt<2;++mt)
            #pragma unroll
            for (int n8=0;n8<4;++n8)
                #pragma unroll
                for (int e=0;e<4;++e) acc[mt][n8][e]=0.f;

        auto load_chunk = [&](int c){
            uint32_t slot = STREAM + (uint32_t)(c&1)*49152u;
            int kbase = c*64;
            #pragma unroll
            for (int i=0;i<2;++i){
                int u = tid + i*512, row = u>>3, c16 = u&7;
                uint32_t sw = (uint32_t)(row*128 + ((c16^(row&7))*16));
                int kg = kbase + c16*8;
                const bf16 *ah,*al;
                if (kg < 128){ size_t o=(size_t)(rowbase+row)*128+kg;       ah=a0h+o; al=a0l+o; }
                else         { size_t o=(size_t)(rowbase+row)*128+(kg-128); ah=a1h+o; al=a1l+o; }
                CPA16(slot + sw,          ah);
                CPA16(slot + 16384u + sw, al);
                CPA16(slot + 32768u + sw, wlo + (size_t)row*kw + kg);
            }
            CP_COMMIT();
        };

        const uint32_t axor = (uint32_t)((lane&7)<<4);
        const int arow = mw*32 + (lane&15);
        const uint32_t acolh = (uint32_t)((lane>>4)*16);
        const int brow = nwp*32 + (lane&7);
        const uint32_t bcolh = (uint32_t)(((lane>>3)&1)*16);

        load_chunk(0);
        for (int c = 0; c < nch; ++c){
            if (c + 1 < nch) load_chunk(c + 1);
            if (c + 1 < nch) asm volatile("cp.async.wait_group 1;":::"memory");
            else             asm volatile("cp.async.wait_group 0;":::"memory");
            __syncthreads();
            uint32_t slot = STREAM + (uint32_t)(c&1)*49152u;
            uint32_t whi  = wres + (uint32_t)c*16384u;
            #pragma unroll
            for (int kk = 0; kk < 4; ++kk){
                uint32_t ah2[2][4], al2[2][4];
                #pragma unroll
                for (int mt = 0; mt < 2; ++mt){
                    uint32_t off = (uint32_t)((arow + mt*16)*128) + (((uint32_t)(kk*32) + acolh) ^ axor);
                    ldmx4(ah2[mt], slot + off);
                    ldmx4(al2[mt], slot + 16384u + off);
                }
                uint32_t bh[4][2], bl2[4][2];
                #pragma unroll
                for (int n8 = 0; n8 < 4; ++n8){
                    uint32_t off = (uint32_t)((brow + n8*8)*128) + (((uint32_t)(kk*32) + bcolh) ^ axor);
                    ldmx2(bh[n8],  whi + off);
                    ldmx2(bl2[n8], slot + 32768u + off);
                }
                // pass-ordered: 8 independent accumulators between dependent MMAs
                #pragma unroll
                for (int mt = 0; mt < 2; ++mt)
                    #pragma unroll
                    for (int n8 = 0; n8 < 4; ++n8) mmabf(acc[mt][n8], ah2[mt], bh[n8]);
                #pragma unroll
                for (int mt = 0; mt < 2; ++mt)
                    #pragma unroll
                    for (int n8 = 0; n8 < 4; ++n8) mmabf(acc[mt][n8], ah2[mt], bl2[n8]);
                #pragma unroll
                for (int mt = 0; mt < 2; ++mt)
                    #pragma unroll
                    for (int n8 = 0; n8 < 4; ++n8) mmabf(acc[mt][n8], al2[mt], bh[n8]);
            }
            __syncthreads();
        }

        {
            const int qr = lane >> 2, qc = (lane & 3) * 2;
            #pragma unroll
            for (int mt = 0; mt < 2; ++mt){
                int r0 = mw*32 + mt*16 + qr;
                #pragma unroll
                for (int n8 = 0; n8 < 4; ++n8){
                    int c0 = nwp*32 + n8*8 + qc;
                    Zs[r0*ZSTR + c0]         = acc[mt][n8][0];
                    Zs[r0*ZSTR + c0 + 1]     = acc[mt][n8][1];
                    Zs[(r0+8)*ZSTR + c0]     = acc[mt][n8][2];
                    Zs[(r0+8)*ZSTR + c0 + 1] = acc[mt][n8][3];
                }
            }
        }
        __syncthreads();

        {
            const int row = tid >> 2, jb = (tid & 3) * 8;
            const int cell = rowbase + row;
            const float* zr = zinit ? zinit + (size_t)cell*szinit + nt*128 : nullptr;
            #pragma unroll
            for (int jj = 0; jj < 8; ++jj){
                int j = jb + jj;
                int d = nt*32 + j;
                float vi = Zs[row*ZSTR + j]      + bias[d];
                float vf = Zs[row*ZSTR + 32 + j] + bias[128 + d];
                float vg = Zs[row*ZSTR + 64 + j] + bias[256 + d];
                float vo = Zs[row*ZSTR + 96 + j] + bias[384 + d];
                if (zr){ vi += zr[j]; vf += zr[32+j]; vg += zr[64+j]; vo += zr[96+j]; }
                float cold = __ldcg(cin + (size_t)cell*128 + d);
                float c2 = sigf(vf)*cold + sigf(vi)*tanh_(vg);
                float hv = sigf(vo)*tanh_(c2);
                cout[(size_t)cell*128 + d] = c2;
                if (hout) hout[(size_t)cell*128 + d] = hv;
                bf16 hh = __float2bfloat16(hv);
                houth[(size_t)cell*128 + d] = hh;
                houtl[(size_t)cell*128 + d] = __float2bfloat16(hv - __bfloat162float(hh));
            }
        }
        __syncthreads();
    };

    auto gemm_l0 = [&](int t){
        int cur = t & 1, prv = (t-1) & 1;
        const bf16* h0h = (t==0) ? g_hst_h : g_ht_h[prv];
        const bf16* h0l = (t==0) ? g_hst_l : g_ht_l[prv];
        const float* ci0 = (t==0) ? g_c_st : g_c_tok;
        gemm(h0h, h0l, h0h, h0l,
             WRES, g_w0h_l + (size_t)(nt*128)*128, 128, 2,
             g_xw + t*512, NT*512, bl,
             ci0, g_c_tok,
             (cur ? g_hfin : nullptr), g_ht_h[cur], g_ht_l[cur]);
    };
    auto gemm_l1 = [&](int t){
        int cur = t & 1, prv = (t-1) & 1;
        const bf16* h1h = (t==0) ? g_hst_h + LOFF : g_ht_h[prv] + LOFF;
        const bf16* h1l = (t==0) ? g_hst_l + LOFF : g_ht_l[prv] + LOFF;
        const float* ci1 = (t==0) ? g_c_st + LOFF : g_c_tok + LOFF;
        gemm(g_ht_h[cur], g_ht_l[cur], h1h, h1l,
             WRES + 32768u, g_w1_l + (size_t)(nt*128)*256, 256, 4,
             nullptr, 0, bl + 512,
             ci1, g_c_tok + LOFF,
             (cur ? g_hfin + LOFF : nullptr), g_ht_h[cur] + LOFF, g_ht_l[cur] + LOFF);
    };

    unsigned scnt = 0;
    const int nsteps = __ldg(steps + b);

    for (int s = 0; s < nsteps; ++s){
        // P0: layer0 token0
        gemm_l0(0);
        batchsync(b, scnt);
        // Pk: {layer1(k-1), layer0(k)}
        #pragma unroll
        for (int k = 1; k <= 4; ++k){
            gemm_l1(k - 1);
            if (k < 4) gemm_l0(k);
            batchsync(b, scnt);
        }

        // ---- branch phase (+ exit snapshot) ----
        {
            #pragma unroll
            for (int q = 0; q < 2; ++q){
                int cell = bid*32 + wid*2 + q;
                int ecell = b*256 + __ldg(exi + b);
                const float* pc = (cell == ecell) ? g_c_st : g_c_tok;
                const float* ph = (cell == ecell) ? g_h_st : g_hfin;
                float a0 = 0.f, a1 = 0.f;
                #pragma unroll
                for (int arr = 0; arr < 4; ++arr){
                    const float* p = ((arr & 1) ? ph : pc) + (size_t)(arr>>1)*LOFF + (size_t)cell*128;
                    #pragma unroll
                    for (int d = lane; d < 128; d += 32){
                        float v = __ldcg(p + d);
                        int fi = (arr*128 + d) * 2;
                        a0 += v * __ldg(Wb + fi);
                        a1 += v * __ldg(Wb + fi + 1);
                    }
                }
                #pragma unroll
                for (int o2 = 16; o2; o2 >>= 1){
                    a0 += __shfl_xor_sync(~0u, a0, o2);
                    a1 += __shfl_xor_sync(~0u, a1, o2);
                }
                if (lane == 0){
                    a0 += bb[0]; a1 += bb[1];
                    float m = fmaxf(a0, a1), e0 = __expf(a0 - m), e1 = __expf(a1 - m);
                    float inv = 1.0f/(e0 + e1), w = __ldcg(g_ip + cell);
                    g_wtb[cell] = e0*inv*w;
                    g_wfb[cell] = e1*inv*w;
                }
            }
            if ((bid & 7) == 0){
                int ecell = b*256 + __ldg(exi + b);
                int d = tid & 127, l = (tid>>7) & 1, which = tid >> 8;
                size_t o = (size_t)l*LOFF + (size_t)ecell*128 + d;
                if (which == 0) g_snapC[b*256 + l*128 + d] = __ldcg(g_c_st + o);
                else            g_snapH[b*256 + l*128 + d] = __ldcg(g_h_st + o);
            }
        }
        batchsync(b, scnt);

        // ---- aggregation phase (CSR) ----
        {
            for (int i = tid; i < NN; i += 512){
                swt_s[i] = __ldcg(g_wtb + b*NN + i);
                swf_s[i] = __ldcg(g_wfb + b*NN + i);
            }
            __syncthreads();
            int e = __ldg(exi + b);
            #pragma unroll
            for (int ci = 0; ci < 8; ++ci){
                int cell = bid*32 + ci*4 + (tid >> 7);
                int d = tid & 127, dst = cell & 255;
                int o0 = g_csr_off[b*NN + dst];
                int o1 = (dst == NN-1) ? (b*2*NN + 2*NN) : g_csr_off[b*NN + dst + 1];
                float a0=0.f, a1=0.f, a2=0.f, a3=0.f, ipn=0.f;
                for (int qq = o0; qq < o1; ++qq){
                    int v = g_csr_ent[qq];
                    int src = v & 255;
                    float w = (v < 0) ? swf_s[src] : swt_s[src];
                    ipn += w;
                    if (src == e){
                        a0 += w * g_snapC[b*256 + d];
                        a1 += w * g_snapH[b*256 + d];
                        a2 += w * g_snapC[b*256 + 128 + d];
                        a3 += w * g_snapH[b*256 + 128 + d];
                    } else {
                        size_t o = (size_t)(b*NN + src)*128 + d;
                        a0 += w * __ldcg(g_c_tok + o);
                        a1 += w * __ldcg(g_hfin  + o);
                        a2 += w * __ldcg(g_c_tok + LOFF + o);
                        a3 += w * __ldcg(g_hfin  + LOFF + o);
                    }
                }
                float inv = 1.0f/(ipn + 1e-7f);
                size_t od = (size_t)cell*128 + d;
                float h0 = a1*inv, h1v = a3*inv;
                g_c_st[od] = a0*inv;        g_h_st[od] = h0;
                g_c_st[od+LOFF] = a2*inv;   g_h_st[od+LOFF] = h1v;
                bf16 x0 = __float2bfloat16(h0), x1 = __float2bfloat16(h1v);
                g_hst_h[od] = x0;        g_hst_l[od] = __float2bfloat16(h0 - __bfloat162float(x0));
                g_hst_h[od+LOFF] = x1;   g_hst_l[od+LOFF] = __float2bfloat16(h1v - __bfloat162float(x1));
                if (d == 0) g_ip[cell] = ipn;
            }
        }
        batchsync(b, scnt);
    }
}

// ==================== xw precompute ====================
__global__ void __launch_bounds__(256,1) xwgemm()
{
    extern __shared__ char smem[];
    const uint32_t BUF0 = (smem_u32(smem) + 127u) & ~127u;
    float* Z = (float*)(smem + (BUF0 - smem_u32(smem)));
    const int tid = threadIdx.x, lane = tid & 31, wid = tid >> 5;
    const int mw = wid & 3, nw = wid >> 2;
    const int rowbase = blockIdx.x * 128, nt = blockIdx.y;
    const bf16* a0h = g_emb_h; const bf16* a0l = g_emb_l;
    const bf16* wth = g_w0x_h; const bf16* wtl = g_w0x_l;

    auto load_chunk = [&](int c){
        const uint32_t b = BUF0 + (uint32_t)(c & 1) * 65536u;
        const int kbase = c * 64;
        #pragma unroll
        for (int i = 0; i < 4; ++i){
            int u = tid + i * 256;
            int row = u >> 3, col16 = u & 7;
            uint32_t sw = (uint32_t)(row * 128 + ((col16 ^ (row & 7)) * 16));
            int kg = kbase + col16 * 8;
            size_t o = (size_t)(rowbase + row) * 128 + kg;
            CPA16(b + sw,         a0h + o);
            CPA16(b + 16384 + sw, a0l + o);
            size_t wo = (size_t)(nt * 128 + row) * 128 + kg;
            CPA16(b + 32768 + sw, wth + wo);
            CPA16(b + 49152 + sw, wtl + wo);
        }
        CP_COMMIT();
    };

    float acc[2][8][4];
    #pragma unroll
    for (int mt=0;mt<2;++mt)
        #pragma unroll
        for (int n8=0;n8<8;++n8)
            #pragma unroll
            for (int e=0;e<4;++e) acc[mt][n8][e]=0.f;

    const int arow = mw * 32 + (lane & 15);
    const uint32_t arbase = (uint32_t)(arow * 128);
    const uint32_t axr = (uint32_t)((arow & 7) << 4);
    const uint32_t acolh = (uint32_t)((lane >> 4) * 16);
    const int brow = nw * 64 + (lane & 7);
    const uint32_t bcolh = (uint32_t)(((lane >> 3) & 1) * 16);

    load_chunk(0);
    #pragma unroll
    for (int c = 0; c < 2; ++c){
        if (c + 1 < 2) load_chunk(c + 1);
        if (c + 1 < 2) asm volatile("cp.async.wait_group 1;":::"memory");
        else           asm volatile("cp.async.wait_group 0;":::"memory");
        __syncthreads();
        const uint32_t b = BUF0 + (uint32_t)(c & 1) * 65536u;
        #pragma unroll
        for (int kk = 0; kk < 4; ++kk){
            uint32_t ah[2][4], al[2][4];
            #pragma unroll
            for (int mt = 0; mt < 2; ++mt){
                uint32_t off = (uint32_t)(mt * 16 * 128) + arbase + (((uint32_t)(kk * 32) + acolh) ^ axr);
                ldmx4(ah[mt], b + off);
                ldmx4(al[mt], b + 16384 + off);
            }
            uint32_t bh[8][2], bl[8][2];
            #pragma unroll
            for (int n8 = 0; n8 < 8; ++n8){
                int r = brow + n8 * 8;
                uint32_t off = (uint32_t)(r * 128) + (((uint32_t)(kk * 32) + bcolh) ^ ((uint32_t)((r & 7) << 4)));
                ldmx2(bh[n8], b + 32768 + off);
                ldmx2(bl[n8], b + 49152 + off);
            }
            #pragma unroll
            for (int mt = 0; mt < 2; ++mt)
                #pragma unroll
                for (int n8 = 0; n8 < 8; ++n8) mmabf(acc[mt][n8], ah[mt], bh[n8]);
            #pragma unroll
            for (int mt = 0; mt < 2; ++mt)
                #pragma unroll
                for (int n8 = 0; n8 < 8; ++n8) mmabf(acc[mt][n8], ah[mt], bl[n8]);
            #pragma unroll
            for (int mt = 0; mt < 2; ++mt)
                #pragma unroll
                for (int n8 = 0; n8 < 8; ++n8) mmabf(acc[mt][n8], al[mt], bh[n8]);
        }
        __syncthreads();
    }
    {
        const int qr = lane >> 2, qc = (lane & 3) * 2;
        #pragma unroll
        for (int mt = 0; mt < 2; ++mt){
            int r0 = mw * 32 + mt * 16 + qr;
            #pragma unroll
            for (int n8 = 0; n8 < 8; ++n8){
                int c0 = nw * 64 + n8 * 8 + qc;
                Z[r0 * ZSTR + c0]           = acc[mt][n8][0];
                Z[r0 * ZSTR + c0 + 1]       = acc[mt][n8][1];
                Z[(r0 + 8) * ZSTR + c0]     = acc[mt][n8][2];
                Z[(r0 + 8) * ZSTR + c0 + 1] = acc[mt][n8][3];
            }
        }
    }
    __syncthreads();
    const int row = tid >> 1;
    const int cell = rowbase + row;
    const int cb = (tid & 1) * 64;
    float* zp = g_xw + (size_t)cell * 512 + nt * 128 + cb;
    #pragma unroll
    for (int q = 0; q < 16; ++q)
        *(float4*)(zp + q * 4) = *(float4*)&Z[row * ZSTR + cb + q * 4];
}

// ==================== setup / final kernels ====================
__global__ void gather_kernel(const int* __restrict__ data, const float* __restrict__ embed)
{
    int i = blockIdx.x*blockDim.x + threadIdx.x;
    if (i >= CELLS*NT*HD) return;
    float v = embed[(size_t)data[i>>7]*HD + (i&127)];
    bf16 h = __float2bfloat16(v);
    g_emb_h[i] = h; g_emb_l[i] = __float2bfloat16(v - __bfloat162float(h));
}

__global__ void buildwt_kernel(const float* __restrict__ Wi, const float* __restrict__ Wh)
{
    int i = blockIdx.x*blockDim.x + threadIdx.x;
    if (i < 512*256){
        int p = i>>8, k = i&255;
        int ntc = p>>7, c = p&127, g = c>>5, j = c&31;
        int orig = g*128 + ntc*32 + j;
        float v = (k<128) ? Wi[(size_t)(128+k)*512+orig] : Wh[(size_t)(128+(k-128))*512+orig];
        bf16 h = __float2bfloat16(v);
        g_w1_h[i] = h; g_w1_l[i] = __float2bfloat16(v - __bfloat162float(h));
    }
    if (i < 512*128){
        int p = i>>7, k = i&127;
        int ntc = p>>7, c = p&127, g = c>>5, j = c&31;
        int orig = g*128 + ntc*32 + j;
        float vx = Wi[(size_t)k*512+orig], vh = Wh[(size_t)k*512+orig];
        bf16 hx = __float2bfloat16(vx), hh = __float2bfloat16(vh);
        g_w0x_h[i] = hx; g_w0x_l[i] = __float2bfloat16(vx - __bfloat162float(hx));
        g_w0h_h[i] = hh; g_w0h_l[i] = __float2bfloat16(vh - __bfloat162float(hh));
    }
}

__global__ void ipinit_kernel(){ if (threadIdx.x < NB) g_ip[threadIdx.x*NN] = 1.0f; }

__global__ void csr_kernel(const int* __restrict__ tb, const int* __restrict__ fb)
{
    int b = blockIdx.x, dst = threadIdx.x;
    __shared__ int stb[NN], sfb[NN], ps[NN];
    stb[dst] = tb[b*NN+dst]; sfb[dst] = fb[b*NN+dst];
    __syncthreads();
    int cnt = 0;
    for (int ss = 0; ss < NN; ++ss) cnt += (stb[ss]==dst) + (sfb[ss]==dst);
    ps[dst] = cnt; __syncthreads();
    for (int o2 = 1; o2 < NN; o2 <<= 1){
        int v = (dst >= o2) ? ps[dst-o2] : 0;
        __syncthreads();
        ps[dst] += v;
        __syncthreads();
    }
    int start = ps[dst] - cnt;
    g_csr_off[b*NN + dst] = b*2*NN + start;
    int p = b*2*NN + start;
    for (int ss = 0; ss < NN; ++ss) if (stb[ss]==dst) g_csr_ent[p++] = ss;
    for (int ss = 0; ss < NN; ++ss) if (sfb[ss]==dst) g_csr_ent[p++] = ss | (int)0x80000000;
}

__global__ void final_kernel(const int* __restrict__ exi,
                             const float* __restrict__ Wo, const float* __restrict__ bo,
                             float* __restrict__ out)
{
    int b = blockIdx.x;
    __shared__ float f[4*HD];
    int cell = b*NN + exi[b];
    for (int i = threadIdx.x; i < 4*HD; i += blockDim.x){
        int l = i>>8, ch = (i>>7)&1, d = i&127;
        const float* src = ch ? g_h_st : g_c_st;
        f[i] = src[(size_t)l*LOFF + (size_t)cell*HD + d];
    }
    __syncthreads();
    for (int o = threadIdx.x; o < OUTV; o += blockDim.x){
        float acc = bo[o];
        #pragma unroll 8
        for (int k = 0; k < 4*HD; ++k) acc += f[k]*Wo[(size_t)k*OUTV + o];
        out[(size_t)b*OUTV + o] = acc;
    }
}

// ==================== host ====================
#define TSMEM_P  197632
#define TSMEM_XW (131072 + 128)

extern "C" void kernel_launch(void* const* d_in, const int* in_sizes, int n_in,
                              void* d_out, int out_size)
{
    const int*   data  = (const int*)  d_in[0];
    const int*   tb    = (const int*)  d_in[1];
    const int*   fb    = (const int*)  d_in[2];
    const int*   exi   = (const int*)  d_in[3];
    const int*   steps = (const int*)  d_in[4];
    const float* embed = (const float*)d_in[5];
    const float* Wi    = (const float*)d_in[6];
    const float* Wh    = (const float*)d_in[7];
    const float* bl    = (const float*)d_in[8];
    const float* Wb    = (const float*)d_in[9];
    const float* bb    = (const float*)d_in[10];
    const float* Wo    = (const float*)d_in[11];
    const float* bo    = (const float*)d_in[12];
    float* out = (float*)d_out;

    float *c_st, *h_st, *ip; bf16 *hsth, *hstl;
    unsigned *bctr, *bgen;
    cudaGetSymbolAddress((void**)&c_st, g_c_st);
    cudaGetSymbolAddress((void**)&h_st, g_h_st);
    cudaGetSymbolAddress((void**)&hsth, g_hst_h);
    cudaGetSymbolAddress((void**)&hstl, g_hst_l);
    cudaGetSymbolAddress((void**)&ip,   g_ip);
    cudaGetSymbolAddress((void**)&bctr, g_bctr);
    cudaGetSymbolAddress((void**)&bgen, g_bgen);

    cudaFuncSetAttribute(persist, cudaFuncAttributeMaxDynamicSharedMemorySize, TSMEM_P);
    cudaFuncSetAttribute(xwgemm,  cudaFuncAttributeMaxDynamicSharedMemorySize, TSMEM_XW);

    cudaMemsetAsync(c_st, 0, sizeof(float)*NL*CELLS*HD, 0);
    cudaMemsetAsync(h_st, 0, sizeof(float)*NL*CELLS*HD, 0);
    cudaMemsetAsync(hsth, 0, sizeof(bf16)*NL*CELLS*HD, 0);
    cudaMemsetAsync(hstl, 0, sizeof(bf16)*NL*CELLS*HD, 0);
    cudaMemsetAsync(ip,   0, sizeof(float)*CELLS, 0);
    cudaMemsetAsync(bctr, 0, sizeof(unsigned)*NB, 0);
    cudaMemsetAsync(bgen, 0, sizeof(unsigned)*NB, 0);
    ipinit_kernel<<<1, 32>>>();
    gather_kernel<<<(CELLS*NT*HD + 255)/256, 256>>>(data, embed);
    buildwt_kernel<<<(512*256 + 255)/256, 256>>>(Wi, Wh);
    csr_kernel<<<NB, NN>>>(tb, fb);

    xwgemm<<<dim3(CELLS*NT/128, 4), 256, TSMEM_XW>>>();

    persist<<<NCTA, 512, TSMEM_P>>>(exi, steps, bl, Wb, bb);

    final_kernel<<<NB, 256>>>(exi, Wo, bo, out);
}

// round 7
// speedup vs baseline: 4.0788x; 1.7781x over previous
#include <cuda_runtime.h>
#include <cuda_bf16.h>
#include <cuda_fp16.h>
#include <cstdint>
#include <cstddef>

#define NB     16
#define NN     256
#define NT     4
#define HD     128
#define NL     2
#define CELLS  (NB*NN)
#define LOFF   (CELLS*HD)
#define MAXST  15
#define OUTV   1000
#define NCTA   128
#define ZSTR   132

typedef __nv_bfloat16 bf16;
typedef __half f16;

// ---------------- device scratch ----------------
__device__ float g_c_st [NL*CELLS*HD];
__device__ float g_h_st [NL*CELLS*HD];
__device__ float g_pubC [2][NL*CELLS*HD];
__device__ float g_pubH [2][NL*CELLS*HD];
__device__ bf16  g_emb_h[CELLS*NT*HD];
__device__ bf16  g_emb_l[CELLS*NT*HD];
__device__ float g_xw   [CELLS*NT*512];
__device__ bf16  g_w0x_h[512*128];
__device__ bf16  g_w0x_l[512*128];
__device__ f16   g_w0t  [512*128];     // Wh0^T, new permutation, fp16
__device__ f16   g_w1t  [512*256];     // [Wi1;Wh1]^T, new permutation, fp16
__device__ float g_wtb[2][CELLS], g_wfb[2][CELLS];
__device__ int   g_csr_off[NB*NN];
__device__ int   g_csr_ent[NB*NN*2];
__device__ unsigned g_bctr[NB];
__device__ unsigned g_bgen[NB];

__device__ __forceinline__ float sigf(float x)  { return 1.0f/(1.0f+__expf(-x)); }
__device__ __forceinline__ float tanh_(float x) { return 2.0f/(1.0f+__expf(-2.0f*x))-1.0f; }

__device__ __forceinline__ uint32_t smem_u32(const void* p){
    uint32_t a; asm("{ .reg .u64 t; cvta.to.shared.u64 t, %1; cvt.u32.u64 %0, t; }":"=r"(a):"l"(p)); return a;
}
#define CPA16(d,s) asm volatile("cp.async.cg.shared.global [%0], [%1], 16;"::"r"(d),"l"((unsigned long long)__cvta_generic_to_global((const void*)(s))):"memory")
#define CP_COMMIT() asm volatile("cp.async.commit_group;":::"memory")

__device__ __forceinline__ void ldmx4(uint32_t* r, uint32_t a){
    asm volatile("ldmatrix.sync.aligned.m8n8.x4.shared.b16 {%0,%1,%2,%3}, [%4];"
        : "=r"(r[0]),"=r"(r[1]),"=r"(r[2]),"=r"(r[3]) : "r"(a));
}
__device__ __forceinline__ void ldmx2(uint32_t* r, uint32_t a){
    asm volatile("ldmatrix.sync.aligned.m8n8.x2.shared.b16 {%0,%1}, [%2];"
        : "=r"(r[0]),"=r"(r[1]) : "r"(a));
}
__device__ __forceinline__ void mmaf16(float* d, const uint32_t* a, const uint32_t* b){
    asm volatile("mma.sync.aligned.m16n8k16.row.col.f32.f16.f16.f32 "
        "{%0,%1,%2,%3}, {%4,%5,%6,%7}, {%8,%9}, {%0,%1,%2,%3};"
        : "+f"(d[0]),"+f"(d[1]),"+f"(d[2]),"+f"(d[3])
        : "r"(a[0]),"r"(a[1]),"r"(a[2]),"r"(a[3]),"r"(b[0]),"r"(b[1]));
}
__device__ __forceinline__ void mmabf(float* d, const uint32_t* a, const uint32_t* b){
    asm volatile("mma.sync.aligned.m16n8k16.row.col.f32.bf16.bf16.f32 "
        "{%0,%1,%2,%3}, {%4,%5,%6,%7}, {%8,%9}, {%0,%1,%2,%3};"
        : "+f"(d[0]),"+f"(d[1]),"+f"(d[2]),"+f"(d[3])
        : "r"(a[0]),"r"(a[1]),"r"(a[2]),"r"(a[3]),"r"(b[0]),"r"(b[1]));
}

__device__ __forceinline__ void batchsync(int b, unsigned &cnt){
    __syncthreads();
    if (threadIdx.x == 0){
        __threadfence();
        unsigned t = ++cnt;
        if (atomicAdd(&g_bctr[b], 1u) == 7u){
            atomicExch(&g_bctr[b], 0u);
            __threadfence();
            *(volatile unsigned*)&g_bgen[b] = t;
        } else {
            while (*(volatile unsigned*)&g_bgen[b] < t) __nanosleep(32);
        }
        __threadfence();
    }
    __syncthreads();
}

// smem layout offsets (bytes, relative to 1KB-aligned base)
#define SW_OFF   0u          // W double buffer: 2 x 65536
#define H0H_OFF  131072u
#define H0L_OFF  139264u
#define H1H_OFF  147456u
#define H1L_OFF  155648u
#define C0_OFF   163840u
#define C1_OFF   180224u
#define SNAP_OFF 196608u     // c0s,c1s,h0s,h1s : 4 x 512B
#define SWT_OFF  198656u
#define SWF_OFF  199680u
#define IP_OFF   200704u
#define SM_NEED  (200832u + 1024u)

// read fp32 h from hi/lo fp16 swizzled buffers
__device__ __forceinline__ float hrd(const char* hh, const char* hl, int row, int d){
    uint32_t off = (uint32_t)(row*256) + ((uint32_t)((d>>3) ^ (row&7))<<4) + (uint32_t)((d&7)*2);
    return __half2float(*(const f16*)(hh+off)) + __half2float(*(const f16*)(hl+off));
}
__device__ __forceinline__ void hwr(char* hh, char* hl, int row, int d, float v){
    uint32_t off = (uint32_t)(row*256) + ((uint32_t)((d>>3) ^ (row&7))<<4) + (uint32_t)((d&7)*2);
    f16 x = __float2half(v);
    *(f16*)(hh+off) = x;
    *(f16*)(hl+off) = __float2half(v - __half2float(x));
}

// ==================== persistent kernel ====================
__global__ __launch_bounds__(512,1) void persist(
    const int* __restrict__ exi, const int* __restrict__ steps,
    const float* __restrict__ bl, const float* __restrict__ Wb,
    const float* __restrict__ bb)
{
    extern __shared__ char dsm[];
    const uint32_t S0 = smem_u32(dsm);
    const uint32_t S  = (S0 + 1023u) & ~1023u;
    char* base = dsm + (S - S0);
    char* h0h = base + H0H_OFF; char* h0l = base + H0L_OFF;
    char* h1h = base + H1H_OFF; char* h1l = base + H1L_OFF;
    float* c0 = (float*)(base + C0_OFF);
    float* c1 = (float*)(base + C1_OFF);
    float* snC0 = (float*)(base + SNAP_OFF);
    float* snC1 = snC0 + 128; float* snH0 = snC0 + 256; float* snH1 = snC0 + 384;
    float* swt = (float*)(base + SWT_OFF);
    float* swf = (float*)(base + SWF_OFF);
    float* ips = (float*)(base + IP_OFF);

    const int tid = threadIdx.x, lane = tid & 31, wid = tid >> 5;
    const int bid = blockIdx.x;
    const int b = bid >> 3, cell0 = bid * 32, lb = (bid & 7) * 32;
    const int mw = wid & 1, nw = wid >> 1;
    const int qr = lane >> 2, qc = (lane & 3) * 2;

    // init state
    for (int i = tid; i < 8192; i += 512){    // 32KB of h (4 bufs x 8KB) as u32
        ((uint32_t*)h0h)[i & 2047 ? 0 : 0] = 0;  // placeholder avoided below
    }
    for (int i = tid; i < 2048; i += 512){
        ((uint32_t*)h0h)[i] = 0; ((uint32_t*)h0l)[i] = 0;
        ((uint32_t*)h1h)[i] = 0; ((uint32_t*)h1l)[i] = 0;
        c0[i*2] = 0.f; c0[i*2+1] = 0.f; c1[i*2] = 0.f; c1[i*2+1] = 0.f;
    }
    if (tid < 32) ips[tid] = (cell0 + tid == b*256) ? 1.0f : 0.0f;
    __syncthreads();

    const int el = __ldg(exi + b);
    const bool owned = (el >> 5) == (bid & 7);
    const int eloc = el & 31;
    const int nsteps = __ldg(steps + b);

    // fused GEMM (M=32,N=512) + LSTM epilogue; A 2-term fp16, W 1-term fp16
    auto gemm = [&](int nslab, const f16* wsrc, int KK,
                    const char* aHi0, const char* aLo0,
                    const char* aHi1, const char* aLo1,
                    const float* xwp, const float* bias,
                    float* cbuf, char* hOh, char* hOl)
    {
        float acc[8][4];
        #pragma unroll
        for (int n8=0;n8<8;++n8){ acc[n8][0]=0.f; acc[n8][1]=0.f; acc[n8][2]=0.f; acc[n8][3]=0.f; }

        auto pref = [&](int s){
            uint32_t dst = S + SW_OFF + (uint32_t)(s&1)*65536u;
            const f16* src = wsrc + s*64;
            #pragma unroll
            for (int i = 0; i < 8; ++i){
                int idx = tid + i*512;
                int row = idx >> 3, c16 = idx & 7;
                CPA16(dst + (uint32_t)(row*128) + ((uint32_t)(c16 ^ (row&7))<<4),
                      src + (size_t)row*KK + c16*8);
            }
            CP_COMMIT();
        };

        pref(0);
        for (int s = 0; s < nslab; ++s){
            if (s + 1 < nslab) pref(s + 1);
            if (s + 1 < nslab) asm volatile("cp.async.wait_group 1;":::"memory");
            else               asm volatile("cp.async.wait_group 0;":::"memory");
            __syncthreads();
            uint32_t wb = S + SW_OFF + (uint32_t)(s&1)*65536u;
            #pragma unroll
            for (int kk = 0; kk < 4; ++kk){
                int kglob = s*64 + kk*16;
                const char* ah; const char* al; int kr;
                if (kglob < 128){ ah = aHi0; al = aLo0; kr = kglob; }
                else            { ah = aHi1; al = aLo1; kr = kglob - 128; }
                int row = mw*16 + (lane & 15);
                uint32_t u = (uint32_t)(((kr >> 3) + (lane >> 4)) ^ (row & 7));
                uint32_t aoff = (uint32_t)(row*256) + (u << 4);
                uint32_t Ah[4], Al[4];
                ldmx4(Ah, smem_u32(ah) + aoff);
                ldmx4(Al, smem_u32(al) + aoff);
                uint32_t B[8][2];
                #pragma unroll
                for (int n8 = 0; n8 < 8; ++n8){
                    int r = nw*64 + n8*8 + (lane & 7);
                    uint32_t boff = (uint32_t)(r*128) +
                        (((uint32_t)(kk*2 + ((lane>>3)&1)) ^ (uint32_t)(r&7)) << 4);
                    ldmx2(B[n8], wb + boff);
                }
                #pragma unroll
                for (int n8 = 0; n8 < 8; ++n8) mmaf16(acc[n8], Ah, B[n8]);
                #pragma unroll
                for (int n8 = 0; n8 < 8; ++n8) mmaf16(acc[n8], Al, B[n8]);
            }
            __syncthreads();
        }

        // epilogue: pure register gate math (gate-interleaved W permutation)
        #pragma unroll
        for (int rh = 0; rh < 2; ++rh){
            int row = mw*16 + qr + rh*8;
            int cell = cell0 + row;
            const float* xr = xwp ? xwp + (size_t)cell*2048 : nullptr;
            #pragma unroll
            for (int dd = 0; dd < 4; ++dd){
                int dlow = qc + (dd & 1) + (dd >> 1)*8;
                int hb = dd >> 1;
                int e = (dd & 1) + rh*2;
                int d = nw*16 + dlow;
                float vi = acc[hb][e]     + __ldg(bias + d);
                float vf = acc[2+hb][e]   + __ldg(bias + 128 + d);
                float vg = acc[4+hb][e]   + __ldg(bias + 256 + d);
                float vo = acc[6+hb][e]   + __ldg(bias + 384 + d);
                if (xr){
                    int pb = (d >> 5)*128 + (d & 31);
                    vi += __ldg(xr + pb);       vf += __ldg(xr + pb + 32);
                    vg += __ldg(xr + pb + 64);  vo += __ldg(xr + pb + 96);
                }
                float cold = cbuf[row*128 + d];
                float c2 = sigf(vf)*cold + sigf(vi)*tanh_(vg);
                float hv = sigf(vo)*tanh_(c2);
                cbuf[row*128 + d] = c2;
                hwr(hOh, hOl, row, d, hv);
            }
        }
        __syncthreads();
    };

    unsigned scnt = 0;
    for (int s = 0; s < nsteps; ++s){
        int par = s & 1;

        // snapshot exit cell state (pre-execute)
        if (owned){
            int a = tid >> 7, d = tid & 127;
            if (a == 0) snC0[d] = c0[eloc*128 + d];
            else if (a == 1) snC1[d] = c1[eloc*128 + d];
            else if (a == 2) snH0[d] = hrd(h0h, h0l, eloc, d);
            else             snH1[d] = hrd(h1h, h1l, eloc, d);
        }
        __syncthreads();

        // token loop — fully CTA-local
        for (int t = 0; t < NT; ++t){
            gemm(2, g_w0t, 128, h0h, h0l, h0h, h0l,
                 g_xw + t*512, bl, c0, h0h, h0l);
            gemm(4, g_w1t, 256, h0h, h0l, h1h, h1l,
                 nullptr, bl + 512, c1, h1h, h1l);
        }

        // restore exit cell
        if (owned){
            int a = tid >> 7, d = tid & 127;
            if (a == 0) c0[eloc*128 + d] = snC0[d];
            else if (a == 1) c1[eloc*128 + d] = snC1[d];
            else if (a == 2) hwr(h0h, h0l, eloc, d, snH0[d]);
            else             hwr(h1h, h1l, eloc, d, snH1[d]);
        }
        __syncthreads();

        // branch (own 32 cells) + publish
        {
            #pragma unroll
            for (int q = 0; q < 2; ++q){
                int i = wid*2 + q;
                float a0 = 0.f, a1 = 0.f;
                for (int d = lane; d < 128; d += 32){
                    float v0 = c0[i*128 + d];
                    float v1 = hrd(h0h, h0l, i, d);
                    float v2 = c1[i*128 + d];
                    float v3 = hrd(h1h, h1l, i, d);
                    a0 += v0*__ldg(Wb + 2*d)        + v1*__ldg(Wb + 2*(128+d))
                        + v2*__ldg(Wb + 2*(256+d))  + v3*__ldg(Wb + 2*(384+d));
                    a1 += v0*__ldg(Wb + 2*d+1)      + v1*__ldg(Wb + 2*(128+d)+1)
                        + v2*__ldg(Wb + 2*(256+d)+1)+ v3*__ldg(Wb + 2*(384+d)+1);
                }
                #pragma unroll
                for (int o2 = 16; o2; o2 >>= 1){
                    a0 += __shfl_xor_sync(~0u, a0, o2);
                    a1 += __shfl_xor_sync(~0u, a1, o2);
                }
                if (lane == 0){
                    a0 += __ldg(bb); a1 += __ldg(bb + 1);
                    float m = fmaxf(a0, a1), e0 = __expf(a0-m), e1 = __expf(a1-m);
                    float inv = 1.0f/(e0+e1), w = ips[i];
                    g_wtb[par][cell0 + i] = e0*inv*w;
                    g_wfb[par][cell0 + i] = e1*inv*w;
                }
            }
            for (int v = tid; v < 32*128; v += 512){
                int row = v >> 7, d = v & 127;
                size_t o = (size_t)(cell0 + row)*128 + d;
                g_pubC[par][o]        = c0[row*128 + d];
                g_pubC[par][o + LOFF] = c1[row*128 + d];
                g_pubH[par][o]        = hrd(h0h, h0l, row, d);
                g_pubH[par][o + LOFF] = hrd(h1h, h1l, row, d);
            }
        }
        batchsync(b, scnt);

        // aggregation (CSR), writes own cells' new state into smem
        for (int i = tid; i < 256; i += 512){
            swt[i] = __ldcg(&g_wtb[par][b*256 + i]);
            swf[i] = __ldcg(&g_wfb[par][b*256 + i]);
        }
        __syncthreads();
        #pragma unroll
        for (int it = 0; it < 8; ++it){
            int i = it*4 + (tid >> 7);
            int d = tid & 127;
            int dstb = lb + i;
            int o0 = g_csr_off[b*NN + dstb];
            int o1 = (dstb == NN-1) ? (b*2*NN + 2*NN) : g_csr_off[b*NN + dstb + 1];
            float a0=0.f, a1=0.f, a2=0.f, a3=0.f, ipn=0.f;
            for (int qq = o0; qq < o1; ++qq){
                int v = g_csr_ent[qq];
                int src = v & 255;
                float w = (v < 0) ? swf[src] : swt[src];
                ipn += w;
                size_t o = (size_t)(b*256 + src)*128 + d;
                a0 += w * __ldcg(&g_pubC[par][o]);
                a1 += w * __ldcg(&g_pubH[par][o]);
                a2 += w * __ldcg(&g_pubC[par][o + LOFF]);
                a3 += w * __ldcg(&g_pubH[par][o + LOFF]);
            }
            float inv = 1.0f/(ipn + 1e-7f);
            c0[i*128 + d] = a0*inv;
            c1[i*128 + d] = a2*inv;
            hwr(h0h, h0l, i, d, a1*inv);
            hwr(h1h, h1l, i, d, a3*inv);
            if (d == 0) ips[i] = ipn;
        }
        __syncthreads();
    }

    // publish final state
    for (int v = tid; v < 32*128; v += 512){
        int row = v >> 7, d = v & 127;
        size_t o = (size_t)(cell0 + row)*128 + d;
        g_c_st[o]        = c0[row*128 + d];
        g_c_st[o + LOFF] = c1[row*128 + d];
        g_h_st[o]        = hrd(h0h, h0l, row, d);
        g_h_st[o + LOFF] = hrd(h1h, h1l, row, d);
    }
}

// ==================== xw precompute (R4-proven bf16 3-pass) ====================
__global__ void __launch_bounds__(256,1) xwgemm()
{
    extern __shared__ char smem[];
    const uint32_t BUF0 = (smem_u32(smem) + 127u) & ~127u;
    float* Z = (float*)(smem + (BUF0 - smem_u32(smem)));
    const int tid = threadIdx.x, lane = tid & 31, wid = tid >> 5;
    const int mw = wid & 3, nw = wid >> 2;
    const int rowbase = blockIdx.x * 128, nt = blockIdx.y;

    auto load_chunk = [&](int c){
        const uint32_t b = BUF0 + (uint32_t)(c & 1) * 65536u;
        const int kbase = c * 64;
        #pragma unroll
        for (int i = 0; i < 4; ++i){
            int u = tid + i * 256;
            int row = u >> 3, col16 = u & 7;
            uint32_t sw = (uint32_t)(row * 128 + ((col16 ^ (row & 7)) * 16));
            int kg = kbase + col16 * 8;
            size_t o = (size_t)(rowbase + row) * 128 + kg;
            CPA16(b + sw,         g_emb_h + o);
            CPA16(b + 16384 + sw, g_emb_l + o);
            size_t wo = (size_t)(nt * 128 + row) * 128 + kg;
            CPA16(b + 32768 + sw, g_w0x_h + wo);
            CPA16(b + 49152 + sw, g_w0x_l + wo);
        }
        CP_COMMIT();
    };

    float acc[2][8][4];
    #pragma unroll
    for (int mt=0;mt<2;++mt)
        #pragma unroll
        for (int n8=0;n8<8;++n8)
            #pragma unroll
            for (int e=0;e<4;++e) acc[mt][n8][e]=0.f;

    const int arow = mw * 32 + (lane & 15);
    const uint32_t arbase = (uint32_t)(arow * 128);
    const uint32_t axr = (uint32_t)((arow & 7) << 4);
    const uint32_t acolh = (uint32_t)((lane >> 4) * 16);
    const int brow = nw * 64 + (lane & 7);
    const uint32_t bcolh = (uint32_t)(((lane >> 3) & 1) * 16);

    load_chunk(0);
    #pragma unroll
    for (int c = 0; c < 2; ++c){
        if (c + 1 < 2) load_chunk(c + 1);
        if (c + 1 < 2) asm volatile("cp.async.wait_group 1;":::"memory");
        else           asm volatile("cp.async.wait_group 0;":::"memory");
        __syncthreads();
        const uint32_t b = BUF0 + (uint32_t)(c & 1) * 65536u;
        #pragma unroll
        for (int kk = 0; kk < 4; ++kk){
            uint32_t ah[2][4], al[2][4];
            #pragma unroll
            for (int mt = 0; mt < 2; ++mt){
                uint32_t off = (uint32_t)(mt * 16 * 128) + arbase + (((uint32_t)(kk * 32) + acolh) ^ axr);
                ldmx4(ah[mt], b + off);
                ldmx4(al[mt], b + 16384 + off);
            }
            uint32_t bh[8][2], blr[8][2];
            #pragma unroll
            for (int n8 = 0; n8 < 8; ++n8){
                int r = brow + n8 * 8;
                uint32_t off = (uint32_t)(r * 128) + (((uint32_t)(kk * 32) + bcolh) ^ ((uint32_t)((r & 7) << 4)));
                ldmx2(bh[n8],  b + 32768 + off);
                ldmx2(blr[n8], b + 49152 + off);
            }
            #pragma unroll
            for (int mt = 0; mt < 2; ++mt)
                #pragma unroll
                for (int n8 = 0; n8 < 8; ++n8) mmabf(acc[mt][n8], ah[mt], bh[n8]);
            #pragma unroll
            for (int mt = 0; mt < 2; ++mt)
                #pragma unroll
                for (int n8 = 0; n8 < 8; ++n8) mmabf(acc[mt][n8], ah[mt], blr[n8]);
            #pragma unroll
            for (int mt = 0; mt < 2; ++mt)
                #pragma unroll
                for (int n8 = 0; n8 < 8; ++n8) mmabf(acc[mt][n8], al[mt], bh[n8]);
        }
        __syncthreads();
    }
    {
        const int qr = lane >> 2, qc = (lane & 3) * 2;
        #pragma unroll
        for (int mt = 0; mt < 2; ++mt){
            int r0 = mw * 32 + mt * 16 + qr;
            #pragma unroll
            for (int n8 = 0; n8 < 8; ++n8){
                int c0i = nw * 64 + n8 * 8 + qc;
                Z[r0 * ZSTR + c0i]           = acc[mt][n8][0];
                Z[r0 * ZSTR + c0i + 1]       = acc[mt][n8][1];
                Z[(r0 + 8) * ZSTR + c0i]     = acc[mt][n8][2];
                Z[(r0 + 8) * ZSTR + c0i + 1] = acc[mt][n8][3];
            }
        }
    }
    __syncthreads();
    const int row = tid >> 1;
    const int cell = rowbase + row;
    const int cb = (tid & 1) * 64;
    float* zp = g_xw + (size_t)cell * 512 + nt * 128 + cb;
    #pragma unroll
    for (int q = 0; q < 16; ++q)
        *(float4*)(zp + q * 4) = *(float4*)&Z[row * ZSTR + cb + q * 4];
}

// ==================== setup / final kernels ====================
__global__ void gather_kernel(const int* __restrict__ data, const float* __restrict__ embed)
{
    int i = blockIdx.x*blockDim.x + threadIdx.x;
    if (i >= CELLS*NT*HD) return;
    float v = embed[(size_t)data[i>>7]*HD + (i&127)];
    bf16 h = __float2bfloat16(v);
    g_emb_h[i] = h; g_emb_l[i] = __float2bfloat16(v - __bfloat162float(h));
}

__global__ void buildwt_kernel(const float* __restrict__ Wi, const float* __restrict__ Wh)
{
    int i = blockIdx.x*blockDim.x + threadIdx.x;
    // bf16 hi/lo of Wi(l0) with OLD permutation (for xwgemm)
    if (i < 512*128){
        int p = i>>7, k = i&127;
        int ntc = p>>7, c = p&127, g = c>>5, j = c&31;
        int orig = g*128 + ntc*32 + j;
        float vx = Wi[(size_t)k*512+orig];
        bf16 hx = __float2bfloat16(vx);
        g_w0x_h[i] = hx; g_w0x_l[i] = __float2bfloat16(vx - __bfloat162float(hx));
    }
    // fp16 Wh0 with NEW permutation: P(d,g) = (d>>4)*64 + g*16 + (d&15)
    if (i < 512*128){
        int p = i>>7, k = i&127;
        int d = (p>>6)*16 + (p&15), g = (p>>4)&3;
        int orig = g*128 + d;
        g_w0t[i] = __float2half(Wh[(size_t)k*512 + orig]);
    }
    // fp16 [Wi1;Wh1] with NEW permutation
    if (i < 512*256){
        int p = i>>8, k = i&255;
        int d = (p>>6)*16 + (p&15), g = (p>>4)&3;
        int orig = g*128 + d;
        float v = (k<128) ? Wi[(size_t)(128+k)*512+orig] : Wh[(size_t)(128+(k-128))*512+orig];
        g_w1t[i] = __float2half(v);
    }
}

__global__ void csr_kernel(const int* __restrict__ tb, const int* __restrict__ fb)
{
    int b = blockIdx.x, dst = threadIdx.x;
    __shared__ int stb[NN], sfb[NN], ps[NN];
    stb[dst] = tb[b*NN+dst]; sfb[dst] = fb[b*NN+dst];
    __syncthreads();
    int cnt = 0;
    for (int ss = 0; ss < NN; ++ss) cnt += (stb[ss]==dst) + (sfb[ss]==dst);
    ps[dst] = cnt; __syncthreads();
    for (int o2 = 1; o2 < NN; o2 <<= 1){
        int v = (dst >= o2) ? ps[dst-o2] : 0;
        __syncthreads();
        ps[dst] += v;
        __syncthreads();
    }
    int start = ps[dst] - cnt;
    g_csr_off[b*NN + dst] = b*2*NN + start;
    int p = b*2*NN + start;
    for (int ss = 0; ss < NN; ++ss) if (stb[ss]==dst) g_csr_ent[p++] = ss;
    for (int ss = 0; ss < NN; ++ss) if (sfb[ss]==dst) g_csr_ent[p++] = ss | (int)0x80000000;
}

__global__ void final_kernel(const int* __restrict__ exi,
                             const float* __restrict__ Wo, const float* __restrict__ bo,
                             float* __restrict__ out)
{
    int b = blockIdx.x;
    __shared__ float f[4*HD];
    int cell = b*NN + exi[b];
    for (int i = threadIdx.x; i < 4*HD; i += blockDim.x){
        int l = i>>8, ch = (i>>7)&1, d = i&127;
        const float* src = ch ? g_h_st : g_c_st;
        f[i] = src[(size_t)l*LOFF + (size_t)cell*HD + d];
    }
    __syncthreads();
    for (int o = threadIdx.x; o < OUTV; o += blockDim.x){
        float acc = bo[o];
        #pragma unroll 8
        for (int k = 0; k < 4*HD; ++k) acc += f[k]*Wo[(size_t)k*OUTV + o];
        out[(size_t)b*OUTV + o] = acc;
    }
}

// ==================== host ====================
#define TSMEM_XW (131072 + 128)

extern "C" void kernel_launch(void* const* d_in, const int* in_sizes, int n_in,
                              void* d_out, int out_size)
{
    const int*   data  = (const int*)  d_in[0];
    const int*   tb    = (const int*)  d_in[1];
    const int*   fb    = (const int*)  d_in[2];
    const int*   exi   = (const int*)  d_in[3];
    const int*   steps = (const int*)  d_in[4];
    const float* embed = (const float*)d_in[5];
    const float* Wi    = (const float*)d_in[6];
    const float* Wh    = (const float*)d_in[7];
    const float* bl    = (const float*)d_in[8];
    const float* Wb    = (const float*)d_in[9];
    const float* bb    = (const float*)d_in[10];
    const float* Wo    = (const float*)d_in[11];
    const float* bo    = (const float*)d_in[12];
    float* out = (float*)d_out;

    unsigned *bctr, *bgen;
    cudaGetSymbolAddress((void**)&bctr, g_bctr);
    cudaGetSymbolAddress((void**)&bgen, g_bgen);

    cudaFuncSetAttribute(persist, cudaFuncAttributeMaxDynamicSharedMemorySize, SM_NEED);
    cudaFuncSetAttribute(xwgemm,  cudaFuncAttributeMaxDynamicSharedMemorySize, TSMEM_XW);

    cudaMemsetAsync(bctr, 0, sizeof(unsigned)*NB, 0);
    cudaMemsetAsync(bgen, 0, sizeof(unsigned)*NB, 0);
    gather_kernel<<<(CELLS*NT*HD + 255)/256, 256>>>(data, embed);
    buildwt_kernel<<<(512*256 + 255)/256, 256>>>(Wi, Wh);
    csr_kernel<<<NB, NN>>>(tb, fb);

    xwgemm<<<dim3(CELLS*NT/128, 4), 256, TSMEM_XW>>>();

    persist<<<NCTA, 512, SM_NEED>>>(exi, steps, bl, Wb, bb);

    final_kernel<<<NB, 256>>>(exi, Wo, bo, out);
}

// round 8
// speedup vs baseline: 4.8797x; 1.1963x over previous
#include <cuda_runtime.h>
#include <cuda_bf16.h>
#include <cuda_fp16.h>
#include <cstdint>
#include <cstddef>

#define NB     16
#define NN     256
#define NT     4
#define HD     128
#define NL     2
#define CELLS  (NB*NN)
#define LOFF   (CELLS*HD)
#define MAXST  15
#define OUTV   1000
#define NCTA   128
#define ZSTR   132

typedef __nv_bfloat16 bf16;
typedef __half f16;

// ---------------- device scratch ----------------
__device__ float g_c_st [NL*CELLS*HD];
__device__ float g_h_st [NL*CELLS*HD];
__device__ float g_pubC [2][NL*CELLS*HD];
__device__ float g_pubH [2][NL*CELLS*HD];
__device__ bf16  g_emb_h[CELLS*NT*HD];
__device__ bf16  g_emb_l[CELLS*NT*HD];
__device__ float g_xw   [CELLS*NT*512];
__device__ bf16  g_w0x_h[512*128];
__device__ bf16  g_w0x_l[512*128];
__device__ f16   g_w0t  [512*128];     // Wh0^T, interleaved permutation, fp16
__device__ f16   g_w1t  [512*256];     // [Wi1;Wh1]^T, interleaved permutation, fp16
__device__ float g_wtb[2][CELLS], g_wfb[2][CELLS];
__device__ int   g_csr_off[NB*NN];
__device__ int   g_csr_ent[NB*NN*2];
__device__ unsigned g_bctr[NB];
__device__ unsigned g_bgen[NB];

__device__ __forceinline__ float sigf(float x)  { return 1.0f/(1.0f+__expf(-x)); }
__device__ __forceinline__ float tanh_(float x) { return 2.0f/(1.0f+__expf(-2.0f*x))-1.0f; }

__device__ __forceinline__ uint32_t smem_u32(const void* p){
    uint32_t a; asm("{ .reg .u64 t; cvta.to.shared.u64 t, %1; cvt.u32.u64 %0, t; }":"=r"(a):"l"(p)); return a;
}
#define CPA16(d,s) asm volatile("cp.async.cg.shared.global [%0], [%1], 16;"::"r"(d),"l"((unsigned long long)__cvta_generic_to_global((const void*)(s))):"memory")
#define CP_COMMIT() asm volatile("cp.async.commit_group;":::"memory")

__device__ __forceinline__ void ldmx4(uint32_t* r, uint32_t a){
    asm volatile("ldmatrix.sync.aligned.m8n8.x4.shared.b16 {%0,%1,%2,%3}, [%4];"
        : "=r"(r[0]),"=r"(r[1]),"=r"(r[2]),"=r"(r[3]) : "r"(a));
}
__device__ __forceinline__ void ldmx2(uint32_t* r, uint32_t a){
    asm volatile("ldmatrix.sync.aligned.m8n8.x2.shared.b16 {%0,%1}, [%2];"
        : "=r"(r[0]),"=r"(r[1]) : "r"(a));
}
__device__ __forceinline__ void mmaf16(float* d, const uint32_t* a, const uint32_t* b){
    asm volatile("mma.sync.aligned.m16n8k16.row.col.f32.f16.f16.f32 "
        "{%0,%1,%2,%3}, {%4,%5,%6,%7}, {%8,%9}, {%0,%1,%2,%3};"
        : "+f"(d[0]),"+f"(d[1]),"+f"(d[2]),"+f"(d[3])
        : "r"(a[0]),"r"(a[1]),"r"(a[2]),"r"(a[3]),"r"(b[0]),"r"(b[1]));
}
__device__ __forceinline__ void mmabf(float* d, const uint32_t* a, const uint32_t* b){
    asm volatile("mma.sync.aligned.m16n8k16.row.col.f32.bf16.bf16.f32 "
        "{%0,%1,%2,%3}, {%4,%5,%6,%7}, {%8,%9}, {%0,%1,%2,%3};"
        : "+f"(d[0]),"+f"(d[1]),"+f"(d[2]),"+f"(d[3])
        : "r"(a[0]),"r"(a[1]),"r"(a[2]),"r"(a[3]),"r"(b[0]),"r"(b[1]));
}

__device__ __forceinline__ void batchsync(int b, unsigned &cnt){
    __syncthreads();
    if (threadIdx.x == 0){
        __threadfence();
        unsigned t = ++cnt;
        if (atomicAdd(&g_bctr[b], 1u) == 7u){
            atomicExch(&g_bctr[b], 0u);
            __threadfence();
            *(volatile unsigned*)&g_bgen[b] = t;
        } else {
            while (*(volatile unsigned*)&g_bgen[b] < t) __nanosleep(32);
        }
        __threadfence();
    }
    __syncthreads();
}

// smem layout (bytes, from 1KB-aligned base)
#define SW_OFF   0u          // W double buffer: 2 x 65536
#define H0H_OFF  131072u
#define H1H_OFF  139264u
#define C0_OFF   147456u
#define C1_OFF   163840u
#define SNAP_OFF 180224u
#define SWT_OFF  182272u
#define SWF_OFF  183296u
#define IP_OFF   184320u
#define SM_NEED  (184448u + 1024u)

__device__ __forceinline__ float hrd1(const char* hh, int row, int d){
    uint32_t off = (uint32_t)(row*256) + ((uint32_t)((d>>3) ^ (row&7))<<4) + (uint32_t)((d&7)*2);
    return __half2float(*(const f16*)(hh+off));
}
__device__ __forceinline__ void hwr1(char* hh, int row, int d, float v){
    uint32_t off = (uint32_t)(row*256) + ((uint32_t)((d>>3) ^ (row&7))<<4) + (uint32_t)((d&7)*2);
    *(f16*)(hh+off) = __float2half(v);
}

// ==================== persistent kernel ====================
__global__ __launch_bounds__(512,1) void persist(
    const int* __restrict__ exi, const int* __restrict__ steps,
    const float* __restrict__ bl, const float* __restrict__ Wb,
    const float* __restrict__ bb)
{
    extern __shared__ char dsm[];
    const uint32_t S0 = smem_u32(dsm);
    const uint32_t S  = (S0 + 1023u) & ~1023u;
    char* base = dsm + (S - S0);
    char* h0h = base + H0H_OFF;
    char* h1h = base + H1H_OFF;
    float* c0 = (float*)(base + C0_OFF);
    float* c1 = (float*)(base + C1_OFF);
    float* snC0 = (float*)(base + SNAP_OFF);
    float* snC1 = snC0 + 128; float* snH0 = snC0 + 256; float* snH1 = snC0 + 384;
    float* swt = (float*)(base + SWT_OFF);
    float* swf = (float*)(base + SWF_OFF);
    float* ips = (float*)(base + IP_OFF);

    const int tid = threadIdx.x, lane = tid & 31, wid = tid >> 5;
    const int bid = blockIdx.x;
    const int b = bid >> 3, cell0 = bid * 32, lb = (bid & 7) * 32;
    const int mw = wid & 1, nw = wid >> 1;
    const int qr = lane >> 2, qc = (lane & 3) * 2;

    // init state
    for (int i = tid; i < 2048; i += 512){
        ((uint32_t*)h0h)[i] = 0; ((uint32_t*)h1h)[i] = 0;
    }
    for (int i = tid; i < 4096; i += 512){ c0[i] = 0.f; c1[i] = 0.f; }
    if (tid < 32) ips[tid] = (cell0 + tid == b*256) ? 1.0f : 0.0f;
    __syncthreads();

    const int el = __ldg(exi + b);
    const bool owned = (el >> 5) == (bid & 7);
    const int eloc = el & 31;
    const int nsteps = __ldg(steps + b);

    // fused GEMM (M=32,N=512) + LSTM epilogue; A fp16 1-term, W fp16 1-term
    auto gemm = [&](int nslab, const f16* wsrc, int KK,
                    const char* aHi0, const char* aHi1,
                    const float* xwp, const float* bias,
                    float* cbuf, char* hOh)
    {
        float acc[8][4];
        #pragma unroll
        for (int n8=0;n8<8;++n8){ acc[n8][0]=0.f; acc[n8][1]=0.f; acc[n8][2]=0.f; acc[n8][3]=0.f; }

        auto pref = [&](int s){
            uint32_t dst = S + SW_OFF + (uint32_t)(s&1)*65536u;
            const f16* src = wsrc + s*64;
            #pragma unroll
            for (int i = 0; i < 8; ++i){
                int idx = tid + i*512;
                int row = idx >> 3, c16 = idx & 7;
                CPA16(dst + (uint32_t)(row*128) + ((uint32_t)(c16 ^ (row&7))<<4),
                      src + (size_t)row*KK + c16*8);
            }
            CP_COMMIT();
        };

        pref(0);
        for (int s = 0; s < nslab; ++s){
            asm volatile("cp.async.wait_group 0;":::"memory");
            __syncthreads();
            if (s + 1 < nslab) pref(s + 1);
            uint32_t wb = S + SW_OFF + (uint32_t)(s&1)*65536u;
            #pragma unroll
            for (int kk = 0; kk < 4; ++kk){
                int kglob = s*64 + kk*16;
                const char* ah; int kr;
                if (kglob < 128){ ah = aHi0; kr = kglob; }
                else            { ah = aHi1; kr = kglob - 128; }
                int row = mw*16 + (lane & 15);
                uint32_t u = (uint32_t)(((kr >> 3) + (lane >> 4)) ^ (row & 7));
                uint32_t Ah[4];
                ldmx4(Ah, smem_u32(ah) + (uint32_t)(row*256) + (u << 4));
                uint32_t B[4][4];
                #pragma unroll
                for (int p = 0; p < 4; ++p){
                    int r = nw*64 + p*16 + ((lane >> 4) << 3) + (lane & 7);
                    uint32_t kh = (uint32_t)(kk*2 + ((lane >> 3) & 1));
                    ldmx4(B[p], wb + (uint32_t)(r*128) + ((kh ^ (uint32_t)(r & 7)) << 4));
                }
                #pragma unroll
                for (int p = 0; p < 4; ++p){
                    mmaf16(acc[2*p],   Ah, &B[p][0]);
                    mmaf16(acc[2*p+1], Ah, &B[p][2]);
                }
            }
        }
        __syncthreads();   // last MMA reads of h complete before epilogue writes

        // epilogue: register gate math (gate-interleaved W permutation)
        #pragma unroll
        for (int rh = 0; rh < 2; ++rh){
            int row = mw*16 + qr + rh*8;
            int cell = cell0 + row;
            const float* xr = xwp ? xwp + (size_t)cell*2048 : nullptr;
            #pragma unroll
            for (int dd = 0; dd < 4; ++dd){
                int dlow = qc + (dd & 1) + (dd >> 1)*8;
                int hb = dd >> 1;
                int e = (dd & 1) + rh*2;
                int d = nw*16 + dlow;
                float vi = acc[hb][e]     + __ldg(bias + d);
                float vf = acc[2+hb][e]   + __ldg(bias + 128 + d);
                float vg = acc[4+hb][e]   + __ldg(bias + 256 + d);
                float vo = acc[6+hb][e]   + __ldg(bias + 384 + d);
                if (xr){
                    int pb = (d >> 5)*128 + (d & 31);
                    vi += __ldg(xr + pb);       vf += __ldg(xr + pb + 32);
                    vg += __ldg(xr + pb + 64);  vo += __ldg(xr + pb + 96);
                }
                float cold = cbuf[row*128 + d];
                float c2 = sigf(vf)*cold + sigf(vi)*tanh_(vg);
                float hv = sigf(vo)*tanh_(c2);
                cbuf[row*128 + d] = c2;
                hwr1(hOh, row, d, hv);
            }
        }
        __syncthreads();
    };

    unsigned scnt = 0;
    for (int s = 0; s < nsteps; ++s){
        int par = s & 1;

        // snapshot exit cell state (pre-execute)
        if (owned){
            int a = tid >> 7, d = tid & 127;
            if (a == 0) snC0[d] = c0[eloc*128 + d];
            else if (a == 1) snC1[d] = c1[eloc*128 + d];
            else if (a == 2) snH0[d] = hrd1(h0h, eloc, d);
            else             snH1[d] = hrd1(h1h, eloc, d);
        }
        __syncthreads();

        // token loop — fully CTA-local
        for (int t = 0; t < NT; ++t){
            gemm(2, g_w0t, 128, h0h, h0h, g_xw + t*512, bl,       c0, h0h);
            gemm(4, g_w1t, 256, h0h, h1h, nullptr,      bl + 512, c1, h1h);
        }

        // restore exit cell
        if (owned){
            int a = tid >> 7, d = tid & 127;
            if (a == 0) c0[eloc*128 + d] = snC0[d];
            else if (a == 1) c1[eloc*128 + d] = snC1[d];
            else if (a == 2) hwr1(h0h, eloc, d, snH0[d]);
            else             hwr1(h1h, eloc, d, snH1[d]);
        }
        __syncthreads();

        // branch (own 32 cells) + publish
        {
            #pragma unroll
            for (int q = 0; q < 2; ++q){
                int i = wid*2 + q;
                float a0 = 0.f, a1 = 0.f;
                for (int d = lane; d < 128; d += 32){
                    float v0 = c0[i*128 + d];
                    float v1 = hrd1(h0h, i, d);
                    float v2 = c1[i*128 + d];
                    float v3 = hrd1(h1h, i, d);
                    a0 += v0*__ldg(Wb + 2*d)        + v1*__ldg(Wb + 2*(128+d))
                        + v2*__ldg(Wb + 2*(256+d))  + v3*__ldg(Wb + 2*(384+d));
                    a1 += v0*__ldg(Wb + 2*d+1)      + v1*__ldg(Wb + 2*(128+d)+1)
                        + v2*__ldg(Wb + 2*(256+d)+1)+ v3*__ldg(Wb + 2*(384+d)+1);
                }
                #pragma unroll
                for (int o2 = 16; o2; o2 >>= 1){
                    a0 += __shfl_xor_sync(~0u, a0, o2);
                    a1 += __shfl_xor_sync(~0u, a1, o2);
                }
                if (lane == 0){
                    a0 += __ldg(bb); a1 += __ldg(bb + 1);
                    float m = fmaxf(a0, a1), e0 = __expf(a0-m), e1 = __expf(a1-m);
                    float inv = 1.0f/(e0+e1), w = ips[i];
                    g_wtb[par][cell0 + i] = e0*inv*w;
                    g_wfb[par][cell0 + i] = e1*inv*w;
                }
            }
            for (int v = tid; v < 32*128; v += 512){
                int row = v >> 7, d = v & 127;
                size_t o = (size_t)(cell0 + row)*128 + d;
                g_pubC[par][o]        = c0[row*128 + d];
                g_pubC[par][o + LOFF] = c1[row*128 + d];
                g_pubH[par][o]        = hrd1(h0h, row, d);
                g_pubH[par][o + LOFF] = hrd1(h1h, row, d);
            }
        }
        batchsync(b, scnt);

        // aggregation (CSR)
        for (int i = tid; i < 256; i += 512){
            swt[i] = __ldcg(&g_wtb[par][b*256 + i]);
            swf[i] = __ldcg(&g_wfb[par][b*256 + i]);
        }
        __syncthreads();
        #pragma unroll
        for (int it = 0; it < 8; ++it){
            int i = it*4 + (tid >> 7);
            int d = tid & 127;
            int dstb = lb + i;
            int o0 = g_csr_off[b*NN + dstb];
            int o1 = (dstb == NN-1) ? (b*2*NN + 2*NN) : g_csr_off[b*NN + dstb + 1];
            float a0=0.f, a1=0.f, a2=0.f, a3=0.f, ipn=0.f;
            for (int qq = o0; qq < o1; ++qq){
                int v = g_csr_ent[qq];
                int src = v & 255;
                float w = (v < 0) ? swf[src] : swt[src];
                ipn += w;
                size_t o = (size_t)(b*256 + src)*128 + d;
                a0 += w * __ldcg(&g_pubC[par][o]);
                a1 += w * __ldcg(&g_pubH[par][o]);
                a2 += w * __ldcg(&g_pubC[par][o + LOFF]);
                a3 += w * __ldcg(&g_pubH[par][o + LOFF]);
            }
            float inv = 1.0f/(ipn + 1e-7f);
            c0[i*128 + d] = a0*inv;
            c1[i*128 + d] = a2*inv;
            hwr1(h0h, i, d, a1*inv);
            hwr1(h1h, i, d, a3*inv);
            if (d == 0) ips[i] = ipn;
        }
        __syncthreads();
    }

    // publish final state
    for (int v = tid; v < 32*128; v += 512){
        int row = v >> 7, d = v & 127;
        size_t o = (size_t)(cell0 + row)*128 + d;
        g_c_st[o]        = c0[row*128 + d];
        g_c_st[o + LOFF] = c1[row*128 + d];
        g_h_st[o]        = hrd1(h0h, row, d);
        g_h_st[o + LOFF] = hrd1(h1h, row, d);
    }
}

// ==================== xw precompute (bf16 3-pass, exact-ish) ====================
__global__ void __launch_bounds__(256,1) xwgemm()
{
    extern __shared__ char smem[];
    const uint32_t BUF0 = (smem_u32(smem) + 127u) & ~127u;
    float* Z = (float*)(smem + (BUF0 - smem_u32(smem)));
    const int tid = threadIdx.x, lane = tid & 31, wid = tid >> 5;
    const int mw = wid & 3, nw = wid >> 2;
    const int rowbase = blockIdx.x * 128, nt = blockIdx.y;

    auto load_chunk = [&](int c){
        const uint32_t b = BUF0 + (uint32_t)(c & 1) * 65536u;
        const int kbase = c * 64;
        #pragma unroll
        for (int i = 0; i < 4; ++i){
            int u = tid + i * 256;
            int row = u >> 3, col16 = u & 7;
            uint32_t sw = (uint32_t)(row * 128 + ((col16 ^ (row & 7)) * 16));
            int kg = kbase + col16 * 8;
            size_t o = (size_t)(rowbase + row) * 128 + kg;
            CPA16(b + sw,         g_emb_h + o);
            CPA16(b + 16384 + sw, g_emb_l + o);
            size_t wo = (size_t)(nt * 128 + row) * 128 + kg;
            CPA16(b + 32768 + sw, g_w0x_h + wo);
            CPA16(b + 49152 + sw, g_w0x_l + wo);
        }
        CP_COMMIT();
    };

    float acc[2][8][4];
    #pragma unroll
    for (int mt=0;mt<2;++mt)
        #pragma unroll
        for (int n8=0;n8<8;++n8)
            #pragma unroll
            for (int e=0;e<4;++e) acc[mt][n8][e]=0.f;

    const int arow = mw * 32 + (lane & 15);
    const uint32_t arbase = (uint32_t)(arow * 128);
    const uint32_t axr = (uint32_t)((arow & 7) << 4);
    const uint32_t acolh = (uint32_t)((lane >> 4) * 16);
    const int brow = nw * 64 + (lane & 7);
    const uint32_t bcolh = (uint32_t)(((lane >> 3) & 1) * 16);

    load_chunk(0);
    #pragma unroll
    for (int c = 0; c < 2; ++c){
        if (c + 1 < 2) load_chunk(c + 1);
        if (c + 1 < 2) asm volatile("cp.async.wait_group 1;":::"memory");
        else           asm volatile("cp.async.wait_group 0;":::"memory");
        __syncthreads();
        const uint32_t b = BUF0 + (uint32_t)(c & 1) * 65536u;
        #pragma unroll
        for (int kk = 0; kk < 4; ++kk){
            uint32_t ah[2][4], al[2][4];
            #pragma unroll
            for (int mt = 0; mt < 2; ++mt){
                uint32_t off = (uint32_t)(mt * 16 * 128) + arbase + (((uint32_t)(kk * 32) + acolh) ^ axr);
                ldmx4(ah[mt], b + off);
                ldmx4(al[mt], b + 16384 + off);
            }
            uint32_t bh[8][2], blr[8][2];
            #pragma unroll
            for (int n8 = 0; n8 < 8; ++n8){
                int r = brow + n8 * 8;
                uint32_t off = (uint32_t)(r * 128) + (((uint32_t)(kk * 32) + bcolh) ^ ((uint32_t)((r & 7) << 4)));
                ldmx2(bh[n8],  b + 32768 + off);
                ldmx2(blr[n8], b + 49152 + off);
            }
            #pragma unroll
            for (int mt = 0; mt < 2; ++mt)
                #pragma unroll
                for (int n8 = 0; n8 < 8; ++n8) mmabf(acc[mt][n8], ah[mt], bh[n8]);
            #pragma unroll
            for (int mt = 0; mt < 2; ++mt)
                #pragma unroll
                for (int n8 = 0; n8 < 8; ++n8) mmabf(acc[mt][n8], ah[mt], blr[n8]);
            #pragma unroll
            for (int mt = 0; mt < 2; ++mt)
                #pragma unroll
                for (int n8 = 0; n8 < 8; ++n8) mmabf(acc[mt][n8], al[mt], bh[n8]);
        }
        __syncthreads();
    }
    {
        const int qr = lane >> 2, qc = (lane & 3) * 2;
        #pragma unroll
        for (int mt = 0; mt < 2; ++mt){
            int r0 = mw * 32 + mt * 16 + qr;
            #pragma unroll
            for (int n8 = 0; n8 < 8; ++n8){
                int c0i = nw * 64 + n8 * 8 + qc;
                Z[r0 * ZSTR + c0i]           = acc[mt][n8][0];
                Z[r0 * ZSTR + c0i + 1]       = acc[mt][n8][1];
                Z[(r0 + 8) * ZSTR + c0i]     = acc[mt][n8][2];
                Z[(r0 + 8) * ZSTR + c0i + 1] = acc[mt][n8][3];
            }
        }
    }
    __syncthreads();
    const int row = tid >> 1;
    const int cell = rowbase + row;
    const int cb = (tid & 1) * 64;
    float* zp = g_xw + (size_t)cell * 512 + nt * 128 + cb;
    #pragma unroll
    for (int q = 0; q < 16; ++q)
        *(float4*)(zp + q * 4) = *(float4*)&Z[row * ZSTR + cb + q * 4];
}

// ==================== setup / final kernels ====================
__global__ void gather_kernel(const int* __restrict__ data, const float* __restrict__ embed)
{
    int i = blockIdx.x*blockDim.x + threadIdx.x;
    if (i >= CELLS*NT*HD) return;
    float v = embed[(size_t)data[i>>7]*HD + (i&127)];
    bf16 h = __float2bfloat16(v);
    g_emb_h[i] = h; g_emb_l[i] = __float2bfloat16(v - __bfloat162float(h));
}

__global__ void buildwt_kernel(const float* __restrict__ Wi, const float* __restrict__ Wh)
{
    int i = blockIdx.x*blockDim.x + threadIdx.x;
    // bf16 hi/lo of Wi(l0), OLD permutation (for xwgemm)
    if (i < 512*128){
        int p = i>>7, k = i&127;
        int ntc = p>>7, c = p&127, g = c>>5, j = c&31;
        int orig = g*128 + ntc*32 + j;
        float vx = Wi[(size_t)k*512+orig];
        bf16 hx = __float2bfloat16(vx);
        g_w0x_h[i] = hx; g_w0x_l[i] = __float2bfloat16(vx - __bfloat162float(hx));
    }
    // fp16 Wh0, NEW permutation: p = (d>>4)*64 + g*16 + (d&15)
    if (i < 512*128){
        int p = i>>7, k = i&127;
        int d = (p>>6)*16 + (p&15), g = (p>>4)&3;
        int orig = g*128 + d;
        g_w0t[i] = __float2half(Wh[(size_t)k*512 + orig]);
    }
    // fp16 [Wi1;Wh1], NEW permutation
    if (i < 512*256){
        int p = i>>8, k = i&255;
        int d = (p>>6)*16 + (p&15), g = (p>>4)&3;
        int orig = g*128 + d;
        float v = (k<128) ? Wi[(size_t)(128+k)*512+orig] : Wh[(size_t)(128+(k-128))*512+orig];
        g_w1t[i] = __float2half(v);
    }
}

__global__ void csr_kernel(const int* __restrict__ tb, const int* __restrict__ fb)
{
    int b = blockIdx.x, dst = threadIdx.x;
    __shared__ int stb[NN], sfb[NN], ps[NN];
    stb[dst] = tb[b*NN+dst]; sfb[dst] = fb[b*NN+dst];
    __syncthreads();
    int cnt = 0;
    for (int ss = 0; ss < NN; ++ss) cnt += (stb[ss]==dst) + (sfb[ss]==dst);
    ps[dst] = cnt; __syncthreads();
    for (int o2 = 1; o2 < NN; o2 <<= 1){
        int v = (dst >= o2) ? ps[dst-o2] : 0;
        __syncthreads();
        ps[dst] += v;
        __syncthreads();
    }
    int start = ps[dst] - cnt;
    g_csr_off[b*NN + dst] = b*2*NN + start;
    int p = b*2*NN + start;
    for (int ss = 0; ss < NN; ++ss) if (stb[ss]==dst) g_csr_ent[p++] = ss;
    for (int ss = 0; ss < NN; ++ss) if (sfb[ss]==dst) g_csr_ent[p++] = ss | (int)0x80000000;
}

__global__ void final_kernel(const int* __restrict__ exi,
                             const float* __restrict__ Wo, const float* __restrict__ bo,
                             float* __restrict__ out)
{
    int b = blockIdx.x;
    __shared__ float f[4*HD];
    int cell = b*NN + exi[b];
    for (int i = threadIdx.x; i < 4*HD; i += blockDim.x){
        int l = i>>8, ch = (i>>7)&1, d = i&127;
        const float* src = ch ? g_h_st : g_c_st;
        f[i] = src[(size_t)l*LOFF + (size_t)cell*HD + d];
    }
    __syncthreads();
    for (int o = threadIdx.x; o < OUTV; o += blockDim.x){
        float acc = bo[o];
        #pragma unroll 8
        for (int k = 0; k < 4*HD; ++k) acc += f[k]*Wo[(size_t)k*OUTV + o];
        out[(size_t)b*OUTV + o] = acc;
    }
}

// ==================== host ====================
#define TSMEM_XW (131072 + 128)

extern "C" void kernel_launch(void* const* d_in, const int* in_sizes, int n_in,
                              void* d_out, int out_size)
{
    const int*   data  = (const int*)  d_in[0];
    const int*   tb    = (const int*)  d_in[1];
    const int*   fb    = (const int*)  d_in[2];
    const int*   exi   = (const int*)  d_in[3];
    const int*   steps = (const int*)  d_in[4];
    const float* embed = (const float*)d_in[5];
    const float* Wi    = (const float*)d_in[6];
    const float* Wh    = (const float*)d_in[7];
    const float* bl    = (const float*)d_in[8];
    const float* Wb    = (const float*)d_in[9];
    const float* bb    = (const float*)d_in[10];
    const float* Wo    = (const float*)d_in[11];
    const float* bo    = (const float*)d_in[12];
    float* out = (float*)d_out;

    unsigned *bctr, *bgen;
    cudaGetSymbolAddress((void**)&bctr, g_bctr);
    cudaGetSymbolAddress((void**)&bgen, g_bgen);

    cudaFuncSetAttribute(persist, cudaFuncAttributeMaxDynamicSharedMemorySize, SM_NEED);
    cudaFuncSetAttribute(xwgemm,  cudaFuncAttributeMaxDynamicSharedMemorySize, TSMEM_XW);

    cudaMemsetAsync(bctr, 0, sizeof(unsigned)*NB, 0);
    cudaMemsetAsync(bgen, 0, sizeof(unsigned)*NB, 0);
    gather_kernel<<<(CELLS*NT*HD + 255)/256, 256>>>(data, embed);
    buildwt_kernel<<<(512*256 + 255)/256, 256>>>(Wi, Wh);
    csr_kernel<<<NB, NN>>>(tb, fb);

    xwgemm<<<dim3(CELLS*NT/128, 4), 256, TSMEM_XW>>>();

    persist<<<NCTA, 512, SM_NEED>>>(exi, steps, bl, Wb, bb);

    final_kernel<<<NB, 256>>>(exi, Wo, bo, out);
}

// round 9
// speedup vs baseline: 5.8583x; 1.2006x over previous
#include <cuda_runtime.h>
#include <cuda_fp16.h>
#include <cstdint>
#include <cstddef>

#define NB     16
#define NN     256
#define NT     4
#define HD     128
#define NL     2
#define CELLS  (NB*NN)
#define LOFF   (CELLS*HD)
#define MAXST  15
#define OUTV   1000
#define NCTA   128
#define ZSTR   132

typedef __half f16;

// ---------------- device scratch ----------------
__device__ float g_c_st [NL*CELLS*HD];
__device__ float g_h_st [NL*CELLS*HD];
__device__ float g_pubC [2][NL*CELLS*HD];
__device__ float g_pubH [2][NL*CELLS*HD];
__device__ f16   g_embf_h[CELLS*NT*HD];
__device__ f16   g_embf_l[CELLS*NT*HD];
__device__ float g_xw   [CELLS*NT*512];
__device__ f16   g_w0xf [512*128];     // Wi(l0)^T, xw permutation, fp16
__device__ f16   g_w0t  [512*128];     // Wh0^T, interleaved permutation, fp16
__device__ f16   g_w1t  [512*256];     // [Wi1;Wh1]^T, interleaved permutation, fp16
__device__ float g_wtb[2][CELLS], g_wfb[2][CELLS];
__device__ int   g_csr_off[NB*NN];
__device__ int   g_csr_ent[NB*NN*2];
__device__ unsigned g_bctr[NB];
__device__ unsigned g_bgen[NB];

__device__ __forceinline__ float tanhap(float x){
    float r; asm("tanh.approx.f32 %0, %1;" : "=f"(r) : "f"(x)); return r;
}
__device__ __forceinline__ float sigf(float x){ return fmaf(tanhap(0.5f*x), 0.5f, 0.5f); }

__device__ __forceinline__ uint32_t smem_u32(const void* p){
    uint32_t a; asm("{ .reg .u64 t; cvta.to.shared.u64 t, %1; cvt.u32.u64 %0, t; }":"=r"(a):"l"(p)); return a;
}
#define CPA16(d,s) asm volatile("cp.async.cg.shared.global [%0], [%1], 16;"::"r"(d),"l"((unsigned long long)__cvta_generic_to_global((const void*)(s))):"memory")
#define CP_COMMIT() asm volatile("cp.async.commit_group;":::"memory")

__device__ __forceinline__ void ldmx4(uint32_t* r, uint32_t a){
    asm volatile("ldmatrix.sync.aligned.m8n8.x4.shared.b16 {%0,%1,%2,%3}, [%4];"
        : "=r"(r[0]),"=r"(r[1]),"=r"(r[2]),"=r"(r[3]) : "r"(a));
}
__device__ __forceinline__ void ldmx2(uint32_t* r, uint32_t a){
    asm volatile("ldmatrix.sync.aligned.m8n8.x2.shared.b16 {%0,%1}, [%2];"
        : "=r"(r[0]),"=r"(r[1]) : "r"(a));
}
__device__ __forceinline__ void mmaf16(float* d, const uint32_t* a, const uint32_t* b){
    asm volatile("mma.sync.aligned.m16n8k16.row.col.f32.f16.f16.f32 "
        "{%0,%1,%2,%3}, {%4,%5,%6,%7}, {%8,%9}, {%0,%1,%2,%3};"
        : "+f"(d[0]),"+f"(d[1]),"+f"(d[2]),"+f"(d[3])
        : "r"(a[0]),"r"(a[1]),"r"(a[2]),"r"(a[3]),"r"(b[0]),"r"(b[1]));
}

__device__ __forceinline__ void batchsync(int b, unsigned &cnt){
    __syncthreads();
    if (threadIdx.x == 0){
        __threadfence();
        unsigned t = ++cnt;
        if (atomicAdd(&g_bctr[b], 1u) == 7u){
            atomicExch(&g_bctr[b], 0u);
            __threadfence();
            *(volatile unsigned*)&g_bgen[b] = t;
        } else {
            while (*(volatile unsigned*)&g_bgen[b] < t) __nanosleep(32);
        }
        __threadfence();
    }
    __syncthreads();
}

// smem layout (bytes, from 1KB-aligned base)
#define SW_OFF   0u          // W double buffer: 2 x 65536
#define H0H_OFF  131072u
#define H1H_OFF  139264u
#define C0_OFF   147456u
#define C1_OFF   163840u
#define SNAP_OFF 180224u
#define SWT_OFF  182272u
#define SWF_OFF  183296u
#define IP_OFF   184320u
#define WBS_OFF  184448u
#define SM_NEED  (188544u + 1024u)

__device__ __forceinline__ float hrd1(const char* hh, int row, int d){
    uint32_t off = (uint32_t)(row*256) + ((uint32_t)((d>>3) ^ (row&7))<<4) + (uint32_t)((d&7)*2);
    return __half2float(*(const f16*)(hh+off));
}
__device__ __forceinline__ void hwr1(char* hh, int row, int d, float v){
    uint32_t off = (uint32_t)(row*256) + ((uint32_t)((d>>3) ^ (row&7))<<4) + (uint32_t)((d&7)*2);
    *(f16*)(hh+off) = __float2half(v);
}

// ==================== persistent kernel ====================
__global__ __launch_bounds__(512,1) void persist(
    const int* __restrict__ exi, const int* __restrict__ steps,
    const float* __restrict__ bl, const float* __restrict__ Wb,
    const float* __restrict__ bb)
{
    extern __shared__ char dsm[];
    const uint32_t S0 = smem_u32(dsm);
    const uint32_t S  = (S0 + 1023u) & ~1023u;
    char* base = dsm + (S - S0);
    char* h0h = base + H0H_OFF;
    char* h1h = base + H1H_OFF;
    float* c0 = (float*)(base + C0_OFF);
    float* c1 = (float*)(base + C1_OFF);
    float* snC0 = (float*)(base + SNAP_OFF);
    float* snC1 = snC0 + 128; float* snH0 = snC0 + 256; float* snH1 = snC0 + 384;
    float* swt = (float*)(base + SWT_OFF);
    float* swf = (float*)(base + SWF_OFF);
    float* ips = (float*)(base + IP_OFF);
    float* wbs = (float*)(base + WBS_OFF);

    const int tid = threadIdx.x, lane = tid & 31, wid = tid >> 5;
    const int bid = blockIdx.x;
    const int b = bid >> 3, cell0 = bid * 32, lb = (bid & 7) * 32;
    const int mw = wid & 1, nw = wid >> 1;
    const int qr = lane >> 2, qc = (lane & 3) * 2;

    // W slab prefetch (64KB: 512 rows x 64 k f16, swizzled)
    int wpar = 0;
    auto pref = [&](const f16* src, int KK, int buf){
        uint32_t dst = S + SW_OFF + (uint32_t)buf*65536u;
        #pragma unroll
        for (int i = 0; i < 8; ++i){
            int idx = tid + i*512;
            int row = idx >> 3, c16 = idx & 7;
            CPA16(dst + (uint32_t)(row*128) + ((uint32_t)(c16 ^ (row&7))<<4),
                  src + (size_t)row*KK + c16*8);
        }
        CP_COMMIT();
    };

    // kick off the continuous W pipeline: first slab of l0 W into buffer 0
    pref(g_w0t, 128, 0);

    // init state
    for (int i = tid; i < 2048; i += 512){
        ((uint32_t*)h0h)[i] = 0; ((uint32_t*)h1h)[i] = 0;
    }
    for (int i = tid; i < 4096; i += 512){ c0[i] = 0.f; c1[i] = 0.f; }
    if (tid < 32) ips[tid] = (cell0 + tid == b*256) ? 1.0f : 0.0f;
    for (int i = tid; i < 1024; i += 512) wbs[i] = __ldg(Wb + i);
    __syncthreads();

    const int el = __ldg(exi + b);
    const bool owned = (el >> 5) == (bid & 7);
    const int eloc = el & 31;
    const int nsteps = __ldg(steps + b);
    const float bb0 = __ldg(bb), bb1 = __ldg(bb + 1);

    // fused GEMM (M=32,N=512) + LSTM epilogue; continuous W pipeline
    auto gemm = [&](int nslab, const f16* wsrc, int KK,
                    const f16* nextw, int nextKK,
                    const char* aHi0, const char* aHi1,
                    const float* xwp, const float* bias,
                    float* cbuf, char* hOh)
    {
        float acc[8][4];
        #pragma unroll
        for (int n8=0;n8<8;++n8){ acc[n8][0]=0.f; acc[n8][1]=0.f; acc[n8][2]=0.f; acc[n8][3]=0.f; }

        for (int s = 0; s < nslab; ++s){
            asm volatile("cp.async.wait_group 0;":::"memory");
            __syncthreads();
            if (s + 1 < nslab) pref(wsrc + (s+1)*64, KK, wpar^1);
            else               pref(nextw, nextKK, wpar^1);   // next gemm's slab 0
            uint32_t wb = S + SW_OFF + (uint32_t)wpar*65536u;
            #pragma unroll
            for (int kk = 0; kk < 4; ++kk){
                int kglob = s*64 + kk*16;
                const char* ah; int kr;
                if (kglob < 128){ ah = aHi0; kr = kglob; }
                else            { ah = aHi1; kr = kglob - 128; }
                int row = mw*16 + (lane & 15);
                uint32_t u = (uint32_t)(((kr >> 3) + (lane >> 4)) ^ (row & 7));
                uint32_t Ah[4];
                ldmx4(Ah, smem_u32(ah) + (uint32_t)(row*256) + (u << 4));
                uint32_t B[4][4];
                #pragma unroll
                for (int p = 0; p < 4; ++p){
                    int r = nw*64 + p*16 + ((lane >> 4) << 3) + (lane & 7);
                    uint32_t kh = (uint32_t)(kk*2 + ((lane >> 3) & 1));
                    ldmx4(B[p], wb + (uint32_t)(r*128) + ((kh ^ (uint32_t)(r & 7)) << 4));
                }
                #pragma unroll
                for (int p = 0; p < 4; ++p){
                    mmaf16(acc[2*p],   Ah, &B[p][0]);
                    mmaf16(acc[2*p+1], Ah, &B[p][2]);
                }
            }
            wpar ^= 1;
        }
        __syncthreads();   // all MMA reads of h done before epilogue writes

        // epilogue: register gate math (gate-interleaved W permutation)
        #pragma unroll
        for (int rh = 0; rh < 2; ++rh){
            int row = mw*16 + qr + rh*8;
            int cell = cell0 + row;
            const float* xr = xwp ? xwp + (size_t)cell*2048 : nullptr;
            #pragma unroll
            for (int dd = 0; dd < 4; ++dd){
                int dlow = qc + (dd & 1) + (dd >> 1)*8;
                int hb = dd >> 1;
                int e = (dd & 1) + rh*2;
                int d = nw*16 + dlow;
                float vi = acc[hb][e]     + __ldg(bias + d);
                float vf = acc[2+hb][e]   + __ldg(bias + 128 + d);
                float vg = acc[4+hb][e]   + __ldg(bias + 256 + d);
                float vo = acc[6+hb][e]   + __ldg(bias + 384 + d);
                if (xr){
                    int pb = (d >> 5)*128 + (d & 31);
                    vi += __ldg(xr + pb);       vf += __ldg(xr + pb + 32);
                    vg += __ldg(xr + pb + 64);  vo += __ldg(xr + pb + 96);
                }
                float cold = cbuf[row*128 + d];
                float c2 = sigf(vf)*cold + sigf(vi)*tanhap(vg);
                float hv = sigf(vo)*tanhap(c2);
                cbuf[row*128 + d] = c2;
                hwr1(hOh, row, d, hv);
            }
        }
        __syncthreads();
    };

    unsigned scnt = 0;
    for (int s = 0; s < nsteps; ++s){
        int par = s & 1;

        // snapshot exit cell state (pre-execute)
        if (owned){
            int a = tid >> 7, d = tid & 127;
            if (a == 0) snC0[d] = c0[eloc*128 + d];
            else if (a == 1) snC1[d] = c1[eloc*128 + d];
            else if (a == 2) snH0[d] = hrd1(h0h, eloc, d);
            else             snH1[d] = hrd1(h1h, eloc, d);
        }
        __syncthreads();

        // token loop — fully CTA-local; W pipeline threads across gemms
        for (int t = 0; t < NT; ++t){
            gemm(2, g_w0t, 128, g_w1t, 256, h0h, h0h, g_xw + t*512, bl,       c0, h0h);
            gemm(4, g_w1t, 256, g_w0t, 128, h0h, h1h, nullptr,      bl + 512, c1, h1h);
        }

        // restore exit cell
        if (owned){
            int a = tid >> 7, d = tid & 127;
            if (a == 0) c0[eloc*128 + d] = snC0[d];
            else if (a == 1) c1[eloc*128 + d] = snC1[d];
            else if (a == 2) hwr1(h0h, eloc, d, snH0[d]);
            else             hwr1(h1h, eloc, d, snH1[d]);
        }
        __syncthreads();

        // branch (own 32 cells) + publish
        {
            #pragma unroll
            for (int q = 0; q < 2; ++q){
                int i = wid*2 + q;
                float a0 = 0.f, a1 = 0.f;
                for (int d = lane; d < 128; d += 32){
                    float v0 = c0[i*128 + d];
                    float v1 = hrd1(h0h, i, d);
                    float v2 = c1[i*128 + d];
                    float v3 = hrd1(h1h, i, d);
                    a0 += v0*wbs[2*d]        + v1*wbs[2*(128+d)]
                        + v2*wbs[2*(256+d)]  + v3*wbs[2*(384+d)];
                    a1 += v0*wbs[2*d+1]      + v1*wbs[2*(128+d)+1]
                        + v2*wbs[2*(256+d)+1]+ v3*wbs[2*(384+d)+1];
                }
                #pragma unroll
                for (int o2 = 16; o2; o2 >>= 1){
                    a0 += __shfl_xor_sync(~0u, a0, o2);
                    a1 += __shfl_xor_sync(~0u, a1, o2);
                }
                if (lane == 0){
                    a0 += bb0; a1 += bb1;
                    float m = fmaxf(a0, a1), e0 = __expf(a0-m), e1 = __expf(a1-m);
                    float inv = 1.0f/(e0+e1), w = ips[i];
                    g_wtb[par][cell0 + i] = e0*inv*w;
                    g_wfb[par][cell0 + i] = e1*inv*w;
                }
            }
            for (int v = tid; v < 32*128; v += 512){
                int row = v >> 7, d = v & 127;
                size_t o = (size_t)(cell0 + row)*128 + d;
                g_pubC[par][o]        = c0[row*128 + d];
                g_pubC[par][o + LOFF] = c1[row*128 + d];
                g_pubH[par][o]        = hrd1(h0h, row, d);
                g_pubH[par][o + LOFF] = hrd1(h1h, row, d);
            }
        }
        batchsync(b, scnt);

        // aggregation (CSR)
        for (int i = tid; i < 256; i += 512){
            swt[i] = __ldcg(&g_wtb[par][b*256 + i]);
            swf[i] = __ldcg(&g_wfb[par][b*256 + i]);
        }
        __syncthreads();
        #pragma unroll
        for (int it = 0; it < 8; ++it){
            int i = it*4 + (tid >> 7);
            int d = tid & 127;
            int dstb = lb + i;
            int o0 = g_csr_off[b*NN + dstb];
            int o1 = (dstb == NN-1) ? (b*2*NN + 2*NN) : g_csr_off[b*NN + dstb + 1];
            float a0=0.f, a1=0.f, a2=0.f, a3=0.f, ipn=0.f;
            for (int qq = o0; qq < o1; ++qq){
                int v = g_csr_ent[qq];
                int src = v & 255;
                float w = (v < 0) ? swf[src] : swt[src];
                ipn += w;
                size_t o = (size_t)(b*256 + src)*128 + d;
                a0 += w * __ldcg(&g_pubC[par][o]);
                a1 += w * __ldcg(&g_pubH[par][o]);
                a2 += w * __ldcg(&g_pubC[par][o + LOFF]);
                a3 += w * __ldcg(&g_pubH[par][o + LOFF]);
            }
            float inv = 1.0f/(ipn + 1e-7f);
            c0[i*128 + d] = a0*inv;
            c1[i*128 + d] = a2*inv;
            hwr1(h0h, i, d, a1*inv);
            hwr1(h1h, i, d, a3*inv);
            if (d == 0) ips[i] = ipn;
        }
        __syncthreads();
    }

    asm volatile("cp.async.wait_group 0;":::"memory");

    // publish final state
    for (int v = tid; v < 32*128; v += 512){
        int row = v >> 7, d = v & 127;
        size_t o = (size_t)(cell0 + row)*128 + d;
        g_c_st[o]        = c0[row*128 + d];
        g_c_st[o + LOFF] = c1[row*128 + d];
        g_h_st[o]        = hrd1(h0h, row, d);
        g_h_st[o + LOFF] = hrd1(h1h, row, d);
    }
}

// ==================== xw precompute (fp16 2-pass: A hi/lo, W 1-term) ====================
__global__ void __launch_bounds__(256,1) xwgemm()
{
    extern __shared__ char smem[];
    const uint32_t BUF0 = (smem_u32(smem) + 127u) & ~127u;
    float* Z = (float*)(smem + (BUF0 - smem_u32(smem)));
    const int tid = threadIdx.x, lane = tid & 31, wid = tid >> 5;
    const int mw = wid & 3, nw = wid >> 2;
    const int rowbase = blockIdx.x * 128, nt = blockIdx.y;

    auto load_chunk = [&](int c){
        const uint32_t b = BUF0 + (uint32_t)(c & 1) * 49152u;
        const int kbase = c * 64;
        #pragma unroll
        for (int i = 0; i < 4; ++i){
            int u = tid + i * 256;
            int row = u >> 3, col16 = u & 7;
            uint32_t sw = (uint32_t)(row * 128 + ((col16 ^ (row & 7)) * 16));
            int kg = kbase + col16 * 8;
            size_t o = (size_t)(rowbase + row) * 128 + kg;
            CPA16(b + sw,         g_embf_h + o);
            CPA16(b + 16384 + sw, g_embf_l + o);
            size_t wo = (size_t)(nt * 128 + row) * 128 + kg;
            CPA16(b + 32768 + sw, g_w0xf + wo);
        }
        CP_COMMIT();
    };

    float acc[2][8][4];
    #pragma unroll
    for (int mt=0;mt<2;++mt)
        #pragma unroll
        for (int n8=0;n8<8;++n8)
            #pragma unroll
            for (int e=0;e<4;++e) acc[mt][n8][e]=0.f;

    const int arow = mw * 32 + (lane & 15);
    const uint32_t arbase = (uint32_t)(arow * 128);
    const uint32_t axr = (uint32_t)((arow & 7) << 4);
    const uint32_t acolh = (uint32_t)((lane >> 4) * 16);
    const int brow = nw * 64 + (lane & 7);
    const uint32_t bcolh = (uint32_t)(((lane >> 3) & 1) * 16);

    load_chunk(0);
    #pragma unroll
    for (int c = 0; c < 2; ++c){
        if (c + 1 < 2) load_chunk(c + 1);
        if (c + 1 < 2) asm volatile("cp.async.wait_group 1;":::"memory");
        else           asm volatile("cp.async.wait_group 0;":::"memory");
        __syncthreads();
        const uint32_t b = BUF0 + (uint32_t)(c & 1) * 49152u;
        #pragma unroll
        for (int kk = 0; kk < 4; ++kk){
            uint32_t ah[2][4], al[2][4];
            #pragma unroll
            for (int mt = 0; mt < 2; ++mt){
                uint32_t off = (uint32_t)(mt * 16 * 128) + arbase + (((uint32_t)(kk * 32) + acolh) ^ axr);
                ldmx4(ah[mt], b + off);
                ldmx4(al[mt], b + 16384 + off);
            }
            uint32_t bh[8][2];
            #pragma unroll
            for (int n8 = 0; n8 < 8; ++n8){
                int r = brow + n8 * 8;
                uint32_t off = (uint32_t)(r * 128) + (((uint32_t)(kk * 32) + bcolh) ^ ((uint32_t)((r & 7) << 4)));
                ldmx2(bh[n8], b + 32768 + off);
            }
            #pragma unroll
            for (int mt = 0; mt < 2; ++mt)
                #pragma unroll
                for (int n8 = 0; n8 < 8; ++n8) mmaf16(acc[mt][n8], ah[mt], bh[n8]);
            #pragma unroll
            for (int mt = 0; mt < 2; ++mt)
                #pragma unroll
                for (int n8 = 0; n8 < 8; ++n8) mmaf16(acc[mt][n8], al[mt], bh[n8]);
        }
        __syncthreads();
    }
    {
        const int qr = lane >> 2, qc = (lane & 3) * 2;
        #pragma unroll
        for (int mt = 0; mt < 2; ++mt){
            int r0 = mw * 32 + mt * 16 + qr;
            #pragma unroll
            for (int n8 = 0; n8 < 8; ++n8){
                int c0i = nw * 64 + n8 * 8 + qc;
                Z[r0 * ZSTR + c0i]           = acc[mt][n8][0];
                Z[r0 * ZSTR + c0i + 1]       = acc[mt][n8][1];
                Z[(r0 + 8) * ZSTR + c0i]     = acc[mt][n8][2];
                Z[(r0 + 8) * ZSTR + c0i + 1] = acc[mt][n8][3];
            }
        }
    }
    __syncthreads();
    const int row = tid >> 1;
    const int cell = rowbase + row;
    const int cb = (tid & 1) * 64;
    float* zp = g_xw + (size_t)cell * 512 + nt * 128 + cb;
    #pragma unroll
    for (int q = 0; q < 16; ++q)
        *(float4*)(zp + q * 4) = *(float4*)&Z[row * ZSTR + cb + q * 4];
}

// ==================== setup / final kernels ====================
__global__ void gather_kernel(const int* __restrict__ data, const float* __restrict__ embed)
{
    int i = blockIdx.x*blockDim.x + threadIdx.x;
    if (i >= CELLS*NT*HD) return;
    float v = embed[(size_t)data[i>>7]*HD + (i&127)];
    f16 h = __float2half(v);
    g_embf_h[i] = h; g_embf_l[i] = __float2half(v - __half2float(h));
}

__global__ void buildwt_kernel(const float* __restrict__ Wi, const float* __restrict__ Wh)
{
    int i = blockIdx.x*blockDim.x + threadIdx.x;
    // fp16 Wi(l0), OLD (nt-block) permutation — for xwgemm
    if (i < 512*128){
        int p = i>>7, k = i&127;
        int ntc = p>>7, c = p&127, g = c>>5, j = c&31;
        int orig = g*128 + ntc*32 + j;
        g_w0xf[i] = __float2half(Wi[(size_t)k*512+orig]);
    }
    // fp16 Wh0, interleaved permutation: p = (d>>4)*64 + g*16 + (d&15)
    if (i < 512*128){
        int p = i>>7, k = i&127;
        int d = (p>>6)*16 + (p&15), g = (p>>4)&3;
        int orig = g*128 + d;
        g_w0t[i] = __float2half(Wh[(size_t)k*512 + orig]);
    }
    // fp16 [Wi1;Wh1], interleaved permutation
    if (i < 512*256){
        int p = i>>8, k = i&255;
        int d = (p>>6)*16 + (p&15), g = (p>>4)&3;
        int orig = g*128 + d;
        float v = (k<128) ? Wi[(size_t)(128+k)*512+orig] : Wh[(size_t)(128+(k-128))*512+orig];
        g_w1t[i] = __float2half(v);
    }
}

__global__ void csr_kernel(const int* __restrict__ tb, const int* __restrict__ fb)
{
    int b = blockIdx.x, dst = threadIdx.x;
    __shared__ int stb[NN], sfb[NN], ps[NN];
    stb[dst] = tb[b*NN+dst]; sfb[dst] = fb[b*NN+dst];
    __syncthreads();
    int cnt = 0;
    for (int ss = 0; ss < NN; ++ss) cnt += (stb[ss]==dst) + (sfb[ss]==dst);
    ps[dst] = cnt; __syncthreads();
    for (int o2 = 1; o2 < NN; o2 <<= 1){
        int v = (dst >= o2) ? ps[dst-o2] : 0;
        __syncthreads();
        ps[dst] += v;
        __syncthreads();
    }
    int start = ps[dst] - cnt;
    g_csr_off[b*NN + dst] = b*2*NN + start;
    int p = b*2*NN + start;
    for (int ss = 0; ss < NN; ++ss) if (stb[ss]==dst) g_csr_ent[p++] = ss;
    for (int ss = 0; ss < NN; ++ss) if (sfb[ss]==dst) g_csr_ent[p++] = ss | (int)0x80000000;
}

__global__ void final_kernel(const int* __restrict__ exi,
                             const float* __restrict__ Wo, const float* __restrict__ bo,
                             float* __restrict__ out)
{
    int b = blockIdx.x;
    __shared__ float f[4*HD];
    int cell = b*NN + exi[b];
    for (int i = threadIdx.x; i < 4*HD; i += blockDim.x){
        int l = i>>8, ch = (i>>7)&1, d = i&127;
        const float* src = ch ? g_h_st : g_c_st;
        f[i] = src[(size_t)l*LOFF + (size_t)cell*HD + d];
    }
    __syncthreads();
    for (int o = threadIdx.x; o < OUTV; o += blockDim.x){
        float acc = bo[o];
        #pragma unroll 8
        for (int k = 0; k < 4*HD; ++k) acc += f[k]*Wo[(size_t)k*OUTV + o];
        out[(size_t)b*OUTV + o] = acc;
    }
}

// ==================== host ====================
#define TSMEM_XW (98304 + 128)

extern "C" void kernel_launch(void* const* d_in, const int* in_sizes, int n_in,
                              void* d_out, int out_size)
{
    const int*   data  = (const int*)  d_in[0];
    const int*   tb    = (const int*)  d_in[1];
    const int*   fb    = (const int*)  d_in[2];
    const int*   exi   = (const int*)  d_in[3];
    const int*   steps = (const int*)  d_in[4];
    const float* embed = (const float*)d_in[5];
    const float* Wi    = (const float*)d_in[6];
    const float* Wh    = (const float*)d_in[7];
    const float* bl    = (const float*)d_in[8];
    const float* Wb    = (const float*)d_in[9];
    const float* bb    = (const float*)d_in[10];
    const float* Wo    = (const float*)d_in[11];
    const float* bo    = (const float*)d_in[12];
    float* out = (float*)d_out;

    unsigned *bctr, *bgen;
    cudaGetSymbolAddress((void**)&bctr, g_bctr);
    cudaGetSymbolAddress((void**)&bgen, g_bgen);

    cudaFuncSetAttribute(persist, cudaFuncAttributeMaxDynamicSharedMemorySize, SM_NEED);
    cudaFuncSetAttribute(xwgemm,  cudaFuncAttributeMaxDynamicSharedMemorySize, TSMEM_XW);

    cudaMemsetAsync(bctr, 0, sizeof(unsigned)*NB, 0);
    cudaMemsetAsync(bgen, 0, sizeof(unsigned)*NB, 0);
    gather_kernel<<<(CELLS*NT*HD + 255)/256, 256>>>(data, embed);
    buildwt_kernel<<<(512*256 + 255)/256, 256>>>(Wi, Wh);
    csr_kernel<<<NB, NN>>>(tb, fb);

    xwgemm<<<dim3(CELLS*NT/128, 4), 256, TSMEM_XW>>>();

    persist<<<NCTA, 512, SM_NEED>>>(exi, steps, bl, Wb, bb);

    final_kernel<<<NB, 256>>>(exi, Wo, bo, out);
}

// round 10
// speedup vs baseline: 6.5187x; 1.1127x over previous
#include <cuda_runtime.h>
#include <cuda_fp16.h>
#include <cstdint>
#include <cstddef>

#define NB     16
#define NN     256
#define NT     4
#define HD     128
#define NL     2
#define CELLS  (NB*NN)
#define LOFF   (CELLS*HD)
#define MAXST  15
#define OUTV   1000
#define NCTA   128
#define ZSTR   132

typedef __half f16;

// ---------------- device scratch ----------------
__device__ float g_c_st [NL*CELLS*HD];
__device__ float g_h_st [NL*CELLS*HD];
__device__ float g_pubC [2][NL*CELLS*HD];
__device__ float g_pubH [2][NL*CELLS*HD];
__device__ f16   g_embf_h[CELLS*NT*HD];
__device__ f16   g_embf_l[CELLS*NT*HD];
__device__ float g_xw   [CELLS*NT*512];    // layout: [cell*4+t][d*4+gate]
__device__ f16   g_w0xf [512*128];         // Wi(l0)^T, block permutation, fp16
__device__ f16   g_w0t  [512*128];         // Wh0^T, interleaved permutation, fp16
__device__ f16   g_w1t  [512*256];         // [Wi1;Wh1]^T, interleaved permutation, fp16
__device__ float g_wtb[2][CELLS], g_wfb[2][CELLS];
__device__ int   g_csr_off[NB*NN];
__device__ int   g_csr_ent[NB*NN*2];
__device__ unsigned g_bctr[NB];
__device__ unsigned g_bgen[NB];

__device__ __forceinline__ float tanhap(float x){
    float r; asm("tanh.approx.f32 %0, %1;" : "=f"(r) : "f"(x)); return r;
}
__device__ __forceinline__ float sigf(float x){ return fmaf(tanhap(0.5f*x), 0.5f, 0.5f); }

__device__ __forceinline__ uint32_t smem_u32(const void* p){
    uint32_t a; asm("{ .reg .u64 t; cvta.to.shared.u64 t, %1; cvt.u32.u64 %0, t; }":"=r"(a):"l"(p)); return a;
}
#define CPA16(d,s) asm volatile("cp.async.cg.shared.global [%0], [%1], 16;"::"r"(d),"l"((unsigned long long)__cvta_generic_to_global((const void*)(s))):"memory")
#define CP_COMMIT() asm volatile("cp.async.commit_group;":::"memory")

__device__ __forceinline__ void ldmx4(uint32_t* r, uint32_t a){
    asm volatile("ldmatrix.sync.aligned.m8n8.x4.shared.b16 {%0,%1,%2,%3}, [%4];"
        : "=r"(r[0]),"=r"(r[1]),"=r"(r[2]),"=r"(r[3]) : "r"(a));
}
__device__ __forceinline__ void ldmx2(uint32_t* r, uint32_t a){
    asm volatile("ldmatrix.sync.aligned.m8n8.x2.shared.b16 {%0,%1}, [%2];"
        : "=r"(r[0]),"=r"(r[1]) : "r"(a));
}
__device__ __forceinline__ void mmaf16(float* d, const uint32_t* a, const uint32_t* b){
    asm volatile("mma.sync.aligned.m16n8k16.row.col.f32.f16.f16.f32 "
        "{%0,%1,%2,%3}, {%4,%5,%6,%7}, {%8,%9}, {%0,%1,%2,%3};"
        : "+f"(d[0]),"+f"(d[1]),"+f"(d[2]),"+f"(d[3])
        : "r"(a[0]),"r"(a[1]),"r"(a[2]),"r"(a[3]),"r"(b[0]),"r"(b[1]));
}

__device__ __forceinline__ void batchsync(int b, unsigned &cnt){
    __syncthreads();
    if (threadIdx.x == 0){
        __threadfence();
        unsigned t = ++cnt;
        if (atomicAdd(&g_bctr[b], 1u) == 7u){
            atomicExch(&g_bctr[b], 0u);
            __threadfence();
            *(volatile unsigned*)&g_bgen[b] = t;
        } else {
            while (*(volatile unsigned*)&g_bgen[b] < t) __nanosleep(32);
        }
        __threadfence();
    }
    __syncthreads();
}

// smem layout (bytes, from 1KB-aligned base)
#define SW_OFF   0u          // W double buffer: 2 x 65536
#define H0H_OFF  131072u
#define H1H_OFF  139264u
#define C0_OFF   147456u
#define C1_OFF   163840u
#define SNAP_OFF 180224u
#define SWT_OFF  182272u
#define SWF_OFF  183296u
#define IP_OFF   184320u
#define WBS_OFF  184448u
#define BLS_OFF  188544u
#define SM_NEED  (192640u + 1024u)

__device__ __forceinline__ float hrd1(const char* hh, int row, int d){
    uint32_t off = (uint32_t)(row*256) + ((uint32_t)((d>>3) ^ (row&7))<<4) + (uint32_t)((d&7)*2);
    return __half2float(*(const f16*)(hh+off));
}
__device__ __forceinline__ void hwr1(char* hh, int row, int d, float v){
    uint32_t off = (uint32_t)(row*256) + ((uint32_t)((d>>3) ^ (row&7))<<4) + (uint32_t)((d&7)*2);
    *(f16*)(hh+off) = __float2half(v);
}

// ==================== persistent kernel ====================
__global__ __launch_bounds__(512,1) void persist(
    const int* __restrict__ exi, const int* __restrict__ steps,
    const float* __restrict__ bl, const float* __restrict__ Wb,
    const float* __restrict__ bb)
{
    extern __shared__ char dsm[];
    const uint32_t S0 = smem_u32(dsm);
    const uint32_t S  = (S0 + 1023u) & ~1023u;
    char* base = dsm + (S - S0);
    char* h0h = base + H0H_OFF;
    char* h1h = base + H1H_OFF;
    float* c0 = (float*)(base + C0_OFF);
    float* c1 = (float*)(base + C1_OFF);
    float* snC0 = (float*)(base + SNAP_OFF);
    float* snC1 = snC0 + 128; float* snH0 = snC0 + 256; float* snH1 = snC0 + 384;
    float* swt = (float*)(base + SWT_OFF);
    float* swf = (float*)(base + SWF_OFF);
    float* ips = (float*)(base + IP_OFF);
    float* wbs = (float*)(base + WBS_OFF);
    float* bls = (float*)(base + BLS_OFF);

    const int tid = threadIdx.x, lane = tid & 31, wid = tid >> 5;
    const int bid = blockIdx.x;
    const int b = bid >> 3, cell0 = bid * 32, lb = (bid & 7) * 32;
    const int mw = wid & 1, nw = wid >> 1;
    const int qr = lane >> 2, qc = (lane & 3) * 2;

    int wpar = 0;
    auto pref = [&](const f16* src, int KK, int buf){
        uint32_t dst = S + SW_OFF + (uint32_t)buf*65536u;
        #pragma unroll
        for (int i = 0; i < 8; ++i){
            int idx = tid + i*512;
            int row = idx >> 3, c16 = idx & 7;
            CPA16(dst + (uint32_t)(row*128) + ((uint32_t)(c16 ^ (row&7))<<4),
                  src + (size_t)row*KK + c16*8);
        }
        CP_COMMIT();
    };

    pref(g_w0t, 128, 0);   // kick off continuous W pipeline

    // init state
    for (int i = tid; i < 2048; i += 512){
        ((uint32_t*)h0h)[i] = 0; ((uint32_t*)h1h)[i] = 0;
    }
    for (int i = tid; i < 4096; i += 512){ c0[i] = 0.f; c1[i] = 0.f; }
    if (tid < 32) ips[tid] = (cell0 + tid == b*256) ? 1.0f : 0.0f;
    for (int i = tid; i < 1024; i += 512){ wbs[i] = __ldg(Wb + i); bls[i] = __ldg(bl + i); }
    __syncthreads();

    const int el = __ldg(exi + b);
    const bool owned = (el >> 5) == (bid & 7);
    const int eloc = el & 31;
    const int nsteps = __ldg(steps + b);
    const float bb0 = __ldg(bb), bb1 = __ldg(bb + 1);

    // fused GEMM (M=32,N=512) + LSTM epilogue; continuous W pipeline
    auto gemm = [&](int nslab, const f16* wsrc, int KK,
                    const f16* nextw, int nextKK,
                    const char* aHi0, const char* aHi1,
                    const float* xwp, const float* bias,
                    float* cbuf, char* hOh)
    {
        float acc[8][4];
        #pragma unroll
        for (int n8=0;n8<8;++n8){ acc[n8][0]=0.f; acc[n8][1]=0.f; acc[n8][2]=0.f; acc[n8][3]=0.f; }

        for (int s = 0; s < nslab; ++s){
            asm volatile("cp.async.wait_group 0;":::"memory");
            __syncthreads();
            if (s + 1 < nslab) pref(wsrc + (s+1)*64, KK, wpar^1);
            else               pref(nextw, nextKK, wpar^1);
            uint32_t wb = S + SW_OFF + (uint32_t)wpar*65536u;
            #pragma unroll
            for (int kk = 0; kk < 4; ++kk){
                int kglob = s*64 + kk*16;
                const char* ah; int kr;
                if (kglob < 128){ ah = aHi0; kr = kglob; }
                else            { ah = aHi1; kr = kglob - 128; }
                int row = mw*16 + (lane & 15);
                uint32_t u = (uint32_t)(((kr >> 3) + (lane >> 4)) ^ (row & 7));
                uint32_t Ah[4];
                ldmx4(Ah, smem_u32(ah) + (uint32_t)(row*256) + (u << 4));
                uint32_t B[4][4];
                #pragma unroll
                for (int p = 0; p < 4; ++p){
                    int r = nw*64 + p*16 + ((lane >> 4) << 3) + (lane & 7);
                    uint32_t kh = (uint32_t)(kk*2 + ((lane >> 3) & 1));
                    ldmx4(B[p], wb + (uint32_t)(r*128) + ((kh ^ (uint32_t)(r & 7)) << 4));
                }
                #pragma unroll
                for (int p = 0; p < 4; ++p){
                    mmaf16(acc[2*p],   Ah, &B[p][0]);
                    mmaf16(acc[2*p+1], Ah, &B[p][2]);
                }
            }
            wpar ^= 1;
        }
        __syncthreads();

        // epilogue: register gate math; xw loaded as one float4 per output
        #pragma unroll
        for (int rh = 0; rh < 2; ++rh){
            int row = mw*16 + qr + rh*8;
            int cell = cell0 + row;
            const float4* xr4 = xwp ? (const float4*)(xwp + (size_t)cell*2048) : nullptr;
            #pragma unroll
            for (int dd = 0; dd < 4; ++dd){
                int dlow = qc + (dd & 1) + (dd >> 1)*8;
                int hb = dd >> 1;
                int e = (dd & 1) + rh*2;
                int d = nw*16 + dlow;
                float vi = acc[hb][e]     + bias[d];
                float vf = acc[2+hb][e]   + bias[128 + d];
                float vg = acc[4+hb][e]   + bias[256 + d];
                float vo = acc[6+hb][e]   + bias[384 + d];
                if (xr4){
                    float4 xv = __ldg(xr4 + d);
                    vi += xv.x; vf += xv.y; vg += xv.z; vo += xv.w;
                }
                float cold = cbuf[row*128 + d];
                float c2 = sigf(vf)*cold + sigf(vi)*tanhap(vg);
                float hv = sigf(vo)*tanhap(c2);
                cbuf[row*128 + d] = c2;
                hwr1(hOh, row, d, hv);
            }
        }
        __syncthreads();
    };

    unsigned scnt = 0;
    for (int s = 0; s < nsteps; ++s){
        int par = s & 1;

        if (owned){
            int a = tid >> 7, d = tid & 127;
            if (a == 0) snC0[d] = c0[eloc*128 + d];
            else if (a == 1) snC1[d] = c1[eloc*128 + d];
            else if (a == 2) snH0[d] = hrd1(h0h, eloc, d);
            else             snH1[d] = hrd1(h1h, eloc, d);
        }
        __syncthreads();

        for (int t = 0; t < NT; ++t){
            gemm(2, g_w0t, 128, g_w1t, 256, h0h, h0h, g_xw + t*512, bls,       c0, h0h);
            gemm(4, g_w1t, 256, g_w0t, 128, h0h, h1h, nullptr,      bls + 512, c1, h1h);
        }

        if (owned){
            int a = tid >> 7, d = tid & 127;
            if (a == 0) c0[eloc*128 + d] = snC0[d];
            else if (a == 1) c1[eloc*128 + d] = snC1[d];
            else if (a == 2) hwr1(h0h, eloc, d, snH0[d]);
            else             hwr1(h1h, eloc, d, snH1[d]);
        }
        __syncthreads();

        // branch + publish
        {
            #pragma unroll
            for (int q = 0; q < 2; ++q){
                int i = wid*2 + q;
                float a0 = 0.f, a1 = 0.f;
                for (int d = lane; d < 128; d += 32){
                    float v0 = c0[i*128 + d];
                    float v1 = hrd1(h0h, i, d);
                    float v2 = c1[i*128 + d];
                    float v3 = hrd1(h1h, i, d);
                    a0 += v0*wbs[2*d]        + v1*wbs[2*(128+d)]
                        + v2*wbs[2*(256+d)]  + v3*wbs[2*(384+d)];
                    a1 += v0*wbs[2*d+1]      + v1*wbs[2*(128+d)+1]
                        + v2*wbs[2*(256+d)+1]+ v3*wbs[2*(384+d)+1];
                }
                #pragma unroll
                for (int o2 = 16; o2; o2 >>= 1){
                    a0 += __shfl_xor_sync(~0u, a0, o2);
                    a1 += __shfl_xor_sync(~0u, a1, o2);
                }
                if (lane == 0){
                    a0 += bb0; a1 += bb1;
                    float m = fmaxf(a0, a1), e0 = __expf(a0-m), e1 = __expf(a1-m);
                    float inv = 1.0f/(e0+e1), w = ips[i];
                    g_wtb[par][cell0 + i] = e0*inv*w;
                    g_wfb[par][cell0 + i] = e1*inv*w;
                }
            }
            for (int v = tid; v < 32*128; v += 512){
                int row = v >> 7, d = v & 127;
                size_t o = (size_t)(cell0 + row)*128 + d;
                g_pubC[par][o]        = c0[row*128 + d];
                g_pubC[par][o + LOFF] = c1[row*128 + d];
                g_pubH[par][o]        = hrd1(h0h, row, d);
                g_pubH[par][o + LOFF] = hrd1(h1h, row, d);
            }
        }
        batchsync(b, scnt);

        // aggregation (CSR)
        for (int i = tid; i < 256; i += 512){
            swt[i] = __ldcg(&g_wtb[par][b*256 + i]);
            swf[i] = __ldcg(&g_wfb[par][b*256 + i]);
        }
        __syncthreads();
        #pragma unroll
        for (int it = 0; it < 8; ++it){
            int i = it*4 + (tid >> 7);
            int d = tid & 127;
            int dstb = lb + i;
            int o0 = g_csr_off[b*NN + dstb];
            int o1 = (dstb == NN-1) ? (b*2*NN + 2*NN) : g_csr_off[b*NN + dstb + 1];
            float a0=0.f, a1=0.f, a2=0.f, a3=0.f, ipn=0.f;
            for (int qq = o0; qq < o1; ++qq){
                int v = g_csr_ent[qq];
                int src = v & 255;
                float w = (v < 0) ? swf[src] : swt[src];
                ipn += w;
                size_t o = (size_t)(b*256 + src)*128 + d;
                a0 += w * __ldcg(&g_pubC[par][o]);
                a1 += w * __ldcg(&g_pubH[par][o]);
                a2 += w * __ldcg(&g_pubC[par][o + LOFF]);
                a3 += w * __ldcg(&g_pubH[par][o + LOFF]);
            }
            float inv = 1.0f/(ipn + 1e-7f);
            c0[i*128 + d] = a0*inv;
            c1[i*128 + d] = a2*inv;
            hwr1(h0h, i, d, a1*inv);
            hwr1(h1h, i, d, a3*inv);
            if (d == 0) ips[i] = ipn;
        }
        __syncthreads();
    }

    asm volatile("cp.async.wait_group 0;":::"memory");

    for (int v = tid; v < 32*128; v += 512){
        int row = v >> 7, d = v & 127;
        size_t o = (size_t)(cell0 + row)*128 + d;
        g_c_st[o]        = c0[row*128 + d];
        g_c_st[o + LOFF] = c1[row*128 + d];
        g_h_st[o]        = hrd1(h0h, row, d);
        g_h_st[o + LOFF] = hrd1(h1h, row, d);
    }
}

// ==================== xw precompute (fp16 2-pass A, 1-pass W) ====================
__global__ void __launch_bounds__(256,1) xwgemm()
{
    extern __shared__ char smem[];
    const uint32_t BUF0 = (smem_u32(smem) + 127u) & ~127u;
    float* Z = (float*)(smem + (BUF0 - smem_u32(smem)));
    const int tid = threadIdx.x, lane = tid & 31, wid = tid >> 5;
    const int mw = wid & 3, nw = wid >> 2;
    const int rowbase = blockIdx.x * 128, nt = blockIdx.y;

    auto load_chunk = [&](int c){
        const uint32_t b = BUF0 + (uint32_t)(c & 1) * 49152u;
        const int kbase = c * 64;
        #pragma unroll
        for (int i = 0; i < 4; ++i){
            int u = tid + i * 256;
            int row = u >> 3, col16 = u & 7;
            uint32_t sw = (uint32_t)(row * 128 + ((col16 ^ (row & 7)) * 16));
            int kg = kbase + col16 * 8;
            size_t o = (size_t)(rowbase + row) * 128 + kg;
            CPA16(b + sw,         g_embf_h + o);
            CPA16(b + 16384 + sw, g_embf_l + o);
            size_t wo = (size_t)(nt * 128 + row) * 128 + kg;
            CPA16(b + 32768 + sw, g_w0xf + wo);
        }
        CP_COMMIT();
    };

    float acc[2][8][4];
    #pragma unroll
    for (int mt=0;mt<2;++mt)
        #pragma unroll
        for (int n8=0;n8<8;++n8)
            #pragma unroll
            for (int e=0;e<4;++e) acc[mt][n8][e]=0.f;

    const int arow = mw * 32 + (lane & 15);
    const uint32_t arbase = (uint32_t)(arow * 128);
    const uint32_t axr = (uint32_t)((arow & 7) << 4);
    const uint32_t acolh = (uint32_t)((lane >> 4) * 16);
    const int brow = nw * 64 + (lane & 7);
    const uint32_t bcolh = (uint32_t)(((lane >> 3) & 1) * 16);

    load_chunk(0);
    #pragma unroll
    for (int c = 0; c < 2; ++c){
        if (c + 1 < 2) load_chunk(c + 1);
        if (c + 1 < 2) asm volatile("cp.async.wait_group 1;":::"memory");
        else           asm volatile("cp.async.wait_group 0;":::"memory");
        __syncthreads();
        const uint32_t b = BUF0 + (uint32_t)(c & 1) * 49152u;
        #pragma unroll
        for (int kk = 0; kk < 4; ++kk){
            uint32_t ah[2][4], al[2][4];
            #pragma unroll
            for (int mt = 0; mt < 2; ++mt){
                uint32_t off = (uint32_t)(mt * 16 * 128) + arbase + (((uint32_t)(kk * 32) + acolh) ^ axr);
                ldmx4(ah[mt], b + off);
                ldmx4(al[mt], b + 16384 + off);
            }
            uint32_t bh[8][2];
            #pragma unroll
            for (int n8 = 0; n8 < 8; ++n8){
                int r = brow + n8 * 8;
                uint32_t off = (uint32_t)(r * 128) + (((uint32_t)(kk * 32) + bcolh) ^ ((uint32_t)((r & 7) << 4)));
                ldmx2(bh[n8], b + 32768 + off);
            }
            #pragma unroll
            for (int mt = 0; mt < 2; ++mt)
                #pragma unroll
                for (int n8 = 0; n8 < 8; ++n8) mmaf16(acc[mt][n8], ah[mt], bh[n8]);
            #pragma unroll
            for (int mt = 0; mt < 2; ++mt)
                #pragma unroll
                for (int n8 = 0; n8 < 8; ++n8) mmaf16(acc[mt][n8], al[mt], bh[n8]);
        }
        __syncthreads();
    }
    {
        const int qr = lane >> 2, qc = (lane & 3) * 2;
        #pragma unroll
        for (int mt = 0; mt < 2; ++mt){
            int r0 = mw * 32 + mt * 16 + qr;
            #pragma unroll
            for (int n8 = 0; n8 < 8; ++n8){
                int c0i = nw * 64 + n8 * 8 + qc;
                Z[r0 * ZSTR + c0i]           = acc[mt][n8][0];
                Z[r0 * ZSTR + c0i + 1]       = acc[mt][n8][1];
                Z[(r0 + 8) * ZSTR + c0i]     = acc[mt][n8][2];
                Z[(r0 + 8) * ZSTR + c0i + 1] = acc[mt][n8][3];
            }
        }
    }
    __syncthreads();
    // store to gate-interleaved xw layout: [ct][d*4 + gate]
    const int row = tid >> 1;
    const int ct = rowbase + row;
    const int cb = (tid & 1) * 64;
    #pragma unroll
    for (int q = 0; q < 64; ++q){
        int pg = nt*128 + cb + q;            // permuted col (block permutation)
        int g  = (pg >> 5) & 3;
        int d  = (pg >> 7) * 32 + (pg & 31);
        g_xw[(size_t)ct*512 + d*4 + g] = Z[row * ZSTR + cb + q];
    }
}

// ==================== fused setup kernel ====================
__global__ void setup_kernel(const int* __restrict__ data, const float* __restrict__ embed,
                             const float* __restrict__ Wi, const float* __restrict__ Wh,
                             const int* __restrict__ tb, const int* __restrict__ fb)
{
    const int bx = blockIdx.x, tid = threadIdx.x;
    if (bx < NB){
        // ---- CSR build ----
        int b = bx, dst = tid;
        __shared__ int stb[NN], sfb[NN], ps[NN];
        stb[dst] = tb[b*NN+dst]; sfb[dst] = fb[b*NN+dst];
        __syncthreads();
        int cnt = 0;
        for (int ss = 0; ss < NN; ++ss) cnt += (stb[ss]==dst) + (sfb[ss]==dst);
        ps[dst] = cnt; __syncthreads();
        for (int o2 = 1; o2 < NN; o2 <<= 1){
            int v = (dst >= o2) ? ps[dst-o2] : 0;
            __syncthreads();
            ps[dst] += v;
            __syncthreads();
        }
        int start = ps[dst] - cnt;
        g_csr_off[b*NN + dst] = b*2*NN + start;
        int p = b*2*NN + start;
        for (int ss = 0; ss < NN; ++ss) if (stb[ss]==dst) g_csr_ent[p++] = ss;
        for (int ss = 0; ss < NN; ++ss) if (sfb[ss]==dst) g_csr_ent[p++] = ss | (int)0x80000000;
    } else if (bx < NB + 512){
        // ---- weight conversion ----
        int i = (bx - NB)*256 + tid;
        if (i < 512*128){
            int p = i>>7, k = i&127;
            int ntc = p>>7, c = p&127, g = c>>5, j = c&31;
            int orig = g*128 + ntc*32 + j;
            g_w0xf[i] = __float2half(Wi[(size_t)k*512+orig]);
        }
        if (i < 512*128){
            int p = i>>7, k = i&127;
            int d = (p>>6)*16 + (p&15), g = (p>>4)&3;
            int orig = g*128 + d;
            g_w0t[i] = __float2half(Wh[(size_t)k*512 + orig]);
        }
        if (i < 512*256){
            int p = i>>8, k = i&255;
            int d = (p>>6)*16 + (p&15), g = (p>>4)&3;
            int orig = g*128 + d;
            float v = (k<128) ? Wi[(size_t)(128+k)*512+orig] : Wh[(size_t)(128+(k-128))*512+orig];
            g_w1t[i] = __float2half(v);
        }
    } else {
        // ---- embedding gather ----
        int i = (bx - NB - 512)*256 + tid;
        if (i < CELLS*NT*HD){
            float v = embed[(size_t)data[i>>7]*HD + (i&127)];
            f16 h = __float2half(v);
            g_embf_h[i] = h; g_embf_l[i] = __float2half(v - __half2float(h));
        }
    }
}

__global__ void final_kernel(const int* __restrict__ exi,
                             const float* __restrict__ Wo, const float* __restrict__ bo,
                             float* __restrict__ out)
{
    int b = blockIdx.x;
    __shared__ float f[4*HD];
    int cell = b*NN + exi[b];
    for (int i = threadIdx.x; i < 4*HD; i += blockDim.x){
        int l = i>>8, ch = (i>>7)&1, d = i&127;
        const float* src = ch ? g_h_st : g_c_st;
        f[i] = src[(size_t)l*LOFF + (size_t)cell*HD + d];
    }
    __syncthreads();
    for (int o = threadIdx.x; o < OUTV; o += blockDim.x){
        float acc = bo[o];
        #pragma unroll 8
        for (int k = 0; k < 4*HD; ++k) acc += f[k]*Wo[(size_t)k*OUTV + o];
        out[(size_t)b*OUTV + o] = acc;
    }
}

// ==================== host ====================
#define TSMEM_XW (98304 + 128)

extern "C" void kernel_launch(void* const* d_in, const int* in_sizes, int n_in,
                              void* d_out, int out_size)
{
    const int*   data  = (const int*)  d_in[0];
    const int*   tb    = (const int*)  d_in[1];
    const int*   fb    = (const int*)  d_in[2];
    const int*   exi   = (const int*)  d_in[3];
    const int*   steps = (const int*)  d_in[4];
    const float* embed = (const float*)d_in[5];
    const float* Wi    = (const float*)d_in[6];
    const float* Wh    = (const float*)d_in[7];
    const float* bl    = (const float*)d_in[8];
    const float* Wb    = (const float*)d_in[9];
    const float* bb    = (const float*)d_in[10];
    const float* Wo    = (const float*)d_in[11];
    const float* bo    = (const float*)d_in[12];
    float* out = (float*)d_out;

    unsigned *bctr, *bgen;
    cudaGetSymbolAddress((void**)&bctr, g_bctr);
    cudaGetSymbolAddress((void**)&bgen, g_bgen);

    cudaFuncSetAttribute(persist, cudaFuncAttributeMaxDynamicSharedMemorySize, SM_NEED);
    cudaFuncSetAttribute(xwgemm,  cudaFuncAttributeMaxDynamicSharedMemorySize, TSMEM_XW);

    cudaMemsetAsync(bctr, 0, sizeof(unsigned)*NB, 0);
    cudaMemsetAsync(bgen, 0, sizeof(unsigned)*NB, 0);

    const int gather_blocks = (CELLS*NT*HD + 255)/256;     // 8192
    setup_kernel<<<NB + 512 + gather_blocks, 256>>>(data, embed, Wi, Wh, tb, fb);

    xwgemm<<<dim3(CELLS*NT/128, 4), 256, TSMEM_XW>>>();

    persist<<<NCTA, 512, SM_NEED>>>(exi, steps, bl, Wb, bb);

    final_kernel<<<NB, 256>>>(exi, Wo, bo, out);
}

// round 11
// speedup vs baseline: 6.9392x; 1.0645x over previous
#include <cuda_runtime.h>
#include <cuda_fp16.h>
#include <cstdint>
#include <cstddef>

#define NB     16
#define NN     256
#define NT     4
#define HD     128
#define NL     2
#define CELLS  (NB*NN)
#define LOFF   (CELLS*HD)
#define MAXST  15
#define OUTV   1000
#define NCTA   128
#define ZSTR   132

typedef __half f16;

// ---------------- device scratch ----------------
__device__ float g_c_st [NL*CELLS*HD];
__device__ float g_h_st [NL*CELLS*HD];
__device__ float g_pubC [2][NL*CELLS*HD];
__device__ float g_pubH [2][NL*CELLS*HD];
__device__ f16   g_embf_h[CELLS*NT*HD];
__device__ f16   g_embf_l[CELLS*NT*HD];
__device__ float g_xw   [CELLS*NT*512];    // layout: [cell*4+t][d*4+gate]
__device__ f16   g_w0xf [512*128];         // Wi(l0)^T, block permutation, fp16
__device__ f16   g_w0t  [512*128];         // Wh0^T, interleaved permutation, fp16
__device__ f16   g_w1t  [512*256];         // [Wi1;Wh1]^T, interleaved permutation, fp16
__device__ float g_wtb[2][CELLS], g_wfb[2][CELLS];
__device__ int   g_csr_off[NB*NN];
__device__ int   g_csr_ent[NB*NN*2];
__device__ unsigned g_bctr[NB];
__device__ unsigned g_bgen[NB];

__device__ __forceinline__ float tanhap(float x){
    float r; asm("tanh.approx.f32 %0, %1;" : "=f"(r) : "f"(x)); return r;
}
__device__ __forceinline__ float sigf(float x){ return fmaf(tanhap(0.5f*x), 0.5f, 0.5f); }

__device__ __forceinline__ uint32_t smem_u32(const void* p){
    uint32_t a; asm("{ .reg .u64 t; cvta.to.shared.u64 t, %1; cvt.u32.u64 %0, t; }":"=r"(a):"l"(p)); return a;
}
#define CPA16(d,s) asm volatile("cp.async.cg.shared.global [%0], [%1], 16;"::"r"(d),"l"((unsigned long long)__cvta_generic_to_global((const void*)(s))):"memory")
#define CP_COMMIT() asm volatile("cp.async.commit_group;":::"memory")

__device__ __forceinline__ void ldmx4(uint32_t* r, uint32_t a){
    asm volatile("ldmatrix.sync.aligned.m8n8.x4.shared.b16 {%0,%1,%2,%3}, [%4];"
        : "=r"(r[0]),"=r"(r[1]),"=r"(r[2]),"=r"(r[3]) : "r"(a));
}
__device__ __forceinline__ void ldmx2(uint32_t* r, uint32_t a){
    asm volatile("ldmatrix.sync.aligned.m8n8.x2.shared.b16 {%0,%1}, [%2];"
        : "=r"(r[0]),"=r"(r[1]) : "r"(a));
}
__device__ __forceinline__ void mmaf16(float* d, const uint32_t* a, const uint32_t* b){
    asm volatile("mma.sync.aligned.m16n8k16.row.col.f32.f16.f16.f32 "
        "{%0,%1,%2,%3}, {%4,%5,%6,%7}, {%8,%9}, {%0,%1,%2,%3};"
        : "+f"(d[0]),"+f"(d[1]),"+f"(d[2]),"+f"(d[3])
        : "r"(a[0]),"r"(a[1]),"r"(a[2]),"r"(a[3]),"r"(b[0]),"r"(b[1]));
}

__device__ __forceinline__ void batchsync(int b, unsigned &cnt){
    __syncthreads();
    if (threadIdx.x == 0){
        __threadfence();
        unsigned t = ++cnt;
        if (atomicAdd(&g_bctr[b], 1u) == 7u){
            atomicExch(&g_bctr[b], 0u);
            __threadfence();
            *(volatile unsigned*)&g_bgen[b] = t;
        } else {
            while (*(volatile unsigned*)&g_bgen[b] < t) __nanosleep(32);
        }
        __threadfence();
    }
    __syncthreads();
}

// smem layout (bytes, from 1KB-aligned base)
#define SW_OFF   0u          // W double buffer: 2 x 65536
#define H0H_OFF  131072u
#define H1H_OFF  139264u
#define C0_OFF   147456u
#define C1_OFF   163840u
#define SNAP_OFF 180224u
#define SWT_OFF  182272u
#define SWF_OFF  183296u
#define IP_OFF   184320u
#define WBS_OFF  184448u
#define BLS_OFF  188544u
#define SM_NEED  (192640u + 1024u)

__device__ __forceinline__ float hrd1(const char* hh, int row, int d){
    uint32_t off = (uint32_t)(row*256) + ((uint32_t)((d>>3) ^ (row&7))<<4) + (uint32_t)((d&7)*2);
    return __half2float(*(const f16*)(hh+off));
}
__device__ __forceinline__ void hwr1(char* hh, int row, int d, float v){
    uint32_t off = (uint32_t)(row*256) + ((uint32_t)((d>>3) ^ (row&7))<<4) + (uint32_t)((d&7)*2);
    *(f16*)(hh+off) = __float2half(v);
}

// ==================== persistent kernel ====================
__global__ __launch_bounds__(512,1) void persist(
    const int* __restrict__ exi, const int* __restrict__ steps,
    const float* __restrict__ bl, const float* __restrict__ Wb,
    const float* __restrict__ bb)
{
    extern __shared__ char dsm[];
    const uint32_t S0 = smem_u32(dsm);
    const uint32_t S  = (S0 + 1023u) & ~1023u;
    char* base = dsm + (S - S0);
    char* h0h = base + H0H_OFF;
    char* h1h = base + H1H_OFF;
    float* c0 = (float*)(base + C0_OFF);
    float* c1 = (float*)(base + C1_OFF);
    float* snC0 = (float*)(base + SNAP_OFF);
    float* snC1 = snC0 + 128; float* snH0 = snC0 + 256; float* snH1 = snC0 + 384;
    float* swt = (float*)(base + SWT_OFF);
    float* swf = (float*)(base + SWF_OFF);
    float* ips = (float*)(base + IP_OFF);
    float* wbs = (float*)(base + WBS_OFF);
    float* bls = (float*)(base + BLS_OFF);

    const int tid = threadIdx.x, lane = tid & 31, wid = tid >> 5;
    const int bid = blockIdx.x;
    const int b = bid >> 3, cell0 = bid * 32, lb = (bid & 7) * 32;
    const int mw = wid & 1, nw = wid >> 1;
    const int qr = lane >> 2, qc = (lane & 3) * 2;

    int wpar = 0;
    auto pref = [&](const f16* src, int KK, int buf){
        uint32_t dst = S + SW_OFF + (uint32_t)buf*65536u;
        #pragma unroll
        for (int i = 0; i < 8; ++i){
            int idx = tid + i*512;
            int row = idx >> 3, c16 = idx & 7;
            CPA16(dst + (uint32_t)(row*128) + ((uint32_t)(c16 ^ (row&7))<<4),
                  src + (size_t)row*KK + c16*8);
        }
        CP_COMMIT();
    };

    pref(g_w0t, 128, 0);   // kick off continuous W pipeline

    // init state
    for (int i = tid; i < 2048; i += 512){
        ((uint32_t*)h0h)[i] = 0; ((uint32_t*)h1h)[i] = 0;
    }
    for (int i = tid; i < 4096; i += 512){ c0[i] = 0.f; c1[i] = 0.f; }
    if (tid < 32) ips[tid] = (cell0 + tid == b*256) ? 1.0f : 0.0f;
    for (int i = tid; i < 1024; i += 512){ wbs[i] = __ldg(Wb + i); bls[i] = __ldg(bl + i); }
    __syncthreads();

    const int el = __ldg(exi + b);
    const bool owned = (el >> 5) == (bid & 7);
    const int eloc = el & 31;
    const int nsteps = __ldg(steps + b);
    const float bb0 = __ldg(bb), bb1 = __ldg(bb + 1);

    // fused GEMM (M=32,N=512) + LSTM epilogue; continuous W pipeline
    auto gemm = [&](int nslab, const f16* wsrc, int KK,
                    const f16* nextw, int nextKK,
                    const char* aHi0, const char* aHi1,
                    const float* xwp, const float* bias,
                    float* cbuf, char* hOh)
    {
        float acc[8][4];
        #pragma unroll
        for (int n8=0;n8<8;++n8){ acc[n8][0]=0.f; acc[n8][1]=0.f; acc[n8][2]=0.f; acc[n8][3]=0.f; }

        for (int s = 0; s < nslab; ++s){
            asm volatile("cp.async.wait_group 0;":::"memory");
            __syncthreads();
            if (s + 1 < nslab) pref(wsrc + (s+1)*64, KK, wpar^1);
            else               pref(nextw, nextKK, wpar^1);
            uint32_t wb = S + SW_OFF + (uint32_t)wpar*65536u;
            #pragma unroll
            for (int kk = 0; kk < 4; ++kk){
                int kglob = s*64 + kk*16;
                const char* ah; int kr;
                if (kglob < 128){ ah = aHi0; kr = kglob; }
                else            { ah = aHi1; kr = kglob - 128; }
                int row = mw*16 + (lane & 15);
                uint32_t u = (uint32_t)(((kr >> 3) + (lane >> 4)) ^ (row & 7));
                uint32_t Ah[4];
                ldmx4(Ah, smem_u32(ah) + (uint32_t)(row*256) + (u << 4));
                uint32_t B[4][4];
                #pragma unroll
                for (int p = 0; p < 4; ++p){
                    int r = nw*64 + p*16 + ((lane >> 4) << 3) + (lane & 7);
                    uint32_t kh = (uint32_t)(kk*2 + ((lane >> 3) & 1));
                    ldmx4(B[p], wb + (uint32_t)(r*128) + ((kh ^ (uint32_t)(r & 7)) << 4));
                }
                #pragma unroll
                for (int p = 0; p < 4; ++p){
                    mmaf16(acc[2*p],   Ah, &B[p][0]);
                    mmaf16(acc[2*p+1], Ah, &B[p][2]);
                }
            }
            wpar ^= 1;
        }
        __syncthreads();

        // epilogue: register gate math; xw loaded as one float4 per output
        #pragma unroll
        for (int rh = 0; rh < 2; ++rh){
            int row = mw*16 + qr + rh*8;
            int cell = cell0 + row;
            const float4* xr4 = xwp ? (const float4*)(xwp + (size_t)cell*2048) : nullptr;
            #pragma unroll
            for (int dd = 0; dd < 4; ++dd){
                int dlow = qc + (dd & 1) + (dd >> 1)*8;
                int hb = dd >> 1;
                int e = (dd & 1) + rh*2;
                int d = nw*16 + dlow;
                float vi = acc[hb][e]     + bias[d];
                float vf = acc[2+hb][e]   + bias[128 + d];
                float vg = acc[4+hb][e]   + bias[256 + d];
                float vo = acc[6+hb][e]   + bias[384 + d];
                if (xr4){
                    float4 xv = __ldg(xr4 + d);
                    vi += xv.x; vf += xv.y; vg += xv.z; vo += xv.w;
                }
                float cold = cbuf[row*128 + d];
                float c2 = sigf(vf)*cold + sigf(vi)*tanhap(vg);
                float hv = sigf(vo)*tanhap(c2);
                cbuf[row*128 + d] = c2;
                hwr1(hOh, row, d, hv);
            }
        }
        __syncthreads();
    };

    unsigned scnt = 0;
    for (int s = 0; s < nsteps; ++s){
        int par = s & 1;

        if (owned){
            int a = tid >> 7, d = tid & 127;
            if (a == 0) snC0[d] = c0[eloc*128 + d];
            else if (a == 1) snC1[d] = c1[eloc*128 + d];
            else if (a == 2) snH0[d] = hrd1(h0h, eloc, d);
            else             snH1[d] = hrd1(h1h, eloc, d);
        }
        __syncthreads();

        for (int t = 0; t < NT; ++t){
            gemm(2, g_w0t, 128, g_w1t, 256, h0h, h0h, g_xw + t*512, bls,       c0, h0h);
            gemm(4, g_w1t, 256, g_w0t, 128, h0h, h1h, nullptr,      bls + 512, c1, h1h);
        }

        if (owned){
            int a = tid >> 7, d = tid & 127;
            if (a == 0) c0[eloc*128 + d] = snC0[d];
            else if (a == 1) c1[eloc*128 + d] = snC1[d];
            else if (a == 2) hwr1(h0h, eloc, d, snH0[d]);
            else             hwr1(h1h, eloc, d, snH1[d]);
        }
        __syncthreads();

        // branch + publish
        {
            #pragma unroll
            for (int q = 0; q < 2; ++q){
                int i = wid*2 + q;
                float a0 = 0.f, a1 = 0.f;
                for (int d = lane; d < 128; d += 32){
                    float v0 = c0[i*128 + d];
                    float v1 = hrd1(h0h, i, d);
                    float v2 = c1[i*128 + d];
                    float v3 = hrd1(h1h, i, d);
                    a0 += v0*wbs[2*d]        + v1*wbs[2*(128+d)]
                        + v2*wbs[2*(256+d)]  + v3*wbs[2*(384+d)];
                    a1 += v0*wbs[2*d+1]      + v1*wbs[2*(128+d)+1]
                        + v2*wbs[2*(256+d)+1]+ v3*wbs[2*(384+d)+1];
                }
                #pragma unroll
                for (int o2 = 16; o2; o2 >>= 1){
                    a0 += __shfl_xor_sync(~0u, a0, o2);
                    a1 += __shfl_xor_sync(~0u, a1, o2);
                }
                if (lane == 0){
                    a0 += bb0; a1 += bb1;
                    float m = fmaxf(a0, a1), e0 = __expf(a0-m), e1 = __expf(a1-m);
                    float inv = 1.0f/(e0+e1), w = ips[i];
                    g_wtb[par][cell0 + i] = e0*inv*w;
                    g_wfb[par][cell0 + i] = e1*inv*w;
                }
            }
            for (int v = tid; v < 32*128; v += 512){
                int row = v >> 7, d = v & 127;
                size_t o = (size_t)(cell0 + row)*128 + d;
                g_pubC[par][o]        = c0[row*128 + d];
                g_pubC[par][o + LOFF] = c1[row*128 + d];
                g_pubH[par][o]        = hrd1(h0h, row, d);
                g_pubH[par][o + LOFF] = hrd1(h1h, row, d);
            }
        }
        batchsync(b, scnt);

        // aggregation (CSR)
        for (int i = tid; i < 256; i += 512){
            swt[i] = __ldcg(&g_wtb[par][b*256 + i]);
            swf[i] = __ldcg(&g_wfb[par][b*256 + i]);
        }
        __syncthreads();
        #pragma unroll
        for (int it = 0; it < 8; ++it){
            int i = it*4 + (tid >> 7);
            int d = tid & 127;
            int dstb = lb + i;
            int o0 = g_csr_off[b*NN + dstb];
            int o1 = (dstb == NN-1) ? (b*2*NN + 2*NN) : g_csr_off[b*NN + dstb + 1];
            float a0=0.f, a1=0.f, a2=0.f, a3=0.f, ipn=0.f;
            for (int qq = o0; qq < o1; ++qq){
                int v = g_csr_ent[qq];
                int src = v & 255;
                float w = (v < 0) ? swf[src] : swt[src];
                ipn += w;
                size_t o = (size_t)(b*256 + src)*128 + d;
                a0 += w * __ldcg(&g_pubC[par][o]);
                a1 += w * __ldcg(&g_pubH[par][o]);
                a2 += w * __ldcg(&g_pubC[par][o + LOFF]);
                a3 += w * __ldcg(&g_pubH[par][o + LOFF]);
            }
            float inv = 1.0f/(ipn + 1e-7f);
            c0[i*128 + d] = a0*inv;
            c1[i*128 + d] = a2*inv;
            hwr1(h0h, i, d, a1*inv);
            hwr1(h1h, i, d, a3*inv);
            if (d == 0) ips[i] = ipn;
        }
        __syncthreads();
    }

    asm volatile("cp.async.wait_group 0;":::"memory");

    for (int v = tid; v < 32*128; v += 512){
        int row = v >> 7, d = v & 127;
        size_t o = (size_t)(cell0 + row)*128 + d;
        g_c_st[o]        = c0[row*128 + d];
        g_c_st[o + LOFF] = c1[row*128 + d];
        g_h_st[o]        = hrd1(h0h, row, d);
        g_h_st[o + LOFF] = hrd1(h1h, row, d);
    }
}

// ==================== xw precompute (fp16 2-pass A, 1-pass W) ====================
__global__ void __launch_bounds__(256,1) xwgemm()
{
    extern __shared__ char smem[];
    const uint32_t BUF0 = (smem_u32(smem) + 127u) & ~127u;
    float* Z = (float*)(smem + (BUF0 - smem_u32(smem)));
    const int tid = threadIdx.x, lane = tid & 31, wid = tid >> 5;
    const int mw = wid & 3, nw = wid >> 2;
    const int rowbase = blockIdx.x * 128, nt = blockIdx.y;

    auto load_chunk = [&](int c){
        const uint32_t b = BUF0 + (uint32_t)(c & 1) * 49152u;
        const int kbase = c * 64;
        #pragma unroll
        for (int i = 0; i < 4; ++i){
            int u = tid + i * 256;
            int row = u >> 3, col16 = u & 7;
            uint32_t sw = (uint32_t)(row * 128 + ((col16 ^ (row & 7)) * 16));
            int kg = kbase + col16 * 8;
            size_t o = (size_t)(rowbase + row) * 128 + kg;
            CPA16(b + sw,         g_embf_h + o);
            CPA16(b + 16384 + sw, g_embf_l + o);
            size_t wo = (size_t)(nt * 128 + row) * 128 + kg;
            CPA16(b + 32768 + sw, g_w0xf + wo);
        }
        CP_COMMIT();
    };

    float acc[2][8][4];
    #pragma unroll
    for (int mt=0;mt<2;++mt)
        #pragma unroll
        for (int n8=0;n8<8;++n8)
            #pragma unroll
            for (int e=0;e<4;++e) acc[mt][n8][e]=0.f;

    const int arow = mw * 32 + (lane & 15);
    const uint32_t arbase = (uint32_t)(arow * 128);
    const uint32_t axr = (uint32_t)((arow & 7) << 4);
    const uint32_t acolh = (uint32_t)((lane >> 4) * 16);
    const int brow = nw * 64 + (lane & 7);
    const uint32_t bcolh = (uint32_t)(((lane >> 3) & 1) * 16);

    load_chunk(0);
    #pragma unroll
    for (int c = 0; c < 2; ++c){
        if (c + 1 < 2) load_chunk(c + 1);
        if (c + 1 < 2) asm volatile("cp.async.wait_group 1;":::"memory");
        else           asm volatile("cp.async.wait_group 0;":::"memory");
        __syncthreads();
        const uint32_t b = BUF0 + (uint32_t)(c & 1) * 49152u;
        #pragma unroll
        for (int kk = 0; kk < 4; ++kk){
            uint32_t ah[2][4], al[2][4];
            #pragma unroll
            for (int mt = 0; mt < 2; ++mt){
                uint32_t off = (uint32_t)(mt * 16 * 128) + arbase + (((uint32_t)(kk * 32) + acolh) ^ axr);
                ldmx4(ah[mt], b + off);
                ldmx4(al[mt], b + 16384 + off);
            }
            uint32_t bh[8][2];
            #pragma unroll
            for (int n8 = 0; n8 < 8; ++n8){
                int r = brow + n8 * 8;
                uint32_t off = (uint32_t)(r * 128) + (((uint32_t)(kk * 32) + bcolh) ^ ((uint32_t)((r & 7) << 4)));
                ldmx2(bh[n8], b + 32768 + off);
            }
            #pragma unroll
            for (int mt = 0; mt < 2; ++mt)
                #pragma unroll
                for (int n8 = 0; n8 < 8; ++n8) mmaf16(acc[mt][n8], ah[mt], bh[n8]);
            #pragma unroll
            for (int mt = 0; mt < 2; ++mt)
                #pragma unroll
                for (int n8 = 0; n8 < 8; ++n8) mmaf16(acc[mt][n8], al[mt], bh[n8]);
        }
        __syncthreads();
    }
    {
        const int qr = lane >> 2, qc = (lane & 3) * 2;
        #pragma unroll
        for (int mt = 0; mt < 2; ++mt){
            int r0 = mw * 32 + mt * 16 + qr;
            #pragma unroll
            for (int n8 = 0; n8 < 8; ++n8){
                int c0i = nw * 64 + n8 * 8 + qc;
                Z[r0 * ZSTR + c0i]           = acc[mt][n8][0];
                Z[r0 * ZSTR + c0i + 1]       = acc[mt][n8][1];
                Z[(r0 + 8) * ZSTR + c0i]     = acc[mt][n8][2];
                Z[(r0 + 8) * ZSTR + c0i + 1] = acc[mt][n8][3];
            }
        }
    }
    __syncthreads();
    // store to gate-interleaved xw layout: [ct][d*4 + gate]
    const int row = tid >> 1;
    const int ct = rowbase + row;
    const int cb = (tid & 1) * 64;
    #pragma unroll
    for (int q = 0; q < 64; ++q){
        int pg = nt*128 + cb + q;            // permuted col (block permutation)
        int g  = (pg >> 5) & 3;
        int d  = (pg >> 7) * 32 + (pg & 31);
        g_xw[(size_t)ct*512 + d*4 + g] = Z[row * ZSTR + cb + q];
    }
}

// ==================== fused setup kernel ====================
__global__ void setup_kernel(const int* __restrict__ data, const float* __restrict__ embed,
                             const float* __restrict__ Wi, const float* __restrict__ Wh,
                             const int* __restrict__ tb, const int* __restrict__ fb)
{
    const int bx = blockIdx.x, tid = threadIdx.x;
    if (bx < NB){
        // ---- CSR build ----
        int b = bx, dst = tid;
        __shared__ int stb[NN], sfb[NN], ps[NN];
        stb[dst] = tb[b*NN+dst]; sfb[dst] = fb[b*NN+dst];
        __syncthreads();
        int cnt = 0;
        for (int ss = 0; ss < NN; ++ss) cnt += (stb[ss]==dst) + (sfb[ss]==dst);
        ps[dst] = cnt; __syncthreads();
        for (int o2 = 1; o2 < NN; o2 <<= 1){
            int v = (dst >= o2) ? ps[dst-o2] : 0;
            __syncthreads();
            ps[dst] += v;
            __syncthreads();
        }
        int start = ps[dst] - cnt;
        g_csr_off[b*NN + dst] = b*2*NN + start;
        int p = b*2*NN + start;
        for (int ss = 0; ss < NN; ++ss) if (stb[ss]==dst) g_csr_ent[p++] = ss;
        for (int ss = 0; ss < NN; ++ss) if (sfb[ss]==dst) g_csr_ent[p++] = ss | (int)0x80000000;
    } else if (bx < NB + 512){
        // ---- weight conversion ----
        int i = (bx - NB)*256 + tid;
        if (i < 512*128){
            int p = i>>7, k = i&127;
            int ntc = p>>7, c = p&127, g = c>>5, j = c&31;
            int orig = g*128 + ntc*32 + j;
            g_w0xf[i] = __float2half(Wi[(size_t)k*512+orig]);
        }
        if (i < 512*128){
            int p = i>>7, k = i&127;
            int d = (p>>6)*16 + (p&15), g = (p>>4)&3;
            int orig = g*128 + d;
            g_w0t[i] = __float2half(Wh[(size_t)k*512 + orig]);
        }
        if (i < 512*256){
            int p = i>>8, k = i&255;
            int d = (p>>6)*16 + (p&15), g = (p>>4)&3;
            int orig = g*128 + d;
            float v = (k<128) ? Wi[(size_t)(128+k)*512+orig] : Wh[(size_t)(128+(k-128))*512+orig];
            g_w1t[i] = __float2half(v);
        }
    } else {
        // ---- embedding gather ----
        int i = (bx - NB - 512)*256 + tid;
        if (i < CELLS*NT*HD){
            float v = embed[(size_t)data[i>>7]*HD + (i&127)];
            f16 h = __float2half(v);
            g_embf_h[i] = h; g_embf_l[i] = __float2half(v - __half2float(h));
        }
    }
}

// ==================== final projection: grid (NB, 8), 128 thr, 1 output/thread ====================
__global__ void __launch_bounds__(128) final_kernel(
    const int* __restrict__ exi,
    const float* __restrict__ Wo, const float* __restrict__ bo,
    float* __restrict__ out)
{
    int b = blockIdx.x;
    __shared__ float f[4*HD];
    int cell = b*NN + exi[b];
    for (int i = threadIdx.x; i < 4*HD; i += blockDim.x){
        int l = i>>8, ch = (i>>7)&1, d = i&127;
        const float* src = ch ? g_h_st : g_c_st;
        f[i] = src[(size_t)l*LOFF + (size_t)cell*HD + d];
    }
    __syncthreads();
    int o = blockIdx.y * 128 + threadIdx.x;
    if (o >= OUTV) return;
    float acc = __ldg(bo + o);
    #pragma unroll 8
    for (int k = 0; k < 4*HD; ++k) acc += f[k] * __ldg(Wo + (size_t)k*OUTV + o);
    out[(size_t)b*OUTV + o] = acc;
}

// ==================== host ====================
#define TSMEM_XW (98304 + 128)

extern "C" void kernel_launch(void* const* d_in, const int* in_sizes, int n_in,
                              void* d_out, int out_size)
{
    const int*   data  = (const int*)  d_in[0];
    const int*   tb    = (const int*)  d_in[1];
    const int*   fb    = (const int*)  d_in[2];
    const int*   exi   = (const int*)  d_in[3];
    const int*   steps = (const int*)  d_in[4];
    const float* embed = (const float*)d_in[5];
    const float* Wi    = (const float*)d_in[6];
    const float* Wh    = (const float*)d_in[7];
    const float* bl    = (const float*)d_in[8];
    const float* Wb    = (const float*)d_in[9];
    const float* bb    = (const float*)d_in[10];
    const float* Wo    = (const float*)d_in[11];
    const float* bo    = (const float*)d_in[12];
    float* out = (float*)d_out;

    unsigned *bctr, *bgen;
    cudaGetSymbolAddress((void**)&bctr, g_bctr);
    cudaGetSymbolAddress((void**)&bgen, g_bgen);

    cudaFuncSetAttribute(persist, cudaFuncAttributeMaxDynamicSharedMemorySize, SM_NEED);
    cudaFuncSetAttribute(xwgemm,  cudaFuncAttributeMaxDynamicSharedMemorySize, TSMEM_XW);

    cudaMemsetAsync(bctr, 0, sizeof(unsigned)*NB, 0);
    cudaMemsetAsync(bgen, 0, sizeof(unsigned)*NB, 0);

    const int gather_blocks = (CELLS*NT*HD + 255)/256;     // 8192
    setup_kernel<<<NB + 512 + gather_blocks, 256>>>(data, embed, Wi, Wh, tb, fb);

    xwgemm<<<dim3(CELLS*NT/128, 4), 256, TSMEM_XW>>>();

    persist<<<NCTA, 512, SM_NEED>>>(exi, steps, bl, Wb, bb);

    final_kernel<<<dim3(NB, 8), 128>>>(exi, Wo, bo, out);
}